// round 2
// baseline (speedup 1.0000x reference)
#include <cuda_runtime.h>
#include <math.h>

// ---------------------------------------------------------------------------
// Problem constants (fixed by the reference)
// ---------------------------------------------------------------------------
#define KB   4       // batch
#define KN   4096    // tokens (64*64)
#define KC   256     // channels
#define KH   64      // H = W
#define KN1  1024    // tokens after 2x2 stride-2 reduction (32*32)
#define KSCALE 0.17677669529663687f  // 32^-0.5

// scratch offsets in floats
#define OFF_LEPE_LIN ((size_t)0)
#define OFF_LEPE     (OFF_LEPE_LIN + (size_t)KB*KN*KC)
#define OFF_Q1       (OFF_LEPE     + (size_t)KB*KN*KC)
#define OFF_Q2       (OFF_Q1       + (size_t)KB*KN*128)
#define OFF_KV2      (OFF_Q2       + (size_t)KB*KN*128)
#define OFF_XS       (OFF_KV2      + (size_t)KB*KN*256)
#define OFF_KV1      (OFF_XS       + (size_t)KB*KN1*256)
#define OFF_CONCAT   (OFF_KV1      + (size_t)KB*KN1*256)
#define OFF_SRWT     (OFF_CONCAT   + (size_t)KB*KN*KC)
#define OFF_GPART    (OFF_SRWT     + (size_t)1024*256)
#define OFF_GRED     (OFF_GPART    + (size_t)KB*4*128*1024)
#define OFF_LMPART   (OFF_GRED     + (size_t)KB*1024)
#define SCRATCH_TOT  (OFF_LMPART   + (size_t)KB*4*256*16)

__device__ float g_scratch[SCRATCH_TOT];

// ---------------------------------------------------------------------------
// Generic tiled GEMM:  C = alpha * ((A (+A2)) @ B + bias)
// A: M x K row-major, B: K x N row-major. M,N multiples of 64; K multiple of 16.
// block (16,16); 64x64 tile, 4x4 per thread.
// ---------------------------------------------------------------------------
__global__ void gemm_bias(const float* __restrict__ A, const float* __restrict__ A2,
                          const float* __restrict__ Bw, const float* __restrict__ bias,
                          float* __restrict__ C, int M, int N, int K, float alpha)
{
    __shared__ float As[64][16];
    __shared__ float Bs[16][64];
    const int tx = threadIdx.x, ty = threadIdx.y;
    const int tid = ty * 16 + tx;
    const int row0 = blockIdx.y * 64;
    const int col0 = blockIdx.x * 64;

    float acc[4][4] = {};

    for (int kk = 0; kk < K; kk += 16) {
        #pragma unroll
        for (int li = 0; li < 4; li++) {
            int r  = (tid >> 4) + li * 16;
            int kq = tid & 15;
            size_t ai = (size_t)(row0 + r) * K + kk + kq;
            float v = A[ai];
            if (A2) v += A2[ai];
            As[r][kq] = v;
        }
        #pragma unroll
        for (int li = 0; li < 4; li++) {
            int kq = (tid >> 6) + li * 4;
            int c  = tid & 63;
            Bs[kq][c] = Bw[(size_t)(kk + kq) * N + col0 + c];
        }
        __syncthreads();
        #pragma unroll
        for (int k = 0; k < 16; k++) {
            float a[4], b[4];
            #pragma unroll
            for (int i = 0; i < 4; i++) a[i] = As[ty + 16 * i][k];
            #pragma unroll
            for (int j = 0; j < 4; j++) b[j] = Bs[k][tx + 16 * j];
            #pragma unroll
            for (int i = 0; i < 4; i++)
                #pragma unroll
                for (int j = 0; j < 4; j++)
                    acc[i][j] += a[i] * b[j];
        }
        __syncthreads();
    }
    #pragma unroll
    for (int i = 0; i < 4; i++)
        #pragma unroll
        for (int j = 0; j < 4; j++) {
            int r = row0 + ty + 16 * i;
            int c = col0 + tx + 16 * j;
            C[(size_t)r * N + c] = alpha * (acc[i][j] + bias[c]);
        }
}

// ---------------------------------------------------------------------------
// sr conv (2x2 stride 2, VALID) as GEMM with on-the-fly im2col gather.
// M = B*1024 (output positions), N = 256 (C_out), K = 1024 = (ky,kx,ci)
// Bw = repacked weights g_srwt[k][co].
// ---------------------------------------------------------------------------
__global__ void srconv_gemm(const float* __restrict__ x, const float* __restrict__ Bw,
                            const float* __restrict__ bias, float* __restrict__ C)
{
    const int M = KB * KN1, N = 256, K = 1024;
    __shared__ float As[64][16];
    __shared__ float Bs[16][64];
    const int tx = threadIdx.x, ty = threadIdx.y;
    const int tid = ty * 16 + tx;
    const int row0 = blockIdx.y * 64;
    const int col0 = blockIdx.x * 64;

    float acc[4][4] = {};

    for (int kk = 0; kk < K; kk += 16) {
        const int kkid = kk >> 8;          // (ky*2+kx), constant within k-tile
        const int ky = kkid >> 1, kx = kkid & 1;
        #pragma unroll
        for (int li = 0; li < 4; li++) {
            int r  = (tid >> 4) + li * 16;
            int kq = tid & 15;
            int m  = row0 + r;
            int b  = m >> 10;
            int p  = m & 1023;
            int oy = p >> 5, ox = p & 31;
            int ci = (kk & 255) + kq;
            int n  = (2 * oy + ky) * KH + 2 * ox + kx;
            As[r][kq] = x[((size_t)b * KN + n) * KC + ci];
        }
        #pragma unroll
        for (int li = 0; li < 4; li++) {
            int kq = (tid >> 6) + li * 4;
            int c  = tid & 63;
            Bs[kq][c] = Bw[(size_t)(kk + kq) * N + col0 + c];
        }
        __syncthreads();
        #pragma unroll
        for (int k = 0; k < 16; k++) {
            float a[4], b[4];
            #pragma unroll
            for (int i = 0; i < 4; i++) a[i] = As[ty + 16 * i][k];
            #pragma unroll
            for (int j = 0; j < 4; j++) b[j] = Bs[k][tx + 16 * j];
            #pragma unroll
            for (int i = 0; i < 4; i++)
                #pragma unroll
                for (int j = 0; j < 4; j++)
                    acc[i][j] += a[i] * b[j];
        }
        __syncthreads();
    }
    (void)M;
    #pragma unroll
    for (int i = 0; i < 4; i++)
        #pragma unroll
        for (int j = 0; j < 4; j++) {
            int r = row0 + ty + 16 * i;
            int c = col0 + tx + 16 * j;
            C[(size_t)r * N + c] = acc[i][j] + bias[c];
        }
}

// repack sr_w (co,ci,ky,kx) -> srwt[(ky*2+kx)*256+ci][co]
__global__ void repack_srw(const float* __restrict__ srw, float* __restrict__ srwt)
{
    int idx = blockIdx.x * 256 + threadIdx.x;   // 262144
    int co = idx & 255;
    int k  = idx >> 8;
    int ci = k & 255;
    int kk = k >> 8;
    srwt[idx] = srw[(size_t)co * 1024 + ci * 4 + kk];
}

// ---------------------------------------------------------------------------
// depthwise 3x3 conv, pad 1, on (B,N,C) NHWC data
// ---------------------------------------------------------------------------
__global__ void lepe_conv(const float* __restrict__ in, const float* __restrict__ w,
                          const float* __restrict__ bias, float* __restrict__ out)
{
    int idx = blockIdx.x * 256 + threadIdx.x;   // B*N*C
    int c = idx & 255;
    int n = (idx >> 8) & 4095;
    int b = idx >> 20;
    int y = n >> 6, x = n & 63;
    float acc = bias[c];
    #pragma unroll
    for (int dy = -1; dy <= 1; dy++) {
        int yy = y + dy;
        if (yy < 0 || yy >= KH) continue;
        #pragma unroll
        for (int dx = -1; dx <= 1; dx++) {
            int xx = x + dx;
            if (xx < 0 || xx >= KH) continue;
            acc += in[((size_t)b * KN + yy * KH + xx) * KC + c] *
                   w[c * 9 + (dy + 1) * 3 + (dx + 1)];
        }
    }
    out[idx] = acc;
}

// ---------------------------------------------------------------------------
// LayerNorm (biased var, eps 1e-5) + exact GELU, in place. 1 block / row, C=256.
// ---------------------------------------------------------------------------
__global__ void ln_gelu(float* __restrict__ xs, const float* __restrict__ nw,
                        const float* __restrict__ nb)
{
    int row = blockIdx.x;
    int tid = threadIdx.x;
    float v = xs[(size_t)row * 256 + tid];
    __shared__ float red[16];
    float s = v, sq = v * v;
    #pragma unroll
    for (int o = 16; o; o >>= 1) {
        s  += __shfl_xor_sync(0xffffffffu, s, o);
        sq += __shfl_xor_sync(0xffffffffu, sq, o);
    }
    int w = tid >> 5, lane = tid & 31;
    if (lane == 0) { red[w] = s; red[8 + w] = sq; }
    __syncthreads();
    if (tid == 0) {
        float S = 0.f, SQ = 0.f;
        for (int i = 0; i < 8; i++) { S += red[i]; SQ += red[8 + i]; }
        red[0] = S; red[8] = SQ;
    }
    __syncthreads();
    float mean = red[0] * (1.f / 256.f);
    float var  = red[8] * (1.f / 256.f) - mean * mean;
    float t = (v - mean) * rsqrtf(var + 1e-5f) * nw[tid] + nb[tid];
    float g = 0.5f * t * (1.f + erff(t * 0.70710678118654752f));
    xs[(size_t)row * 256 + tid] = g;
}

// ---------------------------------------------------------------------------
// Branch-1 attention: block = (b, h, 32-query tile). Full 1024 score row in smem.
// Writes x1 into concat[:, :, 0:128] and per-block column sums into gpart.
// ---------------------------------------------------------------------------
#define SPITCH 1025
#define ATTN1_SMEM ((32 * SPITCH + 32 * 33 + 128 * 33) * 4)

__global__ void attn1_kernel(const float* __restrict__ q1, const float* __restrict__ kv1,
                             float* __restrict__ concat, float* __restrict__ gpart)
{
    extern __shared__ float sm[];
    float* S  = sm;                         // 32 x 1025
    float* Q  = sm + 32 * SPITCH;           // 32 x 33
    float* KV = Q + 32 * 33;                // 128 x 33
    const int tid = threadIdx.x;
    const int qt = blockIdx.x, h = blockIdx.y, b = blockIdx.z;

    // load 32x32 Q tile
    #pragma unroll
    for (int t = 0; t < 4; t++) {
        int idx = tid + 256 * t;
        int q = idx >> 5, dd = idx & 31;
        Q[q * 33 + dd] = q1[((size_t)b * KN + qt * 32 + q) * 128 + h * 32 + dd];
    }
    __syncthreads();

    const int qb = (tid & 7) * 4;           // query sub-tile (phase 1 & PV)
    const int mb = (tid >> 3) * 4;          // key sub-tile (phase 1)

    // ---- phase 1: S = scale * Q @ K^T ----
    for (int mt = 0; mt < 8; mt++) {
        #pragma unroll
        for (int t = 0; t < 16; t++) {
            int idx = tid + 256 * t;
            int mm = idx >> 5, dd = idx & 31;
            KV[mm * 33 + dd] = kv1[((size_t)b * KN1 + mt * 128 + mm) * 256 + h * 32 + dd];
        }
        __syncthreads();
        float acc[4][4] = {};
        #pragma unroll
        for (int k = 0; k < 32; k++) {
            float a[4], v[4];
            #pragma unroll
            for (int i = 0; i < 4; i++) a[i] = Q[(qb + i) * 33 + k];
            #pragma unroll
            for (int j = 0; j < 4; j++) v[j] = KV[(mb + j) * 33 + k];
            #pragma unroll
            for (int i = 0; i < 4; i++)
                #pragma unroll
                for (int j = 0; j < 4; j++)
                    acc[i][j] += a[i] * v[j];
        }
        #pragma unroll
        for (int i = 0; i < 4; i++)
            #pragma unroll
            for (int j = 0; j < 4; j++)
                S[(qb + i) * SPITCH + mt * 128 + mb + j] = acc[i][j] * KSCALE;
        __syncthreads();
    }

    // ---- softmax rows (warp w handles rows 4w..4w+3) ----
    {
        int w = tid >> 5, lane = tid & 31;
        for (int r = w * 4; r < w * 4 + 4; r++) {
            float mx = -1e30f;
            for (int m = lane; m < 1024; m += 32) mx = fmaxf(mx, S[r * SPITCH + m]);
            #pragma unroll
            for (int o = 16; o; o >>= 1) mx = fmaxf(mx, __shfl_xor_sync(0xffffffffu, mx, o));
            float ssum = 0.f;
            for (int m = lane; m < 1024; m += 32) {
                float e = __expf(S[r * SPITCH + m] - mx);
                S[r * SPITCH + m] = e;
                ssum += e;
            }
            #pragma unroll
            for (int o = 16; o; o >>= 1) ssum += __shfl_xor_sync(0xffffffffu, ssum, o);
            float inv = 1.f / ssum;
            for (int m = lane; m < 1024; m += 32) S[r * SPITCH + m] *= inv;
        }
    }
    __syncthreads();

    // ---- deterministic per-block column sums for g mask ----
    for (int m = tid; m < 1024; m += 256) {
        float cs = 0.f;
        #pragma unroll
        for (int q = 0; q < 32; q++) cs += S[q * SPITCH + m];
        gpart[(((size_t)(b * 4 + h) * 128) + qt) * 1024 + m] = cs;
    }

    // ---- PV: out[32][32] = P @ V, m split 4 ways across thread groups ----
    const int s4 = tid >> 6;                // 0..3 (constant within warp)
    const int d4 = ((tid >> 3) & 7) * 4;    // 0..28
    float acc[4][4] = {};
    for (int mt = 0; mt < 8; mt++) {
        #pragma unroll
        for (int t = 0; t < 16; t++) {
            int idx = tid + 256 * t;
            int mm = idx >> 5, dd = idx & 31;
            KV[mm * 33 + dd] = kv1[((size_t)b * KN1 + mt * 128 + mm) * 256 + 128 + h * 32 + dd];
        }
        __syncthreads();
        for (int mm = s4; mm < 128; mm += 4) {
            float p[4], v[4];
            #pragma unroll
            for (int i = 0; i < 4; i++) p[i] = S[(qb + i) * SPITCH + mt * 128 + mm];
            #pragma unroll
            for (int j = 0; j < 4; j++) v[j] = KV[mm * 33 + d4 + j];
            #pragma unroll
            for (int i = 0; i < 4; i++)
                #pragma unroll
                for (int j = 0; j < 4; j++)
                    acc[i][j] += p[i] * v[j];
        }
        __syncthreads();
    }

    // reduce 4 m-split partials via S region (reuse; all S reads done)
    #pragma unroll
    for (int i = 0; i < 4; i++)
        #pragma unroll
        for (int j = 0; j < 4; j++)
            S[s4 * 1024 + (qb + i) * 32 + d4 + j] = acc[i][j];
    __syncthreads();
    for (int idx = tid; idx < 1024; idx += 256) {
        int q = idx >> 5, dd = idx & 31;
        float sum = S[idx] + S[1024 + idx] + S[2048 + idx] + S[3072 + idx];
        concat[((size_t)b * KN + qt * 32 + q) * 256 + h * 32 + dd] = sum;
    }
}

// ---------------------------------------------------------------------------
// Branch-2 windowed attention: one warp per (b, h, window). 4 warps / block.
// Writes x2 into concat[:, :, 128:256] and per-(b,h,win) column sums to lmpart.
// ---------------------------------------------------------------------------
__global__ void attn2_kernel(const float* __restrict__ q2, const float* __restrict__ kv2,
                             float* __restrict__ concat, float* __restrict__ lmpart)
{
    __shared__ float sQ[4][512];
    __shared__ float sKT[4][512];   // transposed: [k][token]
    __shared__ float sV[4][512];
    __shared__ float sS[4][16 * 17];
    const int w = threadIdx.x >> 5, lane = threadIdx.x & 31;
    const int gw = blockIdx.x * 4 + w;
    const int b = gw >> 10;
    const int rem = gw & 1023;
    const int h = rem >> 8;
    const int win = rem & 255;
    const int wy = win >> 4, wx = win & 15;

    for (int t = 0; t < 16; t++) {
        int n = (wy * 4 + (t >> 2)) * KH + wx * 4 + (t & 3);
        sQ[w][t * 32 + lane]  = q2[((size_t)b * KN + n) * 128 + h * 32 + lane];
        sKT[w][lane * 16 + t] = kv2[((size_t)b * KN + n) * 256 + h * 32 + lane];
        sV[w][t * 32 + lane]  = kv2[((size_t)b * KN + n) * 256 + 128 + h * 32 + lane];
    }
    __syncwarp();

    #pragma unroll
    for (int r = 0; r < 8; r++) {
        int e = r * 32 + lane;
        int i = e >> 4, j = e & 15;
        float acc = 0.f;
        #pragma unroll
        for (int k = 0; k < 32; k++) acc += sQ[w][i * 32 + k] * sKT[w][k * 16 + j];
        sS[w][i * 17 + j] = acc * KSCALE;
    }
    __syncwarp();

    if (lane < 16) {
        float mx = -1e30f;
        #pragma unroll
        for (int j = 0; j < 16; j++) mx = fmaxf(mx, sS[w][lane * 17 + j]);
        float s = 0.f;
        #pragma unroll
        for (int j = 0; j < 16; j++) {
            float e = __expf(sS[w][lane * 17 + j] - mx);
            sS[w][lane * 17 + j] = e;
            s += e;
        }
        float inv = 1.f / s;
        #pragma unroll
        for (int j = 0; j < 16; j++) sS[w][lane * 17 + j] *= inv;
    }
    __syncwarp();

    if (lane < 16) {
        float cs = 0.f;
        #pragma unroll
        for (int i = 0; i < 16; i++) cs += sS[w][i * 17 + lane];
        lmpart[(((size_t)(b * 4 + h) * 256) + win) * 16 + lane] = cs;
    }

    for (int i = 0; i < 16; i++) {
        float acc = 0.f;
        #pragma unroll
        for (int j = 0; j < 16; j++) acc += sS[w][i * 17 + j] * sV[w][j * 32 + lane];
        int n = (wy * 4 + (i >> 2)) * KH + wx * 4 + (i & 3);
        concat[((size_t)b * KN + n) * 256 + 128 + h * 32 + lane] = acc;
    }
}

// ---------------------------------------------------------------------------
// reduce gpart over (h, qt) -> gred[b][m] with 1/(h2*N) scaling
// ---------------------------------------------------------------------------
__global__ void g_reduce(const float* __restrict__ gpart, float* __restrict__ gred)
{
    int idx = blockIdx.x * 256 + threadIdx.x;   // 4096 = B*1024
    int b = idx >> 10, m = idx & 1023;
    float s = 0.f;
    for (int j = 0; j < 512; j++)
        s += gpart[((size_t)b * 512 + j) * 1024 + m];
    gred[idx] = s * (1.f / 16384.f);
}

// ---------------------------------------------------------------------------
// mask assembly: mask = lm + nearest-upsampled g; write mask1 and transposed mask2
// ---------------------------------------------------------------------------
__global__ void mask_kernel(const float* __restrict__ gred, const float* __restrict__ lmpart,
                            float* __restrict__ m1, float* __restrict__ m2)
{
    int idx = blockIdx.x * 256 + threadIdx.x;   // B*4096
    int b = idx >> 12, n = idx & 4095;
    int y = n >> 6, x = n & 63;
    float gv = gred[b * 1024 + (y >> 1) * 32 + (x >> 1)];
    int win = (y >> 2) * 16 + (x >> 2);
    int t = (y & 3) * 4 + (x & 3);
    float lv = 0.f;
    #pragma unroll
    for (int h = 0; h < 4; h++)
        lv += lmpart[(((size_t)(b * 4 + h) * 256) + win) * 16 + t];
    lv *= (1.f / 64.f);
    float val = gv + lv;
    m1[b * KN + y * KH + x] = val;
    m2[b * KN + x * KH + y] = val;
}

// ---------------------------------------------------------------------------
// launcher
// ---------------------------------------------------------------------------
extern "C" void kernel_launch(void* const* d_in, const int* in_sizes, int n_in,
                              void* d_out, int out_size)
{
    const float* x      = (const float*)d_in[0];
    const float* q1_w   = (const float*)d_in[1];
    const float* q1_b   = (const float*)d_in[2];
    const float* kv1_w  = (const float*)d_in[3];
    const float* kv1_b  = (const float*)d_in[4];
    const float* q2_w   = (const float*)d_in[5];
    const float* q2_b   = (const float*)d_in[6];
    const float* kv2_w  = (const float*)d_in[7];
    const float* kv2_b  = (const float*)d_in[8];
    const float* lepe_w = (const float*)d_in[9];
    const float* lepe_b = (const float*)d_in[10];
    const float* lcw    = (const float*)d_in[11];
    const float* lcb    = (const float*)d_in[12];
    const float* sr_w   = (const float*)d_in[13];
    const float* sr_b   = (const float*)d_in[14];
    const float* norm_w = (const float*)d_in[15];
    const float* norm_b = (const float*)d_in[16];
    const float* proj_w = (const float*)d_in[17];
    const float* proj_b = (const float*)d_in[18];
    (void)in_sizes; (void)n_in; (void)out_size;

    float* scratch = nullptr;
    cudaGetSymbolAddress((void**)&scratch, g_scratch);
    float* lepe_lin = scratch + OFF_LEPE_LIN;
    float* lepe     = scratch + OFF_LEPE;
    float* q1buf    = scratch + OFF_Q1;
    float* q2buf    = scratch + OFF_Q2;
    float* kv2buf   = scratch + OFF_KV2;
    float* xs       = scratch + OFF_XS;
    float* kv1buf   = scratch + OFF_KV1;
    float* concat   = scratch + OFF_CONCAT;
    float* srwt     = scratch + OFF_SRWT;
    float* gpart    = scratch + OFF_GPART;
    float* gred     = scratch + OFF_GRED;
    float* lmpart   = scratch + OFF_LMPART;

    float* out = (float*)d_out;
    float* m1  = out + (size_t)KB * KN * KC;
    float* m2  = m1 + (size_t)KB * KN;

    cudaFuncSetAttribute(attn1_kernel, cudaFuncAttributeMaxDynamicSharedMemorySize,
                         ATTN1_SMEM);

    dim3 blk(16, 16);

    repack_srw<<<1024, 256>>>(sr_w, srwt);

    // lepe branch
    gemm_bias<<<dim3(4, 256), blk>>>(x, nullptr, lepe_w, lepe_b, lepe_lin,
                                     KB * KN, 256, 256, 1.f);
    lepe_conv<<<16384, 256>>>(lepe_lin, lcw, lcb, lepe);

    // projections from x
    gemm_bias<<<dim3(2, 256), blk>>>(x, nullptr, q1_w, q1_b, q1buf,
                                     KB * KN, 128, 256, 1.f);
    gemm_bias<<<dim3(2, 256), blk>>>(x, nullptr, q2_w, q2_b, q2buf,
                                     KB * KN, 128, 256, 1.f);
    gemm_bias<<<dim3(4, 256), blk>>>(x, nullptr, kv2_w, kv2_b, kv2buf,
                                     KB * KN, 256, 256, 1.f);

    // spatial reduction -> LN -> GELU -> kv1
    srconv_gemm<<<dim3(4, 64), blk>>>(x, srwt, sr_b, xs);
    ln_gelu<<<KB * KN1, 256>>>(xs, norm_w, norm_b);
    gemm_bias<<<dim3(4, 64), blk>>>(xs, nullptr, kv1_w, kv1_b, kv1buf,
                                    KB * KN1, 256, 256, 1.f);

    // attention branches
    attn1_kernel<<<dim3(128, 4, 4), 256, ATTN1_SMEM>>>(q1buf, kv1buf, concat, gpart);
    g_reduce<<<16, 256>>>(gpart, gred);
    attn2_kernel<<<1024, 128>>>(q2buf, kv2buf, concat, lmpart);
    mask_kernel<<<64, 256>>>(gred, lmpart, m1, m2);

    // fused (concat + lepe) @ proj + bias, x2 epilogue -> d_out
    gemm_bias<<<dim3(4, 256), blk>>>(concat, lepe, proj_w, proj_b, out,
                                     KB * KN, 256, 256, 2.f);
}

// round 4
// speedup vs baseline: 2.2002x; 2.2002x over previous
#include <cuda_runtime.h>
#include <cuda_fp16.h>
#include <mma.h>
#include <math.h>
#include <stdint.h>

using namespace nvcuda;

// ---------------------------------------------------------------------------
// Problem constants
// ---------------------------------------------------------------------------
#define KB   4
#define KN   4096
#define KC   256
#define KH   64
#define KN1  1024
#define KSCALE 0.17677669529663687f

// fp32 scratch offsets
#define OFF_LEPE_LIN ((size_t)0)
#define OFF_LEPE     (OFF_LEPE_LIN + (size_t)KB*KN*KC)
#define OFF_Q2       (OFF_LEPE     + (size_t)KB*KN*KC)
#define OFF_KV2      (OFF_Q2       + (size_t)KB*KN*128)
#define OFF_XS       (OFF_KV2      + (size_t)KB*KN*256)
#define OFF_CONCAT   (OFF_XS       + (size_t)KB*KN1*256)
#define OFF_GPART    (OFF_CONCAT   + (size_t)KB*KN*KC)
#define OFF_GRED     (OFF_GPART    + (size_t)KB*4*128*1024)
#define OFF_LMPART   (OFF_GRED     + (size_t)KB*1024)
#define SCRATCH_TOT  (OFF_LMPART   + (size_t)KB*4*256*16)

__device__ float g_scratch[SCRATCH_TOT];

// f16 scratch offsets (halves, 16B-aligned blocks)
#define HOFF_XH    ((size_t)0)
#define HOFF_XIM   (HOFF_XH   + (size_t)4194304)
#define HOFF_XSH   (HOFF_XIM  + (size_t)4194304)
#define HOFF_CH    (HOFF_XSH  + (size_t)1048576)
#define HOFF_Q1H   (HOFF_CH   + (size_t)4194304)
#define HOFF_KV1H  (HOFF_Q1H  + (size_t)2097152)
#define HOFF_WQ1   (HOFF_KV1H + (size_t)1048576)
#define HOFF_WQ2   (HOFF_WQ1  + (size_t)32768)
#define HOFF_WKV1  (HOFF_WQ2  + (size_t)32768)
#define HOFF_WKV2  (HOFF_WKV1 + (size_t)65536)
#define HOFF_WLEPE (HOFF_WKV2 + (size_t)65536)
#define HOFF_WPROJ (HOFF_WLEPE+ (size_t)65536)
#define HOFF_WSR   (HOFF_WPROJ+ (size_t)65536)
#define HSCRATCH_TOT (HOFF_WSR + (size_t)262144)

__device__ __half g_scratch_h[HSCRATCH_TOT];

// ---------------------------------------------------------------------------
// wmma f16 GEMM: C[M][N] = alpha * (A[M][K] @ BT[N][K]^T + bias)
// 128x128 tile, 256 threads = 8 warps (2 x 4), warp tile 64x32.
// HALF_OUT: write __half instead of float.
// ---------------------------------------------------------------------------
#define APITCH 72
#define CPITCH 132
#define HG_SMEM (128 * CPITCH * 4)   // 67584 >= 2*128*72*2 = 36864

template<bool HALF_OUT>
__global__ __launch_bounds__(256)
void hgemm(const __half* __restrict__ A, const __half* __restrict__ BT,
           const float* __restrict__ bias, void* __restrict__ Cout,
           int M, int N, int K, float alpha)
{
    extern __shared__ char smraw[];
    __half* As = (__half*)smraw;                         // 128 x APITCH
    __half* Bs = As + 128 * APITCH;                      // 128 x APITCH
    float*  Cst = (float*)smraw;                         // 128 x CPITCH (reused)

    const int tid = threadIdx.x;
    const int wid = tid >> 5;
    const int warp_row = wid >> 2;       // 0..1 -> 64 rows
    const int warp_col = wid & 3;        // 0..3 -> 32 cols
    const int row0 = blockIdx.y * 128;
    const int col0 = blockIdx.x * 128;

    wmma::fragment<wmma::accumulator, 16, 16, 16, float> acc[4][2];
    #pragma unroll
    for (int mt = 0; mt < 4; mt++)
        #pragma unroll
        for (int nt = 0; nt < 2; nt++)
            wmma::fill_fragment(acc[mt][nt], 0.f);

    const int kn = K >> 6;
    for (int c = 0; c < kn; c++) {
        // stage A,B 128x64 chunks (uint4 = 8 halves)
        #pragma unroll
        for (int i = 0; i < 4; i++) {
            int li = i * 256 + tid;
            int r = li >> 3, q = (li & 7) * 8;
            *(uint4*)(As + r * APITCH + q) =
                *(const uint4*)(A + (size_t)(row0 + r) * K + c * 64 + q);
            *(uint4*)(Bs + r * APITCH + q) =
                *(const uint4*)(BT + (size_t)(col0 + r) * K + c * 64 + q);
        }
        __syncthreads();
        #pragma unroll
        for (int ks = 0; ks < 4; ks++) {
            wmma::fragment<wmma::matrix_a, 16, 16, 16, __half, wmma::row_major> af[4];
            wmma::fragment<wmma::matrix_b, 16, 16, 16, __half, wmma::col_major> bf[2];
            #pragma unroll
            for (int mt = 0; mt < 4; mt++)
                wmma::load_matrix_sync(af[mt],
                    As + (warp_row * 64 + mt * 16) * APITCH + ks * 16, APITCH);
            #pragma unroll
            for (int nt = 0; nt < 2; nt++)
                wmma::load_matrix_sync(bf[nt],
                    Bs + (warp_col * 32 + nt * 16) * APITCH + ks * 16, APITCH);
            #pragma unroll
            for (int mt = 0; mt < 4; mt++)
                #pragma unroll
                for (int nt = 0; nt < 2; nt++)
                    wmma::mma_sync(acc[mt][nt], af[mt], bf[nt], acc[mt][nt]);
        }
        __syncthreads();
    }

    // epilogue via smem staging
    #pragma unroll
    for (int mt = 0; mt < 4; mt++)
        #pragma unroll
        for (int nt = 0; nt < 2; nt++)
            wmma::store_matrix_sync(
                Cst + (warp_row * 64 + mt * 16) * CPITCH + warp_col * 32 + nt * 16,
                acc[mt][nt], CPITCH, wmma::mem_row_major);
    __syncthreads();

    #pragma unroll
    for (int i = 0; i < 16; i++) {
        int lin = i * 256 + tid;
        int r = lin >> 5, c4 = (lin & 31) * 4;
        const float* s = Cst + r * CPITCH + c4;
        float v0 = alpha * (s[0] + bias[col0 + c4 + 0]);
        float v1 = alpha * (s[1] + bias[col0 + c4 + 1]);
        float v2 = alpha * (s[2] + bias[col0 + c4 + 2]);
        float v3 = alpha * (s[3] + bias[col0 + c4 + 3]);
        size_t o = (size_t)(row0 + r) * N + col0 + c4;
        if (HALF_OUT) {
            __half2 h0 = __floats2half2_rn(v0, v1);
            __half2 h1 = __floats2half2_rn(v2, v3);
            uint2 pk;
            pk.x = *(uint32_t*)&h0;
            pk.y = *(uint32_t*)&h1;
            *(uint2*)((__half*)Cout + o) = pk;
        } else {
            float4 v = make_float4(v0, v1, v2, v3);
            *(float4*)((float*)Cout + o) = v;
        }
    }
}

// ---------------------------------------------------------------------------
// conversion / repack kernels
// ---------------------------------------------------------------------------
__global__ void cvt_f16(const float* __restrict__ in, __half* __restrict__ out) {
    int idx = blockIdx.x * 256 + threadIdx.x;
    out[idx] = __float2half(in[idx]);
}

__global__ void transpose_f16(const float* __restrict__ W, __half* __restrict__ WT,
                              int K, int N) {
    int idx = blockIdx.x * 256 + threadIdx.x;
    int n = idx % N, k = idx / N;
    WT[(size_t)n * K + k] = __float2half(W[idx]);
}

__global__ void repack_sr(const float* __restrict__ srw, __half* __restrict__ wt) {
    int idx = blockIdx.x * 256 + threadIdx.x;  // 262144
    int k = idx & 1023;
    int co = idx >> 10;
    int kk = k >> 8, ci = k & 255;
    wt[idx] = __float2half(srw[(size_t)co * 1024 + ci * 4 + kk]);
}

__global__ void im2col(const __half* __restrict__ xh, __half* __restrict__ xim) {
    int idx = blockIdx.x * 256 + threadIdx.x;  // 4M
    int k = idx & 1023;
    int m = idx >> 10;
    int b = m >> 10, p = m & 1023;
    int oy = p >> 5, ox = p & 31;
    int kk = k >> 8, ci = k & 255;
    int ky = kk >> 1, kx = kk & 1;
    xim[idx] = xh[((size_t)b * KN + (2 * oy + ky) * KH + 2 * ox + kx) * KC + ci];
}

__global__ void addcat(const float* __restrict__ a, const float* __restrict__ b,
                       __half* __restrict__ o) {
    int idx = blockIdx.x * 256 + threadIdx.x;
    o[idx] = __float2half(a[idx] + b[idx]);
}

// ---------------------------------------------------------------------------
// depthwise 3x3 conv, pad 1, NHWC
// ---------------------------------------------------------------------------
__global__ void lepe_conv(const float* __restrict__ in, const float* __restrict__ w,
                          const float* __restrict__ bias, float* __restrict__ out)
{
    int idx = blockIdx.x * 256 + threadIdx.x;
    int c = idx & 255;
    int n = (idx >> 8) & 4095;
    int b = idx >> 20;
    int y = n >> 6, x = n & 63;
    float acc = bias[c];
    #pragma unroll
    for (int dy = -1; dy <= 1; dy++) {
        int yy = y + dy;
        if (yy < 0 || yy >= KH) continue;
        #pragma unroll
        for (int dx = -1; dx <= 1; dx++) {
            int xx = x + dx;
            if (xx < 0 || xx >= KH) continue;
            acc += in[((size_t)b * KN + yy * KH + xx) * KC + c] *
                   w[c * 9 + (dy + 1) * 3 + (dx + 1)];
        }
    }
    out[idx] = acc;
}

// ---------------------------------------------------------------------------
// LayerNorm + GELU, writes f16
// ---------------------------------------------------------------------------
__global__ void ln_gelu(const float* __restrict__ xs, const float* __restrict__ nw,
                        const float* __restrict__ nb, __half* __restrict__ o16)
{
    int row = blockIdx.x;
    int tid = threadIdx.x;
    float v = xs[(size_t)row * 256 + tid];
    __shared__ float red[16];
    float s = v, sq = v * v;
    #pragma unroll
    for (int o = 16; o; o >>= 1) {
        s  += __shfl_xor_sync(0xffffffffu, s, o);
        sq += __shfl_xor_sync(0xffffffffu, sq, o);
    }
    int w = tid >> 5, lane = tid & 31;
    if (lane == 0) { red[w] = s; red[8 + w] = sq; }
    __syncthreads();
    if (tid == 0) {
        float S = 0.f, SQ = 0.f;
        for (int i = 0; i < 8; i++) { S += red[i]; SQ += red[8 + i]; }
        red[0] = S; red[8] = SQ;
    }
    __syncthreads();
    float mean = red[0] * (1.f / 256.f);
    float var  = red[8] * (1.f / 256.f) - mean * mean;
    float t = (v - mean) * rsqrtf(var + 1e-5f) * nw[tid] + nb[tid];
    float g = 0.5f * t * (1.f + erff(t * 0.70710678118654752f));
    o16[(size_t)row * 256 + tid] = __float2half(g);
}

// ---------------------------------------------------------------------------
// Branch-1 attention via wmma.
// block = (qt:128, h:4, b:4), 256 threads = 8 warps.
// smem: S f32 32 x 1040 (133120 B) | P f16 32 x 1032 (66048 B)
// ---------------------------------------------------------------------------
#define SPITCH 1040
#define PPITCH 1032
#define ATTN1_SMEM (32 * SPITCH * 4 + 32 * PPITCH * 2)

__global__ __launch_bounds__(256)
void attn1_kernel(const __half* __restrict__ q1h, const __half* __restrict__ kv1h,
                  float* __restrict__ concat, float* __restrict__ gpart)
{
    extern __shared__ char smraw[];
    float* S = (float*)smraw;
    __half* P = (__half*)(smraw + 32 * SPITCH * 4);
    const int tid = threadIdx.x;
    const int w = tid >> 5, lane = tid & 31;
    const int qt = blockIdx.x, h = blockIdx.y, b = blockIdx.z;

    // ---- QK^T: warp w covers key columns [w*128, w*128+128) ----
    {
        wmma::fragment<wmma::matrix_a, 16, 16, 16, __half, wmma::row_major> af[2][2];
        #pragma unroll
        for (int mt = 0; mt < 2; mt++)
            #pragma unroll
            for (int ks = 0; ks < 2; ks++)
                wmma::load_matrix_sync(af[mt][ks],
                    q1h + ((size_t)b * KN + qt * 32 + mt * 16) * 128 + h * 32 + ks * 16,
                    128);
        #pragma unroll
        for (int nt = 0; nt < 8; nt++) {
            wmma::fragment<wmma::accumulator, 16, 16, 16, float> acc0, acc1;
            wmma::fill_fragment(acc0, 0.f);
            wmma::fill_fragment(acc1, 0.f);
            #pragma unroll
            for (int ks = 0; ks < 2; ks++) {
                wmma::fragment<wmma::matrix_b, 16, 16, 16, __half, wmma::col_major> bf;
                wmma::load_matrix_sync(bf,
                    kv1h + ((size_t)b * KN1 + w * 128 + nt * 16) * 256 + h * 32 + ks * 16,
                    256);
                wmma::mma_sync(acc0, af[0][ks], bf, acc0);
                wmma::mma_sync(acc1, af[1][ks], bf, acc1);
            }
            #pragma unroll
            for (int e = 0; e < acc0.num_elements; e++) {
                acc0.x[e] *= KSCALE;
                acc1.x[e] *= KSCALE;
            }
            wmma::store_matrix_sync(S + 0 * SPITCH + w * 128 + nt * 16, acc0,
                                    SPITCH, wmma::mem_row_major);
            wmma::store_matrix_sync(S + 16 * SPITCH + w * 128 + nt * 16, acc1,
                                    SPITCH, wmma::mem_row_major);
        }
    }
    __syncthreads();

    // ---- fp32 softmax, 4 rows per warp ----
    for (int r = w * 4; r < w * 4 + 4; r++) {
        float mx = -1e30f;
        for (int m = lane; m < 1024; m += 32) mx = fmaxf(mx, S[r * SPITCH + m]);
        #pragma unroll
        for (int o = 16; o; o >>= 1) mx = fmaxf(mx, __shfl_xor_sync(0xffffffffu, mx, o));
        float ssum = 0.f;
        for (int m = lane; m < 1024; m += 32) {
            float e = __expf(S[r * SPITCH + m] - mx);
            S[r * SPITCH + m] = e;
            ssum += e;
        }
        #pragma unroll
        for (int o = 16; o; o >>= 1) ssum += __shfl_xor_sync(0xffffffffu, ssum, o);
        float inv = 1.f / ssum;
        for (int m = lane; m < 1024; m += 32) S[r * SPITCH + m] *= inv;
    }
    __syncthreads();

    // ---- deterministic column sums for g ----
    for (int m = tid; m < 1024; m += 256) {
        float cs = 0.f;
        #pragma unroll
        for (int q = 0; q < 32; q++) cs += S[q * SPITCH + m];
        gpart[(((size_t)(b * 4 + h) * 128) + qt) * 1024 + m] = cs;
    }

    // ---- convert P to f16 ----
    for (int idx = tid; idx < 32 * 1024; idx += 256) {
        int r = idx >> 10, m = idx & 1023;
        P[r * PPITCH + m] = __float2half(S[r * SPITCH + m]);
    }
    __syncthreads();

    // ---- PV: warp w handles key range [w*128, (w+1)*128), partials in S ----
    {
        wmma::fragment<wmma::accumulator, 16, 16, 16, float> acc2[2][2];
        #pragma unroll
        for (int mt = 0; mt < 2; mt++)
            #pragma unroll
            for (int nt = 0; nt < 2; nt++)
                wmma::fill_fragment(acc2[mt][nt], 0.f);
        for (int ks = 0; ks < 8; ks++) {
            int kk = w * 128 + ks * 16;
            wmma::fragment<wmma::matrix_a, 16, 16, 16, __half, wmma::row_major> ap[2];
            wmma::fragment<wmma::matrix_b, 16, 16, 16, __half, wmma::row_major> bp[2];
            #pragma unroll
            for (int mt = 0; mt < 2; mt++)
                wmma::load_matrix_sync(ap[mt], P + (mt * 16) * PPITCH + kk, PPITCH);
            #pragma unroll
            for (int nt = 0; nt < 2; nt++)
                wmma::load_matrix_sync(bp[nt],
                    kv1h + ((size_t)b * KN1 + kk) * 256 + 128 + h * 32 + nt * 16, 256);
            #pragma unroll
            for (int mt = 0; mt < 2; mt++)
                #pragma unroll
                for (int nt = 0; nt < 2; nt++)
                    wmma::mma_sync(acc2[mt][nt], ap[mt], bp[nt], acc2[mt][nt]);
        }
        __syncthreads();   // S reads complete everywhere before overwrite
        float* Sp = S + w * 1024;
        #pragma unroll
        for (int mt = 0; mt < 2; mt++)
            #pragma unroll
            for (int nt = 0; nt < 2; nt++)
                wmma::store_matrix_sync(Sp + mt * 16 * 32 + nt * 16, acc2[mt][nt],
                                        32, wmma::mem_row_major);
    }
    __syncthreads();

    // reduce 8 warp partials -> concat
    for (int idx = tid; idx < 1024; idx += 256) {
        int q = idx >> 5, dd = idx & 31;
        float sum = 0.f;
        #pragma unroll
        for (int j = 0; j < 8; j++) sum += S[j * 1024 + idx];
        concat[((size_t)b * KN + qt * 32 + q) * 256 + h * 32 + dd] = sum;
    }
}

// ---------------------------------------------------------------------------
// Branch-2 windowed attention (fp32, unchanged)
// ---------------------------------------------------------------------------
__global__ void attn2_kernel(const float* __restrict__ q2, const float* __restrict__ kv2,
                             float* __restrict__ concat, float* __restrict__ lmpart)
{
    __shared__ float sQ[4][512];
    __shared__ float sKT[4][512];
    __shared__ float sV[4][512];
    __shared__ float sS[4][16 * 17];
    const int w = threadIdx.x >> 5, lane = threadIdx.x & 31;
    const int gw = blockIdx.x * 4 + w;
    const int b = gw >> 10;
    const int rem = gw & 1023;
    const int h = rem >> 8;
    const int win = rem & 255;
    const int wy = win >> 4, wx = win & 15;

    for (int t = 0; t < 16; t++) {
        int n = (wy * 4 + (t >> 2)) * KH + wx * 4 + (t & 3);
        sQ[w][t * 32 + lane]  = q2[((size_t)b * KN + n) * 128 + h * 32 + lane];
        sKT[w][lane * 16 + t] = kv2[((size_t)b * KN + n) * 256 + h * 32 + lane];
        sV[w][t * 32 + lane]  = kv2[((size_t)b * KN + n) * 256 + 128 + h * 32 + lane];
    }
    __syncwarp();

    #pragma unroll
    for (int r = 0; r < 8; r++) {
        int e = r * 32 + lane;
        int i = e >> 4, j = e & 15;
        float acc = 0.f;
        #pragma unroll
        for (int k = 0; k < 32; k++) acc += sQ[w][i * 32 + k] * sKT[w][k * 16 + j];
        sS[w][i * 17 + j] = acc * KSCALE;
    }
    __syncwarp();

    if (lane < 16) {
        float mx = -1e30f;
        #pragma unroll
        for (int j = 0; j < 16; j++) mx = fmaxf(mx, sS[w][lane * 17 + j]);
        float s = 0.f;
        #pragma unroll
        for (int j = 0; j < 16; j++) {
            float e = __expf(sS[w][lane * 17 + j] - mx);
            sS[w][lane * 17 + j] = e;
            s += e;
        }
        float inv = 1.f / s;
        #pragma unroll
        for (int j = 0; j < 16; j++) sS[w][lane * 17 + j] *= inv;
    }
    __syncwarp();

    if (lane < 16) {
        float cs = 0.f;
        #pragma unroll
        for (int i = 0; i < 16; i++) cs += sS[w][i * 17 + lane];
        lmpart[(((size_t)(b * 4 + h) * 256) + win) * 16 + lane] = cs;
    }

    for (int i = 0; i < 16; i++) {
        float acc = 0.f;
        #pragma unroll
        for (int j = 0; j < 16; j++) acc += sS[w][i * 17 + j] * sV[w][j * 32 + lane];
        int n = (wy * 4 + (i >> 2)) * KH + wx * 4 + (i & 3);
        concat[((size_t)b * KN + n) * 256 + 128 + h * 32 + lane] = acc;
    }
}

__global__ void g_reduce(const float* __restrict__ gpart, float* __restrict__ gred)
{
    int idx = blockIdx.x * 256 + threadIdx.x;
    int b = idx >> 10, m = idx & 1023;
    float s = 0.f;
    for (int j = 0; j < 512; j++)
        s += gpart[((size_t)b * 512 + j) * 1024 + m];
    gred[idx] = s * (1.f / 16384.f);
}

__global__ void mask_kernel(const float* __restrict__ gred, const float* __restrict__ lmpart,
                            float* __restrict__ m1, float* __restrict__ m2)
{
    int idx = blockIdx.x * 256 + threadIdx.x;
    int b = idx >> 12, n = idx & 4095;
    int y = n >> 6, x = n & 63;
    float gv = gred[b * 1024 + (y >> 1) * 32 + (x >> 1)];
    int win = (y >> 2) * 16 + (x >> 2);
    int t = (y & 3) * 4 + (x & 3);
    float lv = 0.f;
    #pragma unroll
    for (int h = 0; h < 4; h++)
        lv += lmpart[(((size_t)(b * 4 + h) * 256) + win) * 16 + t];
    lv *= (1.f / 64.f);
    float val = gv + lv;
    m1[b * KN + y * KH + x] = val;
    m2[b * KN + x * KH + y] = val;
}

// ---------------------------------------------------------------------------
// launcher
// ---------------------------------------------------------------------------
extern "C" void kernel_launch(void* const* d_in, const int* in_sizes, int n_in,
                              void* d_out, int out_size)
{
    const float* x      = (const float*)d_in[0];
    const float* q1_w   = (const float*)d_in[1];
    const float* q1_b   = (const float*)d_in[2];
    const float* kv1_w  = (const float*)d_in[3];
    const float* kv1_b  = (const float*)d_in[4];
    const float* q2_w   = (const float*)d_in[5];
    const float* q2_b   = (const float*)d_in[6];
    const float* kv2_w  = (const float*)d_in[7];
    const float* kv2_b  = (const float*)d_in[8];
    const float* lepe_w = (const float*)d_in[9];
    const float* lepe_b = (const float*)d_in[10];
    const float* lcw    = (const float*)d_in[11];
    const float* lcb    = (const float*)d_in[12];
    const float* sr_w   = (const float*)d_in[13];
    const float* sr_b   = (const float*)d_in[14];
    const float* norm_w = (const float*)d_in[15];
    const float* norm_b = (const float*)d_in[16];
    const float* proj_w = (const float*)d_in[17];
    const float* proj_b = (const float*)d_in[18];
    (void)in_sizes; (void)n_in; (void)out_size;

    float* scratch = nullptr;
    cudaGetSymbolAddress((void**)&scratch, g_scratch);
    __half* hs = nullptr;
    cudaGetSymbolAddress((void**)&hs, g_scratch_h);

    float* lepe_lin = scratch + OFF_LEPE_LIN;
    float* lepe     = scratch + OFF_LEPE;
    float* q2buf    = scratch + OFF_Q2;
    float* kv2buf   = scratch + OFF_KV2;
    float* xs       = scratch + OFF_XS;
    float* concat   = scratch + OFF_CONCAT;
    float* gpart    = scratch + OFF_GPART;
    float* gred     = scratch + OFF_GRED;
    float* lmpart   = scratch + OFF_LMPART;

    __half* xh     = hs + HOFF_XH;
    __half* xim    = hs + HOFF_XIM;
    __half* xsh    = hs + HOFF_XSH;
    __half* ch     = hs + HOFF_CH;
    __half* q1h    = hs + HOFF_Q1H;
    __half* kv1h   = hs + HOFF_KV1H;
    __half* wq1t   = hs + HOFF_WQ1;
    __half* wq2t   = hs + HOFF_WQ2;
    __half* wkv1t  = hs + HOFF_WKV1;
    __half* wkv2t  = hs + HOFF_WKV2;
    __half* wlepet = hs + HOFF_WLEPE;
    __half* wprojt = hs + HOFF_WPROJ;
    __half* wsrt   = hs + HOFF_WSR;

    float* out = (float*)d_out;
    float* m1  = out + (size_t)KB * KN * KC;
    float* m2  = m1 + (size_t)KB * KN;

    cudaFuncSetAttribute(hgemm<false>, cudaFuncAttributeMaxDynamicSharedMemorySize, HG_SMEM);
    cudaFuncSetAttribute(hgemm<true>,  cudaFuncAttributeMaxDynamicSharedMemorySize, HG_SMEM);
    cudaFuncSetAttribute(attn1_kernel, cudaFuncAttributeMaxDynamicSharedMemorySize, ATTN1_SMEM);

    // conversions
    cvt_f16<<<16384, 256>>>(x, xh);
    transpose_f16<<<128, 256>>>(q1_w, wq1t, 256, 128);
    transpose_f16<<<128, 256>>>(q2_w, wq2t, 256, 128);
    transpose_f16<<<256, 256>>>(kv1_w, wkv1t, 256, 256);
    transpose_f16<<<256, 256>>>(kv2_w, wkv2t, 256, 256);
    transpose_f16<<<256, 256>>>(lepe_w, wlepet, 256, 256);
    transpose_f16<<<256, 256>>>(proj_w, wprojt, 256, 256);
    repack_sr<<<1024, 256>>>(sr_w, wsrt);

    // lepe branch
    hgemm<false><<<dim3(2, 128), 256, HG_SMEM>>>(xh, wlepet, lepe_b, lepe_lin,
                                                 KB * KN, 256, 256, 1.f);
    lepe_conv<<<16384, 256>>>(lepe_lin, lcw, lcb, lepe);

    // projections from x
    hgemm<true><<<dim3(1, 128), 256, HG_SMEM>>>(xh, wq1t, q1_b, q1h,
                                                KB * KN, 128, 256, 1.f);
    hgemm<false><<<dim3(1, 128), 256, HG_SMEM>>>(xh, wq2t, q2_b, q2buf,
                                                 KB * KN, 128, 256, 1.f);
    hgemm<false><<<dim3(2, 128), 256, HG_SMEM>>>(xh, wkv2t, kv2_b, kv2buf,
                                                 KB * KN, 256, 256, 1.f);

    // spatial reduction -> LN -> GELU -> kv1
    im2col<<<16384, 256>>>(xh, xim);
    hgemm<false><<<dim3(2, 32), 256, HG_SMEM>>>(xim, wsrt, sr_b, xs,
                                                KB * KN1, 256, 1024, 1.f);
    ln_gelu<<<KB * KN1, 256>>>(xs, norm_w, norm_b, xsh);
    hgemm<true><<<dim3(2, 32), 256, HG_SMEM>>>(xsh, wkv1t, kv1_b, kv1h,
                                               KB * KN1, 256, 256, 1.f);

    // attention branches
    attn1_kernel<<<dim3(128, 4, 4), 256, ATTN1_SMEM>>>(q1h, kv1h, concat, gpart);
    g_reduce<<<16, 256>>>(gpart, gred);
    attn2_kernel<<<1024, 128>>>(q2buf, kv2buf, concat, lmpart);
    mask_kernel<<<64, 256>>>(gred, lmpart, m1, m2);

    // fused (concat + lepe) @ proj + bias, x2 epilogue -> d_out
    addcat<<<16384, 256>>>(concat, lepe, ch);
    hgemm<false><<<dim3(2, 128), 256, HG_SMEM>>>(ch, wprojt, proj_b, out,
                                                 KB * KN, 256, 256, 2.f);
}

// round 8
// speedup vs baseline: 2.8836x; 1.3106x over previous
#include <cuda_runtime.h>
#include <cuda_fp16.h>
#include <mma.h>
#include <math.h>
#include <stdint.h>

using namespace nvcuda;

#define KB   4
#define KN   4096
#define KC   256
#define KH   64
#define KN1  1024
#define KSCALE 0.17677669529663687f

// fp32 scratch
#define OFF_LEPE     ((size_t)0)
#define OFF_Q2       (OFF_LEPE   + (size_t)KB*KN*KC)
#define OFF_KV2      (OFF_Q2     + (size_t)KB*KN*128)
#define OFF_XS       (OFF_KV2    + (size_t)KB*KN*256)
#define OFF_CONCAT   (OFF_XS     + (size_t)KB*KN1*256)
#define OFF_GPART    (OFF_CONCAT + (size_t)KB*KN*KC)
#define OFF_GRED     (OFF_GPART  + (size_t)KB*4*128*1024)
#define OFF_LMPART   (OFF_GRED   + (size_t)KB*1024)
#define SCRATCH_TOT  (OFF_LMPART + (size_t)KB*4*256*16)

__device__ float g_scratch[SCRATCH_TOT];

// f16 scratch
#define HOFF_XH    ((size_t)0)
#define HOFF_XSH   (HOFF_XH   + (size_t)4194304)
#define HOFF_Q1H   (HOFF_XSH  + (size_t)1048576)
#define HOFF_KV1H  (HOFF_Q1H  + (size_t)2097152)
#define HOFF_LEPEH (HOFF_KV1H + (size_t)1048576)
#define HOFF_WFUSE (HOFF_LEPEH+ (size_t)4194304)
#define HOFF_WKV1  (HOFF_WFUSE+ (size_t)196608)
#define HOFF_WPROJ (HOFF_WKV1 + (size_t)65536)
#define HOFF_WSR   (HOFF_WPROJ+ (size_t)65536)
#define HSCRATCH_TOT (HOFF_WSR + (size_t)262144)

__device__ __half g_scratch_h[HSCRATCH_TOT];

// ---------------------------------------------------------------------------
// common wmma tile config: 128x128 tile, 256 threads = 8 warps (2 x 4)
// ---------------------------------------------------------------------------
#define APITCH 72
#define CPITCH 132
#define HG_SMEM (128 * CPITCH * 4)

#define GEMM_CORE_DECL \
    extern __shared__ char smraw[]; \
    __half* As = (__half*)smraw; \
    __half* Bs = As + 128 * APITCH; \
    float*  Cst = (float*)smraw; \
    const int tid = threadIdx.x; \
    const int wid = tid >> 5; \
    const int warp_row = wid >> 2; \
    const int warp_col = wid & 3; \
    wmma::fragment<wmma::accumulator, 16, 16, 16, float> acc[4][2]; \
    _Pragma("unroll") \
    for (int mt = 0; mt < 4; mt++) \
        _Pragma("unroll") \
        for (int nt = 0; nt < 2; nt++) \
            wmma::fill_fragment(acc[mt][nt], 0.f);

#define GEMM_CORE_MMA \
    __syncthreads(); \
    _Pragma("unroll") \
    for (int ks = 0; ks < 4; ks++) { \
        wmma::fragment<wmma::matrix_a, 16, 16, 16, __half, wmma::row_major> af[4]; \
        wmma::fragment<wmma::matrix_b, 16, 16, 16, __half, wmma::col_major> bf[2]; \
        _Pragma("unroll") \
        for (int mt = 0; mt < 4; mt++) \
            wmma::load_matrix_sync(af[mt], As + (warp_row * 64 + mt * 16) * APITCH + ks * 16, APITCH); \
        _Pragma("unroll") \
        for (int nt = 0; nt < 2; nt++) \
            wmma::load_matrix_sync(bf[nt], Bs + (warp_col * 32 + nt * 16) * APITCH + ks * 16, APITCH); \
        _Pragma("unroll") \
        for (int mt = 0; mt < 4; mt++) \
            _Pragma("unroll") \
            for (int nt = 0; nt < 2; nt++) \
                wmma::mma_sync(acc[mt][nt], af[mt], bf[nt], acc[mt][nt]); \
    } \
    __syncthreads();

#define GEMM_STORE_STAGE \
    _Pragma("unroll") \
    for (int mt = 0; mt < 4; mt++) \
        _Pragma("unroll") \
        for (int nt = 0; nt < 2; nt++) \
            wmma::store_matrix_sync(Cst + (warp_row * 64 + mt * 16) * CPITCH + warp_col * 32 + nt * 16, \
                                    acc[mt][nt], CPITCH, wmma::mem_row_major); \
    __syncthreads();

// ---------------------------------------------------------------------------
// generic hgemm (used for kv1): C = A[M][K] @ BT[N][K]^T + bias, f16 out
// ---------------------------------------------------------------------------
__global__ __launch_bounds__(256)
void hgemm_h(const __half* __restrict__ A, const __half* __restrict__ BT,
             const float* __restrict__ bias, __half* __restrict__ Cout,
             int M, int N, int K)
{
    GEMM_CORE_DECL
    const int row0 = blockIdx.y * 128;
    const int col0 = blockIdx.x * 128;
    const int kn = K >> 6;
    for (int c = 0; c < kn; c++) {
        #pragma unroll
        for (int i = 0; i < 4; i++) {
            int li = i * 256 + tid;
            int r = li >> 3, q = (li & 7) * 8;
            *(uint4*)(As + r * APITCH + q) = *(const uint4*)(A + (size_t)(row0 + r) * K + c * 64 + q);
            *(uint4*)(Bs + r * APITCH + q) = *(const uint4*)(BT + (size_t)(col0 + r) * K + c * 64 + q);
        }
        GEMM_CORE_MMA
    }
    GEMM_STORE_STAGE
    #pragma unroll
    for (int i = 0; i < 16; i++) {
        int lin = i * 256 + tid;
        int r = lin >> 5, c4 = (lin & 31) * 4;
        const float* s = Cst + r * CPITCH + c4;
        __half2 h0 = __floats2half2_rn(s[0] + bias[col0 + c4 + 0], s[1] + bias[col0 + c4 + 1]);
        __half2 h1 = __floats2half2_rn(s[2] + bias[col0 + c4 + 2], s[3] + bias[col0 + c4 + 3]);
        uint2 pk; pk.x = *(uint32_t*)&h0; pk.y = *(uint32_t*)&h1;
        *(uint2*)(Cout + (size_t)(row0 + r) * N + col0 + c4) = pk;
    }
}

// ---------------------------------------------------------------------------
// fused projection GEMM: A = xh [16384][256], BT = wfused [768][256]
// col tiles: 0->q1h(f16,p128) 1->q2(f32,p128) 2,3->kv2(f32,p256) 4,5->lepeh(f16,p256)
// ---------------------------------------------------------------------------
__global__ __launch_bounds__(256)
void qkv_gemm(const __half* __restrict__ A, const __half* __restrict__ BT,
              const float* __restrict__ q1_b, const float* __restrict__ q2_b,
              const float* __restrict__ kv2_b, const float* __restrict__ lepe_b,
              __half* __restrict__ q1h, float* __restrict__ q2o,
              float* __restrict__ kv2o, __half* __restrict__ lepeh)
{
    GEMM_CORE_DECL
    const int row0 = blockIdx.y * 128;
    const int col0 = blockIdx.x * 128;
    for (int c = 0; c < 4; c++) {
        #pragma unroll
        for (int i = 0; i < 4; i++) {
            int li = i * 256 + tid;
            int r = li >> 3, q = (li & 7) * 8;
            *(uint4*)(As + r * APITCH + q) = *(const uint4*)(A + (size_t)(row0 + r) * 256 + c * 64 + q);
            *(uint4*)(Bs + r * APITCH + q) = *(const uint4*)(BT + (size_t)(col0 + r) * 256 + c * 64 + q);
        }
        GEMM_CORE_MMA
    }
    GEMM_STORE_STAGE

    const int t = blockIdx.x;
    __half* hdst = nullptr; float* fdst = nullptr;
    const float* bp; int pitch, cofs;
    switch (t) {
        case 0:  hdst = q1h;  bp = q1_b;  pitch = 128; cofs = 0;   break;
        case 1:  fdst = q2o;  bp = q2_b;  pitch = 128; cofs = 0;   break;
        case 2:  fdst = kv2o; bp = kv2_b; pitch = 256; cofs = 0;   break;
        case 3:  fdst = kv2o; bp = kv2_b; pitch = 256; cofs = 128; break;
        case 4:  hdst = lepeh; bp = lepe_b; pitch = 256; cofs = 0;   break;
        default: hdst = lepeh; bp = lepe_b; pitch = 256; cofs = 128; break;
    }
    #pragma unroll
    for (int i = 0; i < 16; i++) {
        int lin = i * 256 + tid;
        int r = lin >> 5, c4 = (lin & 31) * 4;
        const float* s = Cst + r * CPITCH + c4;
        float v0 = s[0] + bp[cofs + c4 + 0];
        float v1 = s[1] + bp[cofs + c4 + 1];
        float v2 = s[2] + bp[cofs + c4 + 2];
        float v3 = s[3] + bp[cofs + c4 + 3];
        size_t o = (size_t)(row0 + r) * pitch + cofs + c4;
        if (hdst) {
            __half2 h0 = __floats2half2_rn(v0, v1);
            __half2 h1 = __floats2half2_rn(v2, v3);
            uint2 pk; pk.x = *(uint32_t*)&h0; pk.y = *(uint32_t*)&h1;
            *(uint2*)(hdst + o) = pk;
        } else {
            *(float4*)(fdst + o) = make_float4(v0, v1, v2, v3);
        }
    }
}

// ---------------------------------------------------------------------------
// sr conv as GEMM with inline im2col gather from xh. M=4096, N=256, K=1024.
// k = kk*256 + ci, kk=(ky,kx). f32 out (feeds LN).
// ---------------------------------------------------------------------------
__global__ __launch_bounds__(256)
void sr_gemm(const __half* __restrict__ xh, const __half* __restrict__ BT,
             const float* __restrict__ bias, float* __restrict__ C)
{
    GEMM_CORE_DECL
    const int row0 = blockIdx.y * 128;
    const int col0 = blockIdx.x * 128;
    for (int c = 0; c < 16; c++) {
        const int kk = c >> 2;              // 64-chunk c sits inside one (ky,kx)
        const int ky = kk >> 1, kx = kk & 1;
        const int cib = (c & 3) * 64;
        #pragma unroll
        for (int i = 0; i < 4; i++) {
            int li = i * 256 + tid;
            int r = li >> 3, q = (li & 7) * 8;
            int m = row0 + r;
            int b = m >> 10, p = m & 1023;
            int oy = p >> 5, ox = p & 31;
            int n = (2 * oy + ky) * KH + 2 * ox + kx;
            *(uint4*)(As + r * APITCH + q) =
                *(const uint4*)(xh + ((size_t)b * KN + n) * 256 + cib + q);
            *(uint4*)(Bs + r * APITCH + q) =
                *(const uint4*)(BT + (size_t)(col0 + r) * 1024 + c * 64 + q);
        }
        GEMM_CORE_MMA
    }
    GEMM_STORE_STAGE
    #pragma unroll
    for (int i = 0; i < 16; i++) {
        int lin = i * 256 + tid;
        int r = lin >> 5, c4 = (lin & 31) * 4;
        const float* s = Cst + r * CPITCH + c4;
        float4 v = make_float4(s[0] + bias[col0 + c4 + 0], s[1] + bias[col0 + c4 + 1],
                               s[2] + bias[col0 + c4 + 2], s[3] + bias[col0 + c4 + 3]);
        *(float4*)(C + (size_t)(row0 + r) * 256 + col0 + c4) = v;
    }
}

// ---------------------------------------------------------------------------
// output GEMM: A = f16(concat + lepe) on the fly, x2 epilogue, f32 out
// ---------------------------------------------------------------------------
__global__ __launch_bounds__(256)
void proj_gemm(const float* __restrict__ Acat, const float* __restrict__ Alepe,
               const __half* __restrict__ BT, const float* __restrict__ bias,
               float* __restrict__ C)
{
    GEMM_CORE_DECL
    const int row0 = blockIdx.y * 128;
    const int col0 = blockIdx.x * 128;
    for (int c = 0; c < 4; c++) {
        #pragma unroll
        for (int i = 0; i < 4; i++) {
            int li = i * 256 + tid;
            int r = li >> 3, qf = (li & 7) * 8;
            size_t ai = (size_t)(row0 + r) * 256 + c * 64 + qf;
            float4 a0 = *(const float4*)(Acat + ai);
            float4 a1 = *(const float4*)(Acat + ai + 4);
            float4 l0 = *(const float4*)(Alepe + ai);
            float4 l1 = *(const float4*)(Alepe + ai + 4);
            __half2 h0 = __floats2half2_rn(a0.x + l0.x, a0.y + l0.y);
            __half2 h1 = __floats2half2_rn(a0.z + l0.z, a0.w + l0.w);
            __half2 h2 = __floats2half2_rn(a1.x + l1.x, a1.y + l1.y);
            __half2 h3 = __floats2half2_rn(a1.z + l1.z, a1.w + l1.w);
            uint4 pk;
            pk.x = *(uint32_t*)&h0; pk.y = *(uint32_t*)&h1;
            pk.z = *(uint32_t*)&h2; pk.w = *(uint32_t*)&h3;
            *(uint4*)(As + r * APITCH + qf) = pk;
            *(uint4*)(Bs + r * APITCH + qf) =
                *(const uint4*)(BT + (size_t)(col0 + r) * 256 + c * 64 + qf);
        }
        GEMM_CORE_MMA
    }
    GEMM_STORE_STAGE
    #pragma unroll
    for (int i = 0; i < 16; i++) {
        int lin = i * 256 + tid;
        int r = lin >> 5, c4 = (lin & 31) * 4;
        const float* s = Cst + r * CPITCH + c4;
        float4 v = make_float4(2.f * (s[0] + bias[col0 + c4 + 0]),
                               2.f * (s[1] + bias[col0 + c4 + 1]),
                               2.f * (s[2] + bias[col0 + c4 + 2]),
                               2.f * (s[3] + bias[col0 + c4 + 3]));
        *(float4*)(C + (size_t)(row0 + r) * 256 + col0 + c4) = v;
    }
}

// ---------------------------------------------------------------------------
// prep: x->f16 (vectorized)
// ---------------------------------------------------------------------------
__global__ void cvt_f16(const float* __restrict__ in, __half* __restrict__ out) {
    int idx = blockIdx.x * 256 + threadIdx.x;      // 1M, x4 elems
    float4 v = *(const float4*)(in + (size_t)idx * 4);
    __half2 h0 = __floats2half2_rn(v.x, v.y);
    __half2 h1 = __floats2half2_rn(v.z, v.w);
    uint2 pk; pk.x = *(uint32_t*)&h0; pk.y = *(uint32_t*)&h1;
    *(uint2*)(out + (size_t)idx * 4) = pk;
}

// all weight transposes/repacks in one kernel
__global__ void prep_w(const float* __restrict__ q1w, const float* __restrict__ q2w,
                       const float* __restrict__ kv2w, const float* __restrict__ lepew,
                       const float* __restrict__ kv1w, const float* __restrict__ projw,
                       const float* __restrict__ srw,
                       __half* __restrict__ wfused, __half* __restrict__ wkv1t,
                       __half* __restrict__ wprojt, __half* __restrict__ wsrt)
{
    int idx = blockIdx.x * 256 + threadIdx.x;      // 589824 total
    if (idx < 196608) {                             // wfused[768][256]
        int r = idx >> 8, k = idx & 255;
        float v;
        if (r < 128)      v = q1w[(size_t)k * 128 + r];
        else if (r < 256) v = q2w[(size_t)k * 128 + (r - 128)];
        else if (r < 512) v = kv2w[(size_t)k * 256 + (r - 256)];
        else              v = lepew[(size_t)k * 256 + (r - 512)];
        wfused[idx] = __float2half(v);
    } else if (idx < 262144) {                      // wkv1t[256][256]
        int i = idx - 196608;
        int n = i >> 8, k = i & 255;
        wkv1t[i] = __float2half(kv1w[(size_t)k * 256 + n]);
    } else if (idx < 327680) {                      // wprojt[256][256]
        int i = idx - 262144;
        int n = i >> 8, k = i & 255;
        wprojt[i] = __float2half(projw[(size_t)k * 256 + n]);
    } else {                                        // wsrt[256][1024]
        int i = idx - 327680;
        int co = i >> 10, k = i & 1023;
        int kk = k >> 8, ci = k & 255;
        wsrt[i] = __float2half(srw[(size_t)co * 1024 + ci * 4 + kk]);
    }
}

// ---------------------------------------------------------------------------
// depthwise 3x3 conv pad 1, f16 in, f32 out, 2 channels per thread
// ---------------------------------------------------------------------------
__global__ void lepe_conv(const __half* __restrict__ in, const float* __restrict__ w,
                          const float* __restrict__ bias, float* __restrict__ out)
{
    int idx = blockIdx.x * 256 + threadIdx.x;      // B*N*128
    int c2 = idx & 127;
    int n = (idx >> 7) & 4095;
    int b = idx >> 19;
    int y = n >> 6, x = n & 63;
    int c = c2 * 2;
    float a0 = bias[c], a1 = bias[c + 1];
    #pragma unroll
    for (int dy = -1; dy <= 1; dy++) {
        int yy = y + dy;
        if (yy < 0 || yy >= KH) continue;
        #pragma unroll
        for (int dx = -1; dx <= 1; dx++) {
            int xx = x + dx;
            if (xx < 0 || xx >= KH) continue;
            __half2 v = *(const __half2*)(in + ((size_t)b * KN + yy * KH + xx) * 256 + c);
            float2 f = __half22float2(v);
            int t = (dy + 1) * 3 + dx + 1;
            a0 += f.x * w[c * 9 + t];
            a1 += f.y * w[(c + 1) * 9 + t];
        }
    }
    *(float2*)(out + ((size_t)b * KN + n) * 256 + c) = make_float2(a0, a1);
}

// ---------------------------------------------------------------------------
// LayerNorm + GELU -> f16
// ---------------------------------------------------------------------------
__global__ void ln_gelu(const float* __restrict__ xs, const float* __restrict__ nw,
                        const float* __restrict__ nb, __half* __restrict__ o16)
{
    int row = blockIdx.x;
    int tid = threadIdx.x;
    float v = xs[(size_t)row * 256 + tid];
    __shared__ float red[16];
    float s = v, sq = v * v;
    #pragma unroll
    for (int o = 16; o; o >>= 1) {
        s  += __shfl_xor_sync(0xffffffffu, s, o);
        sq += __shfl_xor_sync(0xffffffffu, sq, o);
    }
    int w = tid >> 5, lane = tid & 31;
    if (lane == 0) { red[w] = s; red[8 + w] = sq; }
    __syncthreads();
    if (tid == 0) {
        float S = 0.f, SQ = 0.f;
        for (int i = 0; i < 8; i++) { S += red[i]; SQ += red[8 + i]; }
        red[0] = S; red[8] = SQ;
    }
    __syncthreads();
    float mean = red[0] * (1.f / 256.f);
    float var  = red[8] * (1.f / 256.f) - mean * mean;
    float t = (v - mean) * rsqrtf(var + 1e-5f) * nw[tid] + nb[tid];
    float g = 0.5f * t * (1.f + erff(t * 0.70710678118654752f));
    o16[(size_t)row * 256 + tid] = __float2half(g);
}

// ---------------------------------------------------------------------------
// Branch-1 attention, 512 threads = 16 warps, 3 smem passes over S.
// ---------------------------------------------------------------------------
#define SPITCH 1040
#define PPITCH 1032
#define ATTN1_SMEM (32 * SPITCH * 4 + 32 * PPITCH * 2 + 128)

__global__ __launch_bounds__(512)
void attn1_kernel(const __half* __restrict__ q1h, const __half* __restrict__ kv1h,
                  float* __restrict__ concat, float* __restrict__ gpart)
{
    extern __shared__ char smraw[];
    float* S = (float*)smraw;
    __half* P = (__half*)(smraw + 32 * SPITCH * 4);
    float* rs = (float*)(smraw + 32 * SPITCH * 4 + 32 * PPITCH * 2);
    const int tid = threadIdx.x;
    const int w = tid >> 5, lane = tid & 31;
    const int qt = blockIdx.x, h = blockIdx.y, b = blockIdx.z;

    // ---- QK^T: warp w covers key cols [w*64, w*64+64) ----
    {
        wmma::fragment<wmma::matrix_a, 16, 16, 16, __half, wmma::row_major> af[2][2];
        #pragma unroll
        for (int mt = 0; mt < 2; mt++)
            #pragma unroll
            for (int ks = 0; ks < 2; ks++)
                wmma::load_matrix_sync(af[mt][ks],
                    q1h + ((size_t)b * KN + qt * 32 + mt * 16) * 128 + h * 32 + ks * 16, 128);
        #pragma unroll
        for (int nt = 0; nt < 4; nt++) {
            int col = w * 64 + nt * 16;
            wmma::fragment<wmma::accumulator, 16, 16, 16, float> a0, a1;
            wmma::fill_fragment(a0, 0.f);
            wmma::fill_fragment(a1, 0.f);
            #pragma unroll
            for (int ks = 0; ks < 2; ks++) {
                wmma::fragment<wmma::matrix_b, 16, 16, 16, __half, wmma::col_major> bf;
                wmma::load_matrix_sync(bf,
                    kv1h + ((size_t)b * KN1 + col) * 256 + h * 32 + ks * 16, 256);
                wmma::mma_sync(a0, af[0][ks], bf, a0);
                wmma::mma_sync(a1, af[1][ks], bf, a1);
            }
            #pragma unroll
            for (int e = 0; e < a0.num_elements; e++) { a0.x[e] *= KSCALE; a1.x[e] *= KSCALE; }
            wmma::store_matrix_sync(S + 0 * SPITCH + col, a0, SPITCH, wmma::mem_row_major);
            wmma::store_matrix_sync(S + 16 * SPITCH + col, a1, SPITCH, wmma::mem_row_major);
        }
    }
    __syncthreads();

    // ---- exp + row sums (no max subtraction: scores are O(1)) ----
    #pragma unroll
    for (int ri = 0; ri < 2; ri++) {
        int r = w * 2 + ri;
        float ssum = 0.f;
        #pragma unroll 8
        for (int m = lane; m < 1024; m += 32) {
            float e = __expf(S[r * SPITCH + m]);
            S[r * SPITCH + m] = e;
            ssum += e;
        }
        #pragma unroll
        for (int o = 16; o; o >>= 1) ssum += __shfl_xor_sync(0xffffffffu, ssum, o);
        if (lane == 0) rs[r] = ssum;
    }
    __syncthreads();
    if (tid < 32) rs[tid] = 1.f / rs[tid];
    __syncthreads();

    // ---- normalize + convert to f16 + deterministic column sums ----
    #pragma unroll
    for (int mi = 0; mi < 2; mi++) {
        int m = tid + mi * 512;
        float cs = 0.f;
        #pragma unroll
        for (int r = 0; r < 32; r++) {
            float v = S[r * SPITCH + m] * rs[r];
            cs += v;
            P[r * PPITCH + m] = __float2half(v);
        }
        gpart[(((size_t)(b * 4 + h) * 128) + qt) * 1024 + m] = cs;
    }
    __syncthreads();

    // ---- PV: warp w handles keys [w*64, (w+1)*64), partials into S region ----
    {
        wmma::fragment<wmma::accumulator, 16, 16, 16, float> acc2[2][2];
        #pragma unroll
        for (int mt = 0; mt < 2; mt++)
            #pragma unroll
            for (int nt = 0; nt < 2; nt++)
                wmma::fill_fragment(acc2[mt][nt], 0.f);
        #pragma unroll
        for (int ks = 0; ks < 4; ks++) {
            int kk = w * 64 + ks * 16;
            wmma::fragment<wmma::matrix_a, 16, 16, 16, __half, wmma::row_major> ap[2];
            wmma::fragment<wmma::matrix_b, 16, 16, 16, __half, wmma::row_major> bp[2];
            #pragma unroll
            for (int mt = 0; mt < 2; mt++)
                wmma::load_matrix_sync(ap[mt], P + (mt * 16) * PPITCH + kk, PPITCH);
            #pragma unroll
            for (int nt = 0; nt < 2; nt++)
                wmma::load_matrix_sync(bp[nt],
                    kv1h + ((size_t)b * KN1 + kk) * 256 + 128 + h * 32 + nt * 16, 256);
            #pragma unroll
            for (int mt = 0; mt < 2; mt++)
                #pragma unroll
                for (int nt = 0; nt < 2; nt++)
                    wmma::mma_sync(acc2[mt][nt], ap[mt], bp[nt], acc2[mt][nt]);
        }
        float* Sp = S + w * 1024;
        #pragma unroll
        for (int mt = 0; mt < 2; mt++)
            #pragma unroll
            for (int nt = 0; nt < 2; nt++)
                wmma::store_matrix_sync(Sp + mt * 16 * 32 + nt * 16, acc2[mt][nt],
                                        32, wmma::mem_row_major);
    }
    __syncthreads();

    // reduce 16 warp partials -> concat
    #pragma unroll
    for (int ii = 0; ii < 2; ii++) {
        int idx = tid + ii * 512;
        int q = idx >> 5, dd = idx & 31;
        float sum = 0.f;
        #pragma unroll
        for (int j = 0; j < 16; j++) sum += S[j * 1024 + idx];
        concat[((size_t)b * KN + qt * 32 + q) * 256 + h * 32 + dd] = sum;
    }
}

// ---------------------------------------------------------------------------
// Branch-2 windowed attention (fp32)
// ---------------------------------------------------------------------------
__global__ void attn2_kernel(const float* __restrict__ q2, const float* __restrict__ kv2,
                             float* __restrict__ concat, float* __restrict__ lmpart)
{
    __shared__ float sQ[4][512];
    __shared__ float sKT[4][512];
    __shared__ float sV[4][512];
    __shared__ float sS[4][16 * 17];
    const int w = threadIdx.x >> 5, lane = threadIdx.x & 31;
    const int gw = blockIdx.x * 4 + w;
    const int b = gw >> 10;
    const int rem = gw & 1023;
    const int h = rem >> 8;
    const int win = rem & 255;
    const int wy = win >> 4, wx = win & 15;

    for (int t = 0; t < 16; t++) {
        int n = (wy * 4 + (t >> 2)) * KH + wx * 4 + (t & 3);
        sQ[w][t * 32 + lane]  = q2[((size_t)b * KN + n) * 128 + h * 32 + lane];
        sKT[w][lane * 16 + t] = kv2[((size_t)b * KN + n) * 256 + h * 32 + lane];
        sV[w][t * 32 + lane]  = kv2[((size_t)b * KN + n) * 256 + 128 + h * 32 + lane];
    }
    __syncwarp();

    #pragma unroll
    for (int r = 0; r < 8; r++) {
        int e = r * 32 + lane;
        int i = e >> 4, j = e & 15;
        float acc = 0.f;
        #pragma unroll
        for (int k = 0; k < 32; k++) acc += sQ[w][i * 32 + k] * sKT[w][k * 16 + j];
        sS[w][i * 17 + j] = acc * KSCALE;
    }
    __syncwarp();

    if (lane < 16) {
        float mx = -1e30f;
        #pragma unroll
        for (int j = 0; j < 16; j++) mx = fmaxf(mx, sS[w][lane * 17 + j]);
        float s = 0.f;
        #pragma unroll
        for (int j = 0; j < 16; j++) {
            float e = __expf(sS[w][lane * 17 + j] - mx);
            sS[w][lane * 17 + j] = e;
            s += e;
        }
        float inv = 1.f / s;
        #pragma unroll
        for (int j = 0; j < 16; j++) sS[w][lane * 17 + j] *= inv;
    }
    __syncwarp();

    if (lane < 16) {
        float cs = 0.f;
        #pragma unroll
        for (int i = 0; i < 16; i++) cs += sS[w][i * 17 + lane];
        lmpart[(((size_t)(b * 4 + h) * 256) + win) * 16 + lane] = cs;
    }

    for (int i = 0; i < 16; i++) {
        float acc = 0.f;
        #pragma unroll
        for (int j = 0; j < 16; j++) acc += sS[w][i * 17 + j] * sV[w][j * 32 + lane];
        int n = (wy * 4 + (i >> 2)) * KH + wx * 4 + (i & 3);
        concat[((size_t)b * KN + n) * 256 + 128 + h * 32 + lane] = acc;
    }
}

__global__ void g_reduce(const float* __restrict__ gpart, float* __restrict__ gred)
{
    int idx = blockIdx.x * 256 + threadIdx.x;
    int b = idx >> 10, m = idx & 1023;
    float s = 0.f;
    for (int j = 0; j < 512; j++)
        s += gpart[((size_t)b * 512 + j) * 1024 + m];
    gred[idx] = s * (1.f / 16384.f);
}

__global__ void mask_kernel(const float* __restrict__ gred, const float* __restrict__ lmpart,
                            float* __restrict__ m1, float* __restrict__ m2)
{
    int idx = blockIdx.x * 256 + threadIdx.x;
    int b = idx >> 12, n = idx & 4095;
    int y = n >> 6, x = n & 63;
    float gv = gred[b * 1024 + (y >> 1) * 32 + (x >> 1)];
    int win = (y >> 2) * 16 + (x >> 2);
    int t = (y & 3) * 4 + (x & 3);
    float lv = 0.f;
    #pragma unroll
    for (int h = 0; h < 4; h++)
        lv += lmpart[(((size_t)(b * 4 + h) * 256) + win) * 16 + t];
    lv *= (1.f / 64.f);
    float val = gv + lv;
    m1[b * KN + y * KH + x] = val;
    m2[b * KN + x * KH + y] = val;
}

// ---------------------------------------------------------------------------
// launcher
// ---------------------------------------------------------------------------
extern "C" void kernel_launch(void* const* d_in, const int* in_sizes, int n_in,
                              void* d_out, int out_size)
{
    const float* x      = (const float*)d_in[0];
    const float* q1_w   = (const float*)d_in[1];
    const float* q1_b   = (const float*)d_in[2];
    const float* kv1_w  = (const float*)d_in[3];
    const float* kv1_b  = (const float*)d_in[4];
    const float* q2_w   = (const float*)d_in[5];
    const float* q2_b   = (const float*)d_in[6];
    const float* kv2_w  = (const float*)d_in[7];
    const float* kv2_b  = (const float*)d_in[8];
    const float* lepe_w = (const float*)d_in[9];
    const float* lepe_b = (const float*)d_in[10];
    const float* lcw    = (const float*)d_in[11];
    const float* lcb    = (const float*)d_in[12];
    const float* sr_w   = (const float*)d_in[13];
    const float* sr_b   = (const float*)d_in[14];
    const float* norm_w = (const float*)d_in[15];
    const float* norm_b = (const float*)d_in[16];
    const float* proj_w = (const float*)d_in[17];
    const float* proj_b = (const float*)d_in[18];
    (void)in_sizes; (void)n_in; (void)out_size;

    float* scratch = nullptr;
    cudaGetSymbolAddress((void**)&scratch, g_scratch);
    __half* hs = nullptr;
    cudaGetSymbolAddress((void**)&hs, g_scratch_h);

    float* lepe   = scratch + OFF_LEPE;
    float* q2buf  = scratch + OFF_Q2;
    float* kv2buf = scratch + OFF_KV2;
    float* xs     = scratch + OFF_XS;
    float* concat = scratch + OFF_CONCAT;
    float* gpart  = scratch + OFF_GPART;
    float* gred   = scratch + OFF_GRED;
    float* lmpart = scratch + OFF_LMPART;

    __half* xh     = hs + HOFF_XH;
    __half* xsh    = hs + HOFF_XSH;
    __half* q1h    = hs + HOFF_Q1H;
    __half* kv1h   = hs + HOFF_KV1H;
    __half* lepeh  = hs + HOFF_LEPEH;
    __half* wfused = hs + HOFF_WFUSE;
    __half* wkv1t  = hs + HOFF_WKV1;
    __half* wprojt = hs + HOFF_WPROJ;
    __half* wsrt   = hs + HOFF_WSR;

    float* out = (float*)d_out;
    float* m1  = out + (size_t)KB * KN * KC;
    float* m2  = m1 + (size_t)KB * KN;

    cudaFuncSetAttribute(hgemm_h,   cudaFuncAttributeMaxDynamicSharedMemorySize, HG_SMEM);
    cudaFuncSetAttribute(qkv_gemm,  cudaFuncAttributeMaxDynamicSharedMemorySize, HG_SMEM);
    cudaFuncSetAttribute(sr_gemm,   cudaFuncAttributeMaxDynamicSharedMemorySize, HG_SMEM);
    cudaFuncSetAttribute(proj_gemm, cudaFuncAttributeMaxDynamicSharedMemorySize, HG_SMEM);
    cudaFuncSetAttribute(attn1_kernel, cudaFuncAttributeMaxDynamicSharedMemorySize, ATTN1_SMEM);

    cvt_f16<<<4096, 256>>>(x, xh);
    prep_w<<<2304, 256>>>(q1_w, q2_w, kv2_w, lepe_w, kv1_w, proj_w, sr_w,
                          wfused, wkv1t, wprojt, wsrt);

    // fused projections: q1(f16), q2(f32), kv2(f32), lepe_lin(f16)
    qkv_gemm<<<dim3(6, 128), 256, HG_SMEM>>>(xh, wfused, q1_b, q2_b, kv2_b, lepe_b,
                                             q1h, q2buf, kv2buf, lepeh);
    lepe_conv<<<8192, 256>>>(lepeh, lcw, lcb, lepe);

    // spatial reduction -> LN -> GELU -> kv1
    sr_gemm<<<dim3(2, 32), 256, HG_SMEM>>>(xh, wsrt, sr_b, xs);
    ln_gelu<<<KB * KN1, 256>>>(xs, norm_w, norm_b, xsh);
    hgemm_h<<<dim3(2, 32), 256, HG_SMEM>>>(xsh, wkv1t, kv1_b, kv1h,
                                           KB * KN1, 256, 256);

    // attention branches
    attn1_kernel<<<dim3(128, 4, 4), 512, ATTN1_SMEM>>>(q1h, kv1h, concat, gpart);
    g_reduce<<<16, 256>>>(gpart, gred);
    attn2_kernel<<<1024, 128>>>(q2buf, kv2buf, concat, lmpart);
    mask_kernel<<<64, 256>>>(gred, lmpart, m1, m2);

    // output projection with fused (concat + lepe) and x2 epilogue
    proj_gemm<<<dim3(2, 128), 256, HG_SMEM>>>(concat, lepe, wprojt, proj_b, out);
}

// round 13
// speedup vs baseline: 2.9036x; 1.0070x over previous
#include <cuda_runtime.h>
#include <cuda_fp16.h>
#include <mma.h>
#include <math.h>
#include <stdint.h>

using namespace nvcuda;

#define KB   4
#define KN   4096
#define KC   256
#define KH   64
#define KN1  1024
#define KSCALE 0.17677669529663687f

// fp32 scratch
#define OFF_Q2       ((size_t)0)
#define OFF_KV2      (OFF_Q2     + (size_t)KB*KN*128)
#define OFF_XS       (OFF_KV2    + (size_t)KB*KN*256)
#define OFF_CONCAT   (OFF_XS     + (size_t)KB*KN1*256)
#define OFF_GPART    (OFF_CONCAT + (size_t)KB*KN*KC)
#define OFF_GRED2    (OFF_GPART  + (size_t)KB*4*128*1024)
#define OFF_LMPART   (OFF_GRED2  + (size_t)8*KB*1024)
#define SCRATCH_TOT  (OFF_LMPART + (size_t)KB*4*256*16)

__device__ float g_scratch[SCRATCH_TOT];

// f16 scratch
#define HOFF_XH    ((size_t)0)
#define HOFF_XSH   (HOFF_XH    + (size_t)4194304)
#define HOFF_Q1H   (HOFF_XSH   + (size_t)1048576)
#define HOFF_KV1H  (HOFF_Q1H   + (size_t)2097152)
#define HOFF_LEPEH (HOFF_KV1H  + (size_t)1048576)
#define HOFF_LEPEC (HOFF_LEPEH + (size_t)4194304)
#define HOFF_WFUSE (HOFF_LEPEC + (size_t)4194304)
#define HOFF_WKV1  (HOFF_WFUSE + (size_t)196608)
#define HOFF_WPROJ (HOFF_WKV1  + (size_t)65536)
#define HOFF_WSR   (HOFF_WPROJ + (size_t)65536)
#define HSCRATCH_TOT (HOFF_WSR + (size_t)262144)

__device__ __half g_scratch_h[HSCRATCH_TOT];

// ---------------------------------------------------------------------------
// common wmma tile config: 128x128 tile, 256 threads = 8 warps (2 x 4)
// ---------------------------------------------------------------------------
#define APITCH 72
#define CPITCH 132
#define HG_SMEM (128 * CPITCH * 4)

#define GEMM_CORE_DECL \
    extern __shared__ char smraw[]; \
    __half* As = (__half*)smraw; \
    __half* Bs = As + 128 * APITCH; \
    float*  Cst = (float*)smraw; \
    const int tid = threadIdx.x; \
    const int wid = tid >> 5; \
    const int warp_row = wid >> 2; \
    const int warp_col = wid & 3; \
    wmma::fragment<wmma::accumulator, 16, 16, 16, float> acc[4][2]; \
    _Pragma("unroll") \
    for (int mt = 0; mt < 4; mt++) \
        _Pragma("unroll") \
        for (int nt = 0; nt < 2; nt++) \
            wmma::fill_fragment(acc[mt][nt], 0.f);

#define GEMM_CORE_MMA \
    __syncthreads(); \
    _Pragma("unroll") \
    for (int ks = 0; ks < 4; ks++) { \
        wmma::fragment<wmma::matrix_a, 16, 16, 16, __half, wmma::row_major> af[4]; \
        wmma::fragment<wmma::matrix_b, 16, 16, 16, __half, wmma::col_major> bf[2]; \
        _Pragma("unroll") \
        for (int mt = 0; mt < 4; mt++) \
            wmma::load_matrix_sync(af[mt], As + (warp_row * 64 + mt * 16) * APITCH + ks * 16, APITCH); \
        _Pragma("unroll") \
        for (int nt = 0; nt < 2; nt++) \
            wmma::load_matrix_sync(bf[nt], Bs + (warp_col * 32 + nt * 16) * APITCH + ks * 16, APITCH); \
        _Pragma("unroll") \
        for (int mt = 0; mt < 4; mt++) \
            _Pragma("unroll") \
            for (int nt = 0; nt < 2; nt++) \
                wmma::mma_sync(acc[mt][nt], af[mt], bf[nt], acc[mt][nt]); \
    } \
    __syncthreads();

#define GEMM_STORE_STAGE \
    _Pragma("unroll") \
    for (int mt = 0; mt < 4; mt++) \
        _Pragma("unroll") \
        for (int nt = 0; nt < 2; nt++) \
            wmma::store_matrix_sync(Cst + (warp_row * 64 + mt * 16) * CPITCH + warp_col * 32 + nt * 16, \
                                    acc[mt][nt], CPITCH, wmma::mem_row_major); \
    __syncthreads();

// ---------------------------------------------------------------------------
// generic hgemm (kv1): C = A @ BT^T + bias, f16 out
// ---------------------------------------------------------------------------
__global__ __launch_bounds__(256)
void hgemm_h(const __half* __restrict__ A, const __half* __restrict__ BT,
             const float* __restrict__ bias, __half* __restrict__ Cout,
             int M, int N, int K)
{
    GEMM_CORE_DECL
    const int row0 = blockIdx.y * 128;
    const int col0 = blockIdx.x * 128;
    const int kn = K >> 6;
    for (int c = 0; c < kn; c++) {
        #pragma unroll
        for (int i = 0; i < 4; i++) {
            int li = i * 256 + tid;
            int r = li >> 3, q = (li & 7) * 8;
            *(uint4*)(As + r * APITCH + q) = *(const uint4*)(A + (size_t)(row0 + r) * K + c * 64 + q);
            *(uint4*)(Bs + r * APITCH + q) = *(const uint4*)(BT + (size_t)(col0 + r) * K + c * 64 + q);
        }
        GEMM_CORE_MMA
    }
    GEMM_STORE_STAGE
    #pragma unroll
    for (int i = 0; i < 16; i++) {
        int lin = i * 256 + tid;
        int r = lin >> 5, c4 = (lin & 31) * 4;
        const float* s = Cst + r * CPITCH + c4;
        __half2 h0 = __floats2half2_rn(s[0] + bias[col0 + c4 + 0], s[1] + bias[col0 + c4 + 1]);
        __half2 h1 = __floats2half2_rn(s[2] + bias[col0 + c4 + 2], s[3] + bias[col0 + c4 + 3]);
        uint2 pk; pk.x = *(uint32_t*)&h0; pk.y = *(uint32_t*)&h1;
        *(uint2*)(Cout + (size_t)(row0 + r) * N + col0 + c4) = pk;
    }
}

// ---------------------------------------------------------------------------
// fused projection GEMM: col tiles 0->q1h 1->q2 2,3->kv2 4,5->lepeh
// ---------------------------------------------------------------------------
__global__ __launch_bounds__(256)
void qkv_gemm(const __half* __restrict__ A, const __half* __restrict__ BT,
              const float* __restrict__ q1_b, const float* __restrict__ q2_b,
              const float* __restrict__ kv2_b, const float* __restrict__ lepe_b,
              __half* __restrict__ q1h, float* __restrict__ q2o,
              float* __restrict__ kv2o, __half* __restrict__ lepeh)
{
    GEMM_CORE_DECL
    const int row0 = blockIdx.y * 128;
    const int col0 = blockIdx.x * 128;
    for (int c = 0; c < 4; c++) {
        #pragma unroll
        for (int i = 0; i < 4; i++) {
            int li = i * 256 + tid;
            int r = li >> 3, q = (li & 7) * 8;
            *(uint4*)(As + r * APITCH + q) = *(const uint4*)(A + (size_t)(row0 + r) * 256 + c * 64 + q);
            *(uint4*)(Bs + r * APITCH + q) = *(const uint4*)(BT + (size_t)(col0 + r) * 256 + c * 64 + q);
        }
        GEMM_CORE_MMA
    }
    GEMM_STORE_STAGE

    const int t = blockIdx.x;
    __half* hdst = nullptr; float* fdst = nullptr;
    const float* bp; int pitch, cofs;
    switch (t) {
        case 0:  hdst = q1h;  bp = q1_b;  pitch = 128; cofs = 0;   break;
        case 1:  fdst = q2o;  bp = q2_b;  pitch = 128; cofs = 0;   break;
        case 2:  fdst = kv2o; bp = kv2_b; pitch = 256; cofs = 0;   break;
        case 3:  fdst = kv2o; bp = kv2_b; pitch = 256; cofs = 128; break;
        case 4:  hdst = lepeh; bp = lepe_b; pitch = 256; cofs = 0;   break;
        default: hdst = lepeh; bp = lepe_b; pitch = 256; cofs = 128; break;
    }
    #pragma unroll
    for (int i = 0; i < 16; i++) {
        int lin = i * 256 + tid;
        int r = lin >> 5, c4 = (lin & 31) * 4;
        const float* s = Cst + r * CPITCH + c4;
        float v0 = s[0] + bp[cofs + c4 + 0];
        float v1 = s[1] + bp[cofs + c4 + 1];
        float v2 = s[2] + bp[cofs + c4 + 2];
        float v3 = s[3] + bp[cofs + c4 + 3];
        size_t o = (size_t)(row0 + r) * pitch + cofs + c4;
        if (hdst) {
            __half2 h0 = __floats2half2_rn(v0, v1);
            __half2 h1 = __floats2half2_rn(v2, v3);
            uint2 pk; pk.x = *(uint32_t*)&h0; pk.y = *(uint32_t*)&h1;
            *(uint2*)(hdst + o) = pk;
        } else {
            *(float4*)(fdst + o) = make_float4(v0, v1, v2, v3);
        }
    }
}

// ---------------------------------------------------------------------------
// sr conv as GEMM with inline im2col gather from xh
// ---------------------------------------------------------------------------
__global__ __launch_bounds__(256)
void sr_gemm(const __half* __restrict__ xh, const __half* __restrict__ BT,
             const float* __restrict__ bias, float* __restrict__ C)
{
    GEMM_CORE_DECL
    const int row0 = blockIdx.y * 128;
    const int col0 = blockIdx.x * 128;
    for (int c = 0; c < 16; c++) {
        const int kk = c >> 2;
        const int ky = kk >> 1, kx = kk & 1;
        const int cib = (c & 3) * 64;
        #pragma unroll
        for (int i = 0; i < 4; i++) {
            int li = i * 256 + tid;
            int r = li >> 3, q = (li & 7) * 8;
            int m = row0 + r;
            int b = m >> 10, p = m & 1023;
            int oy = p >> 5, ox = p & 31;
            int n = (2 * oy + ky) * KH + 2 * ox + kx;
            *(uint4*)(As + r * APITCH + q) =
                *(const uint4*)(xh + ((size_t)b * KN + n) * 256 + cib + q);
            *(uint4*)(Bs + r * APITCH + q) =
                *(const uint4*)(BT + (size_t)(col0 + r) * 1024 + c * 64 + q);
        }
        GEMM_CORE_MMA
    }
    GEMM_STORE_STAGE
    #pragma unroll
    for (int i = 0; i < 16; i++) {
        int lin = i * 256 + tid;
        int r = lin >> 5, c4 = (lin & 31) * 4;
        const float* s = Cst + r * CPITCH + c4;
        float4 v = make_float4(s[0] + bias[col0 + c4 + 0], s[1] + bias[col0 + c4 + 1],
                               s[2] + bias[col0 + c4 + 2], s[3] + bias[col0 + c4 + 3]);
        *(float4*)(C + (size_t)(row0 + r) * 256 + col0 + c4) = v;
    }
}

// ---------------------------------------------------------------------------
// output GEMM: A = f16(concat_f32 + lepe_f16) on the fly, x2 epilogue, f32 out
// ---------------------------------------------------------------------------
__global__ __launch_bounds__(256)
void proj_gemm(const float* __restrict__ Acat, const __half* __restrict__ Alepe,
               const __half* __restrict__ BT, const float* __restrict__ bias,
               float* __restrict__ C)
{
    GEMM_CORE_DECL
    const int row0 = blockIdx.y * 128;
    const int col0 = blockIdx.x * 128;
    for (int c = 0; c < 4; c++) {
        #pragma unroll
        for (int i = 0; i < 4; i++) {
            int li = i * 256 + tid;
            int r = li >> 3, qf = (li & 7) * 8;
            size_t ai = (size_t)(row0 + r) * 256 + c * 64 + qf;
            float4 a0 = *(const float4*)(Acat + ai);
            float4 a1 = *(const float4*)(Acat + ai + 4);
            uint4 lh = *(const uint4*)(Alepe + ai);
            __half2* lp = (__half2*)&lh;
            float2 l0 = __half22float2(lp[0]);
            float2 l1 = __half22float2(lp[1]);
            float2 l2 = __half22float2(lp[2]);
            float2 l3 = __half22float2(lp[3]);
            __half2 h0 = __floats2half2_rn(a0.x + l0.x, a0.y + l0.y);
            __half2 h1 = __floats2half2_rn(a0.z + l1.x, a0.w + l1.y);
            __half2 h2 = __floats2half2_rn(a1.x + l2.x, a1.y + l2.y);
            __half2 h3 = __floats2half2_rn(a1.z + l3.x, a1.w + l3.y);
            uint4 pk;
            pk.x = *(uint32_t*)&h0; pk.y = *(uint32_t*)&h1;
            pk.z = *(uint32_t*)&h2; pk.w = *(uint32_t*)&h3;
            *(uint4*)(As + r * APITCH + qf) = pk;
            *(uint4*)(Bs + r * APITCH + qf) =
                *(const uint4*)(BT + (size_t)(col0 + r) * 256 + c * 64 + qf);
        }
        GEMM_CORE_MMA
    }
    GEMM_STORE_STAGE
    #pragma unroll
    for (int i = 0; i < 16; i++) {
        int lin = i * 256 + tid;
        int r = lin >> 5, c4 = (lin & 31) * 4;
        const float* s = Cst + r * CPITCH + c4;
        float4 v = make_float4(2.f * (s[0] + bias[col0 + c4 + 0]),
                               2.f * (s[1] + bias[col0 + c4 + 1]),
                               2.f * (s[2] + bias[col0 + c4 + 2]),
                               2.f * (s[3] + bias[col0 + c4 + 3]));
        *(float4*)(C + (size_t)(row0 + r) * 256 + col0 + c4) = v;
    }
}

// ---------------------------------------------------------------------------
// prep
// ---------------------------------------------------------------------------
__global__ void cvt_f16(const float* __restrict__ in, __half* __restrict__ out) {
    int idx = blockIdx.x * 256 + threadIdx.x;
    float4 v = *(const float4*)(in + (size_t)idx * 4);
    __half2 h0 = __floats2half2_rn(v.x, v.y);
    __half2 h1 = __floats2half2_rn(v.z, v.w);
    uint2 pk; pk.x = *(uint32_t*)&h0; pk.y = *(uint32_t*)&h1;
    *(uint2*)(out + (size_t)idx * 4) = pk;
}

__global__ void prep_w(const float* __restrict__ q1w, const float* __restrict__ q2w,
                       const float* __restrict__ kv2w, const float* __restrict__ lepew,
                       const float* __restrict__ kv1w, const float* __restrict__ projw,
                       const float* __restrict__ srw,
                       __half* __restrict__ wfused, __half* __restrict__ wkv1t,
                       __half* __restrict__ wprojt, __half* __restrict__ wsrt)
{
    int idx = blockIdx.x * 256 + threadIdx.x;
    if (idx < 196608) {
        int r = idx >> 8, k = idx & 255;
        float v;
        if (r < 128)      v = q1w[(size_t)k * 128 + r];
        else if (r < 256) v = q2w[(size_t)k * 128 + (r - 128)];
        else if (r < 512) v = kv2w[(size_t)k * 256 + (r - 256)];
        else              v = lepew[(size_t)k * 256 + (r - 512)];
        wfused[idx] = __float2half(v);
    } else if (idx < 262144) {
        int i = idx - 196608;
        int n = i >> 8, k = i & 255;
        wkv1t[i] = __float2half(kv1w[(size_t)k * 256 + n]);
    } else if (idx < 327680) {
        int i = idx - 262144;
        int n = i >> 8, k = i & 255;
        wprojt[i] = __float2half(projw[(size_t)k * 256 + n]);
    } else {
        int i = idx - 327680;
        int co = i >> 10, k = i & 1023;
        int kk = k >> 8, ci = k & 255;
        wsrt[i] = __float2half(srw[(size_t)co * 1024 + ci * 4 + kk]);
    }
}

// ---------------------------------------------------------------------------
// tiled depthwise 3x3 conv, pad 1. 16x16 spatial tile x 64-ch group in smem.
// channel-major smem layout (conflict-free). f16 in, f16 out.
// grid (16 tiles, 4 cgroups, 4 batch), 256 threads.
// ---------------------------------------------------------------------------
__global__ __launch_bounds__(256)
void lepe_conv(const __half* __restrict__ in, const float* __restrict__ w,
               const float* __restrict__ bias, __half* __restrict__ out)
{
    __shared__ __half2 sT[32 * 324];   // [c2][18*18]
    __shared__ float ws[576];
    __shared__ float bs[64];
    const int tile = blockIdx.x;
    const int ty = tile >> 2, tx = tile & 3;
    const int cg = blockIdx.y, b = blockIdx.z;
    const int tid = threadIdx.x;

    for (int i = tid; i < 576; i += 256) ws[i] = w[(cg * 64 + i / 9) * 9 + i % 9];
    if (tid < 64) bs[tid] = bias[cg * 64 + tid];

    for (int idx = tid; idx < 10368; idx += 256) {
        int c2 = idx / 324, p = idx - c2 * 324;
        int py = p / 18, px = p - py * 18;
        int gy = ty * 16 - 1 + py, gx = tx * 16 - 1 + px;
        __half2 v = __float2half2_rn(0.f);
        if (gy >= 0 && gy < KH && gx >= 0 && gx < KH)
            v = *(const __half2*)(in + ((size_t)b * KN + gy * KH + gx) * 256 + cg * 64 + c2 * 2);
        sT[c2 * 324 + p] = v;
    }
    __syncthreads();

    const int py = tid >> 4, px = tid & 15;
    const size_t obase = ((size_t)b * KN + (ty * 16 + py) * KH + tx * 16 + px) * 256 + cg * 64;
    #pragma unroll 4
    for (int c2 = 0; c2 < 32; c2++) {
        float a0 = bs[c2 * 2], a1 = bs[c2 * 2 + 1];
        const float* w0 = ws + c2 * 18;
        const float* w1 = w0 + 9;
        const __half2* tp = sT + c2 * 324 + py * 18 + px;
        #pragma unroll
        for (int dy = 0; dy < 3; dy++)
            #pragma unroll
            for (int dx = 0; dx < 3; dx++) {
                float2 f = __half22float2(tp[dy * 18 + dx]);
                a0 += f.x * w0[dy * 3 + dx];
                a1 += f.y * w1[dy * 3 + dx];
            }
        *(__half2*)(out + obase + c2 * 2) = __floats2half2_rn(a0, a1);
    }
}

// ---------------------------------------------------------------------------
// LayerNorm + GELU -> f16
// ---------------------------------------------------------------------------
__global__ void ln_gelu(const float* __restrict__ xs, const float* __restrict__ nw,
                        const float* __restrict__ nb, __half* __restrict__ o16)
{
    int row = blockIdx.x;
    int tid = threadIdx.x;
    float v = xs[(size_t)row * 256 + tid];
    __shared__ float red[16];
    float s = v, sq = v * v;
    #pragma unroll
    for (int o = 16; o; o >>= 1) {
        s  += __shfl_xor_sync(0xffffffffu, s, o);
        sq += __shfl_xor_sync(0xffffffffu, sq, o);
    }
    int w = tid >> 5, lane = tid & 31;
    if (lane == 0) { red[w] = s; red[8 + w] = sq; }
    __syncthreads();
    if (tid == 0) {
        float S = 0.f, SQ = 0.f;
        for (int i = 0; i < 8; i++) { S += red[i]; SQ += red[8 + i]; }
        red[0] = S; red[8] = SQ;
    }
    __syncthreads();
    float mean = red[0] * (1.f / 256.f);
    float var  = red[8] * (1.f / 256.f) - mean * mean;
    float t = (v - mean) * rsqrtf(var + 1e-5f) * nw[tid] + nb[tid];
    float g = 0.5f * t * (1.f + erff(t * 0.70710678118654752f));
    o16[(size_t)row * 256 + tid] = __float2half(g);
}

// ---------------------------------------------------------------------------
// Branch-1 attention, 512 threads = 16 warps
// ---------------------------------------------------------------------------
#define SPITCH 1040
#define PPITCH 1032
#define ATTN1_SMEM (32 * SPITCH * 4 + 32 * PPITCH * 2 + 128)

__global__ __launch_bounds__(512)
void attn1_kernel(const __half* __restrict__ q1h, const __half* __restrict__ kv1h,
                  float* __restrict__ concat, float* __restrict__ gpart)
{
    extern __shared__ char smraw[];
    float* S = (float*)smraw;
    __half* P = (__half*)(smraw + 32 * SPITCH * 4);
    float* rs = (float*)(smraw + 32 * SPITCH * 4 + 32 * PPITCH * 2);
    const int tid = threadIdx.x;
    const int w = tid >> 5, lane = tid & 31;
    const int qt = blockIdx.x, h = blockIdx.y, b = blockIdx.z;

    {
        wmma::fragment<wmma::matrix_a, 16, 16, 16, __half, wmma::row_major> af[2][2];
        #pragma unroll
        for (int mt = 0; mt < 2; mt++)
            #pragma unroll
            for (int ks = 0; ks < 2; ks++)
                wmma::load_matrix_sync(af[mt][ks],
                    q1h + ((size_t)b * KN + qt * 32 + mt * 16) * 128 + h * 32 + ks * 16, 128);
        #pragma unroll
        for (int nt = 0; nt < 4; nt++) {
            int col = w * 64 + nt * 16;
            wmma::fragment<wmma::accumulator, 16, 16, 16, float> a0, a1;
            wmma::fill_fragment(a0, 0.f);
            wmma::fill_fragment(a1, 0.f);
            #pragma unroll
            for (int ks = 0; ks < 2; ks++) {
                wmma::fragment<wmma::matrix_b, 16, 16, 16, __half, wmma::col_major> bf;
                wmma::load_matrix_sync(bf,
                    kv1h + ((size_t)b * KN1 + col) * 256 + h * 32 + ks * 16, 256);
                wmma::mma_sync(a0, af[0][ks], bf, a0);
                wmma::mma_sync(a1, af[1][ks], bf, a1);
            }
            #pragma unroll
            for (int e = 0; e < a0.num_elements; e++) { a0.x[e] *= KSCALE; a1.x[e] *= KSCALE; }
            wmma::store_matrix_sync(S + 0 * SPITCH + col, a0, SPITCH, wmma::mem_row_major);
            wmma::store_matrix_sync(S + 16 * SPITCH + col, a1, SPITCH, wmma::mem_row_major);
        }
    }
    __syncthreads();

    #pragma unroll
    for (int ri = 0; ri < 2; ri++) {
        int r = w * 2 + ri;
        float ssum = 0.f;
        #pragma unroll 8
        for (int m = lane; m < 1024; m += 32) {
            float e = __expf(S[r * SPITCH + m]);
            S[r * SPITCH + m] = e;
            ssum += e;
        }
        #pragma unroll
        for (int o = 16; o; o >>= 1) ssum += __shfl_xor_sync(0xffffffffu, ssum, o);
        if (lane == 0) rs[r] = ssum;
    }
    __syncthreads();
    if (tid < 32) rs[tid] = 1.f / rs[tid];
    __syncthreads();

    #pragma unroll
    for (int mi = 0; mi < 2; mi++) {
        int m = tid + mi * 512;
        float cs = 0.f;
        #pragma unroll
        for (int r = 0; r < 32; r++) {
            float v = S[r * SPITCH + m] * rs[r];
            cs += v;
            P[r * PPITCH + m] = __float2half(v);
        }
        gpart[(((size_t)(b * 4 + h) * 128) + qt) * 1024 + m] = cs;
    }
    __syncthreads();

    {
        wmma::fragment<wmma::accumulator, 16, 16, 16, float> acc2[2][2];
        #pragma unroll
        for (int mt = 0; mt < 2; mt++)
            #pragma unroll
            for (int nt = 0; nt < 2; nt++)
                wmma::fill_fragment(acc2[mt][nt], 0.f);
        #pragma unroll
        for (int ks = 0; ks < 4; ks++) {
            int kk = w * 64 + ks * 16;
            wmma::fragment<wmma::matrix_a, 16, 16, 16, __half, wmma::row_major> ap[2];
            wmma::fragment<wmma::matrix_b, 16, 16, 16, __half, wmma::row_major> bp[2];
            #pragma unroll
            for (int mt = 0; mt < 2; mt++)
                wmma::load_matrix_sync(ap[mt], P + (mt * 16) * PPITCH + kk, PPITCH);
            #pragma unroll
            for (int nt = 0; nt < 2; nt++)
                wmma::load_matrix_sync(bp[nt],
                    kv1h + ((size_t)b * KN1 + kk) * 256 + 128 + h * 32 + nt * 16, 256);
            #pragma unroll
            for (int mt = 0; mt < 2; mt++)
                #pragma unroll
                for (int nt = 0; nt < 2; nt++)
                    wmma::mma_sync(acc2[mt][nt], ap[mt], bp[nt], acc2[mt][nt]);
        }
        float* Sp = S + w * 1024;
        #pragma unroll
        for (int mt = 0; mt < 2; mt++)
            #pragma unroll
            for (int nt = 0; nt < 2; nt++)
                wmma::store_matrix_sync(Sp + mt * 16 * 32 + nt * 16, acc2[mt][nt],
                                        32, wmma::mem_row_major);
    }
    __syncthreads();

    #pragma unroll
    for (int ii = 0; ii < 2; ii++) {
        int idx = tid + ii * 512;
        int q = idx >> 5, dd = idx & 31;
        float sum = 0.f;
        #pragma unroll
        for (int j = 0; j < 16; j++) sum += S[j * 1024 + idx];
        concat[((size_t)b * KN + qt * 32 + q) * 256 + h * 32 + dd] = sum;
    }
}

// ---------------------------------------------------------------------------
// Branch-2 windowed attention (fp32)
// ---------------------------------------------------------------------------
__global__ void attn2_kernel(const float* __restrict__ q2, const float* __restrict__ kv2,
                             float* __restrict__ concat, float* __restrict__ lmpart)
{
    __shared__ float sQ[4][512];
    __shared__ float sKT[4][512];
    __shared__ float sV[4][512];
    __shared__ float sS[4][16 * 17];
    const int w = threadIdx.x >> 5, lane = threadIdx.x & 31;
    const int gw = blockIdx.x * 4 + w;
    const int b = gw >> 10;
    const int rem = gw & 1023;
    const int h = rem >> 8;
    const int win = rem & 255;
    const int wy = win >> 4, wx = win & 15;

    for (int t = 0; t < 16; t++) {
        int n = (wy * 4 + (t >> 2)) * KH + wx * 4 + (t & 3);
        sQ[w][t * 32 + lane]  = q2[((size_t)b * KN + n) * 128 + h * 32 + lane];
        sKT[w][lane * 16 + t] = kv2[((size_t)b * KN + n) * 256 + h * 32 + lane];
        sV[w][t * 32 + lane]  = kv2[((size_t)b * KN + n) * 256 + 128 + h * 32 + lane];
    }
    __syncwarp();

    #pragma unroll
    for (int r = 0; r < 8; r++) {
        int e = r * 32 + lane;
        int i = e >> 4, j = e & 15;
        float acc = 0.f;
        #pragma unroll
        for (int k = 0; k < 32; k++) acc += sQ[w][i * 32 + k] * sKT[w][k * 16 + j];
        sS[w][i * 17 + j] = acc * KSCALE;
    }
    __syncwarp();

    if (lane < 16) {
        float mx = -1e30f;
        #pragma unroll
        for (int j = 0; j < 16; j++) mx = fmaxf(mx, sS[w][lane * 17 + j]);
        float s = 0.f;
        #pragma unroll
        for (int j = 0; j < 16; j++) {
            float e = __expf(sS[w][lane * 17 + j] - mx);
            sS[w][lane * 17 + j] = e;
            s += e;
        }
        float inv = 1.f / s;
        #pragma unroll
        for (int j = 0; j < 16; j++) sS[w][lane * 17 + j] *= inv;
    }
    __syncwarp();

    if (lane < 16) {
        float cs = 0.f;
        #pragma unroll
        for (int i = 0; i < 16; i++) cs += sS[w][i * 17 + lane];
        lmpart[(((size_t)(b * 4 + h) * 256) + win) * 16 + lane] = cs;
    }

    for (int i = 0; i < 16; i++) {
        float acc = 0.f;
        #pragma unroll
        for (int j = 0; j < 16; j++) acc += sS[w][i * 17 + j] * sV[w][j * 32 + lane];
        int n = (wy * 4 + (i >> 2)) * KH + wx * 4 + (i & 3);
        concat[((size_t)b * KN + n) * 256 + 128 + h * 32 + lane] = acc;
    }
}

// ---------------------------------------------------------------------------
// stage-1 g reduce: 8 partials per (b,m), 32768 threads
// ---------------------------------------------------------------------------
__global__ void g_reduce(const float* __restrict__ gpart, float* __restrict__ gred2)
{
    int idx = blockIdx.x * 256 + threadIdx.x;   // 32768
    int g = idx >> 12;
    int r = idx & 4095;
    int b = r >> 10, m = r & 1023;
    float s = 0.f;
    #pragma unroll 8
    for (int j = 0; j < 64; j++)
        s += gpart[((size_t)b * 512 + g * 64 + j) * 1024 + m];
    gred2[(size_t)g * 4096 + r] = s;
}

__global__ void mask_kernel(const float* __restrict__ gred2, const float* __restrict__ lmpart,
                            float* __restrict__ m1, float* __restrict__ m2)
{
    int idx = blockIdx.x * 256 + threadIdx.x;
    int b = idx >> 12, n = idx & 4095;
    int y = n >> 6, x = n & 63;
    int ri = b * 1024 + (y >> 1) * 32 + (x >> 1);
    float gv = 0.f;
    #pragma unroll
    for (int g = 0; g < 8; g++) gv += gred2[g * 4096 + ri];
    gv *= (1.f / 16384.f);
    int win = (y >> 2) * 16 + (x >> 2);
    int t = (y & 3) * 4 + (x & 3);
    float lv = 0.f;
    #pragma unroll
    for (int h = 0; h < 4; h++)
        lv += lmpart[(((size_t)(b * 4 + h) * 256) + win) * 16 + t];
    lv *= (1.f / 64.f);
    float val = gv + lv;
    m1[b * KN + y * KH + x] = val;
    m2[b * KN + x * KH + y] = val;
}

// ---------------------------------------------------------------------------
// launcher
// ---------------------------------------------------------------------------
extern "C" void kernel_launch(void* const* d_in, const int* in_sizes, int n_in,
                              void* d_out, int out_size)
{
    const float* x      = (const float*)d_in[0];
    const float* q1_w   = (const float*)d_in[1];
    const float* q1_b   = (const float*)d_in[2];
    const float* kv1_w  = (const float*)d_in[3];
    const float* kv1_b  = (const float*)d_in[4];
    const float* q2_w   = (const float*)d_in[5];
    const float* q2_b   = (const float*)d_in[6];
    const float* kv2_w  = (const float*)d_in[7];
    const float* kv2_b  = (const float*)d_in[8];
    const float* lepe_w = (const float*)d_in[9];
    const float* lepe_b = (const float*)d_in[10];
    const float* lcw    = (const float*)d_in[11];
    const float* lcb    = (const float*)d_in[12];
    const float* sr_w   = (const float*)d_in[13];
    const float* sr_b   = (const float*)d_in[14];
    const float* norm_w = (const float*)d_in[15];
    const float* norm_b = (const float*)d_in[16];
    const float* proj_w = (const float*)d_in[17];
    const float* proj_b = (const float*)d_in[18];
    (void)in_sizes; (void)n_in; (void)out_size;

    float* scratch = nullptr;
    cudaGetSymbolAddress((void**)&scratch, g_scratch);
    __half* hs = nullptr;
    cudaGetSymbolAddress((void**)&hs, g_scratch_h);

    float* q2buf  = scratch + OFF_Q2;
    float* kv2buf = scratch + OFF_KV2;
    float* xs     = scratch + OFF_XS;
    float* concat = scratch + OFF_CONCAT;
    float* gpart  = scratch + OFF_GPART;
    float* gred2  = scratch + OFF_GRED2;
    float* lmpart = scratch + OFF_LMPART;

    __half* xh     = hs + HOFF_XH;
    __half* xsh    = hs + HOFF_XSH;
    __half* q1h    = hs + HOFF_Q1H;
    __half* kv1h   = hs + HOFF_KV1H;
    __half* lepeh  = hs + HOFF_LEPEH;
    __half* lepec  = hs + HOFF_LEPEC;
    __half* wfused = hs + HOFF_WFUSE;
    __half* wkv1t  = hs + HOFF_WKV1;
    __half* wprojt = hs + HOFF_WPROJ;
    __half* wsrt   = hs + HOFF_WSR;

    float* out = (float*)d_out;
    float* m1  = out + (size_t)KB * KN * KC;
    float* m2  = m1 + (size_t)KB * KN;

    cudaFuncSetAttribute(hgemm_h,   cudaFuncAttributeMaxDynamicSharedMemorySize, HG_SMEM);
    cudaFuncSetAttribute(qkv_gemm,  cudaFuncAttributeMaxDynamicSharedMemorySize, HG_SMEM);
    cudaFuncSetAttribute(sr_gemm,   cudaFuncAttributeMaxDynamicSharedMemorySize, HG_SMEM);
    cudaFuncSetAttribute(proj_gemm, cudaFuncAttributeMaxDynamicSharedMemorySize, HG_SMEM);
    cudaFuncSetAttribute(attn1_kernel, cudaFuncAttributeMaxDynamicSharedMemorySize, ATTN1_SMEM);

    cvt_f16<<<4096, 256>>>(x, xh);
    prep_w<<<2304, 256>>>(q1_w, q2_w, kv2_w, lepe_w, kv1_w, proj_w, sr_w,
                          wfused, wkv1t, wprojt, wsrt);

    // fused projections: q1(f16), q2(f32), kv2(f32), lepe_lin(f16)
    qkv_gemm<<<dim3(6, 128), 256, HG_SMEM>>>(xh, wfused, q1_b, q2_b, kv2_b, lepe_b,
                                             q1h, q2buf, kv2buf, lepeh);
    lepe_conv<<<dim3(16, 4, 4), 256>>>(lepeh, lcw, lcb, lepec);

    // spatial reduction -> LN -> GELU -> kv1
    sr_gemm<<<dim3(2, 32), 256, HG_SMEM>>>(xh, wsrt, sr_b, xs);
    ln_gelu<<<KB * KN1, 256>>>(xs, norm_w, norm_b, xsh);
    hgemm_h<<<dim3(2, 32), 256, HG_SMEM>>>(xsh, wkv1t, kv1_b, kv1h,
                                           KB * KN1, 256, 256);

    // attention branches
    attn1_kernel<<<dim3(128, 4, 4), 512, ATTN1_SMEM>>>(q1h, kv1h, concat, gpart);
    g_reduce<<<128, 256>>>(gpart, gred2);
    attn2_kernel<<<1024, 128>>>(q2buf, kv2buf, concat, lmpart);
    mask_kernel<<<64, 256>>>(gred2, lmpart, m1, m2);

    // output projection with fused (concat + lepe_f16) and x2 epilogue
    proj_gemm<<<dim3(2, 128), 256, HG_SMEM>>>(concat, lepec, wprojt, proj_b, out);
}

// round 14
// speedup vs baseline: 3.1400x; 1.0814x over previous
#include <cuda_runtime.h>
#include <cuda_fp16.h>
#include <mma.h>
#include <math.h>
#include <stdint.h>

using namespace nvcuda;

#define KB   4
#define KN   4096
#define KC   256
#define KH   64
#define KN1  1024
#define KSCALE 0.17677669529663687f

// fp32 scratch
#define OFF_Q2       ((size_t)0)
#define OFF_KV2      (OFF_Q2     + (size_t)KB*KN*128)
#define OFF_XS       (OFF_KV2    + (size_t)KB*KN*256)
#define OFF_CONCAT   (OFF_XS     + (size_t)KB*KN1*256)
#define OFF_GPART    (OFF_CONCAT + (size_t)KB*KN*KC)
#define OFF_GRED2    (OFF_GPART  + (size_t)KB*4*128*1024)
#define OFF_LMPART   (OFF_GRED2  + (size_t)8*KB*1024)
#define SCRATCH_TOT  (OFF_LMPART + (size_t)KB*4*256*16)

__device__ float g_scratch[SCRATCH_TOT];

// f16 scratch
#define HOFF_XH    ((size_t)0)
#define HOFF_XSH   (HOFF_XH    + (size_t)4194304)
#define HOFF_Q1H   (HOFF_XSH   + (size_t)1048576)
#define HOFF_KV1H  (HOFF_Q1H   + (size_t)2097152)
#define HOFF_LEPEH (HOFF_KV1H  + (size_t)1048576)
#define HOFF_LEPEC (HOFF_LEPEH + (size_t)4194304)
#define HOFF_WFUSE (HOFF_LEPEC + (size_t)4194304)
#define HOFF_WKV1  (HOFF_WFUSE + (size_t)196608)
#define HOFF_WPROJ (HOFF_WKV1  + (size_t)65536)
#define HOFF_WSR   (HOFF_WPROJ + (size_t)65536)
#define HSCRATCH_TOT (HOFF_WSR + (size_t)262144)

__device__ __half g_scratch_h[HSCRATCH_TOT];

// ---------------------------------------------------------------------------
// common wmma tile config: 128x128 tile, 256 threads = 8 warps (2 x 4)
// ---------------------------------------------------------------------------
#define APITCH 72
#define CPITCH 132
#define HG_SMEM (128 * CPITCH * 4)

#define GEMM_CORE_DECL \
    extern __shared__ char smraw[]; \
    __half* As = (__half*)smraw; \
    __half* Bs = As + 128 * APITCH; \
    float*  Cst = (float*)smraw; \
    const int tid = threadIdx.x; \
    const int wid = tid >> 5; \
    const int warp_row = wid >> 2; \
    const int warp_col = wid & 3; \
    wmma::fragment<wmma::accumulator, 16, 16, 16, float> acc[4][2]; \
    _Pragma("unroll") \
    for (int mt = 0; mt < 4; mt++) \
        _Pragma("unroll") \
        for (int nt = 0; nt < 2; nt++) \
            wmma::fill_fragment(acc[mt][nt], 0.f);

#define GEMM_CORE_MMA \
    __syncthreads(); \
    _Pragma("unroll") \
    for (int ks = 0; ks < 4; ks++) { \
        wmma::fragment<wmma::matrix_a, 16, 16, 16, __half, wmma::row_major> af[4]; \
        wmma::fragment<wmma::matrix_b, 16, 16, 16, __half, wmma::col_major> bf[2]; \
        _Pragma("unroll") \
        for (int mt = 0; mt < 4; mt++) \
            wmma::load_matrix_sync(af[mt], As + (warp_row * 64 + mt * 16) * APITCH + ks * 16, APITCH); \
        _Pragma("unroll") \
        for (int nt = 0; nt < 2; nt++) \
            wmma::load_matrix_sync(bf[nt], Bs + (warp_col * 32 + nt * 16) * APITCH + ks * 16, APITCH); \
        _Pragma("unroll") \
        for (int mt = 0; mt < 4; mt++) \
            _Pragma("unroll") \
            for (int nt = 0; nt < 2; nt++) \
                wmma::mma_sync(acc[mt][nt], af[mt], bf[nt], acc[mt][nt]); \
    } \
    __syncthreads();

#define GEMM_STORE_STAGE \
    _Pragma("unroll") \
    for (int mt = 0; mt < 4; mt++) \
        _Pragma("unroll") \
        for (int nt = 0; nt < 2; nt++) \
            wmma::store_matrix_sync(Cst + (warp_row * 64 + mt * 16) * CPITCH + warp_col * 32 + nt * 16, \
                                    acc[mt][nt], CPITCH, wmma::mem_row_major); \
    __syncthreads();

// ---------------------------------------------------------------------------
// generic hgemm (kv1): C = A @ BT^T + bias, f16 out
// ---------------------------------------------------------------------------
__global__ __launch_bounds__(256)
void hgemm_h(const __half* __restrict__ A, const __half* __restrict__ BT,
             const float* __restrict__ bias, __half* __restrict__ Cout,
             int M, int N, int K)
{
    GEMM_CORE_DECL
    const int row0 = blockIdx.y * 128;
    const int col0 = blockIdx.x * 128;
    const int kn = K >> 6;
    for (int c = 0; c < kn; c++) {
        #pragma unroll
        for (int i = 0; i < 4; i++) {
            int li = i * 256 + tid;
            int r = li >> 3, q = (li & 7) * 8;
            *(uint4*)(As + r * APITCH + q) = *(const uint4*)(A + (size_t)(row0 + r) * K + c * 64 + q);
            *(uint4*)(Bs + r * APITCH + q) = *(const uint4*)(BT + (size_t)(col0 + r) * K + c * 64 + q);
        }
        GEMM_CORE_MMA
    }
    GEMM_STORE_STAGE
    #pragma unroll
    for (int i = 0; i < 16; i++) {
        int lin = i * 256 + tid;
        int r = lin >> 5, c4 = (lin & 31) * 4;
        const float* s = Cst + r * CPITCH + c4;
        __half2 h0 = __floats2half2_rn(s[0] + bias[col0 + c4 + 0], s[1] + bias[col0 + c4 + 1]);
        __half2 h1 = __floats2half2_rn(s[2] + bias[col0 + c4 + 2], s[3] + bias[col0 + c4 + 3]);
        uint2 pk; pk.x = *(uint32_t*)&h0; pk.y = *(uint32_t*)&h1;
        *(uint2*)(Cout + (size_t)(row0 + r) * N + col0 + c4) = pk;
    }
}

// ---------------------------------------------------------------------------
// fused projection GEMM: col tiles 0->q1h 1->q2 2,3->kv2 4,5->lepeh
// ---------------------------------------------------------------------------
__global__ __launch_bounds__(256)
void qkv_gemm(const __half* __restrict__ A, const __half* __restrict__ BT,
              const float* __restrict__ q1_b, const float* __restrict__ q2_b,
              const float* __restrict__ kv2_b, const float* __restrict__ lepe_b,
              __half* __restrict__ q1h, float* __restrict__ q2o,
              float* __restrict__ kv2o, __half* __restrict__ lepeh)
{
    GEMM_CORE_DECL
    const int row0 = blockIdx.y * 128;
    const int col0 = blockIdx.x * 128;
    for (int c = 0; c < 4; c++) {
        #pragma unroll
        for (int i = 0; i < 4; i++) {
            int li = i * 256 + tid;
            int r = li >> 3, q = (li & 7) * 8;
            *(uint4*)(As + r * APITCH + q) = *(const uint4*)(A + (size_t)(row0 + r) * 256 + c * 64 + q);
            *(uint4*)(Bs + r * APITCH + q) = *(const uint4*)(BT + (size_t)(col0 + r) * 256 + c * 64 + q);
        }
        GEMM_CORE_MMA
    }
    GEMM_STORE_STAGE

    const int t = blockIdx.x;
    __half* hdst = nullptr; float* fdst = nullptr;
    const float* bp; int pitch, cofs;
    switch (t) {
        case 0:  hdst = q1h;  bp = q1_b;  pitch = 128; cofs = 0;   break;
        case 1:  fdst = q2o;  bp = q2_b;  pitch = 128; cofs = 0;   break;
        case 2:  fdst = kv2o; bp = kv2_b; pitch = 256; cofs = 0;   break;
        case 3:  fdst = kv2o; bp = kv2_b; pitch = 256; cofs = 128; break;
        case 4:  hdst = lepeh; bp = lepe_b; pitch = 256; cofs = 0;   break;
        default: hdst = lepeh; bp = lepe_b; pitch = 256; cofs = 128; break;
    }
    #pragma unroll
    for (int i = 0; i < 16; i++) {
        int lin = i * 256 + tid;
        int r = lin >> 5, c4 = (lin & 31) * 4;
        const float* s = Cst + r * CPITCH + c4;
        float v0 = s[0] + bp[cofs + c4 + 0];
        float v1 = s[1] + bp[cofs + c4 + 1];
        float v2 = s[2] + bp[cofs + c4 + 2];
        float v3 = s[3] + bp[cofs + c4 + 3];
        size_t o = (size_t)(row0 + r) * pitch + cofs + c4;
        if (hdst) {
            __half2 h0 = __floats2half2_rn(v0, v1);
            __half2 h1 = __floats2half2_rn(v2, v3);
            uint2 pk; pk.x = *(uint32_t*)&h0; pk.y = *(uint32_t*)&h1;
            *(uint2*)(hdst + o) = pk;
        } else {
            *(float4*)(fdst + o) = make_float4(v0, v1, v2, v3);
        }
    }
}

// ---------------------------------------------------------------------------
// sr conv as GEMM with inline im2col gather from xh
// ---------------------------------------------------------------------------
__global__ __launch_bounds__(256)
void sr_gemm(const __half* __restrict__ xh, const __half* __restrict__ BT,
             const float* __restrict__ bias, float* __restrict__ C)
{
    GEMM_CORE_DECL
    const int row0 = blockIdx.y * 128;
    const int col0 = blockIdx.x * 128;
    for (int c = 0; c < 16; c++) {
        const int kk = c >> 2;
        const int ky = kk >> 1, kx = kk & 1;
        const int cib = (c & 3) * 64;
        #pragma unroll
        for (int i = 0; i < 4; i++) {
            int li = i * 256 + tid;
            int r = li >> 3, q = (li & 7) * 8;
            int m = row0 + r;
            int b = m >> 10, p = m & 1023;
            int oy = p >> 5, ox = p & 31;
            int n = (2 * oy + ky) * KH + 2 * ox + kx;
            *(uint4*)(As + r * APITCH + q) =
                *(const uint4*)(xh + ((size_t)b * KN + n) * 256 + cib + q);
            *(uint4*)(Bs + r * APITCH + q) =
                *(const uint4*)(BT + (size_t)(col0 + r) * 1024 + c * 64 + q);
        }
        GEMM_CORE_MMA
    }
    GEMM_STORE_STAGE
    #pragma unroll
    for (int i = 0; i < 16; i++) {
        int lin = i * 256 + tid;
        int r = lin >> 5, c4 = (lin & 31) * 4;
        const float* s = Cst + r * CPITCH + c4;
        float4 v = make_float4(s[0] + bias[col0 + c4 + 0], s[1] + bias[col0 + c4 + 1],
                               s[2] + bias[col0 + c4 + 2], s[3] + bias[col0 + c4 + 3]);
        *(float4*)(C + (size_t)(row0 + r) * 256 + col0 + c4) = v;
    }
}

// ---------------------------------------------------------------------------
// output GEMM: A = f16(concat_f32 + lepe_f16) on the fly, x2 epilogue, f32 out
// ---------------------------------------------------------------------------
__global__ __launch_bounds__(256)
void proj_gemm(const float* __restrict__ Acat, const __half* __restrict__ Alepe,
               const __half* __restrict__ BT, const float* __restrict__ bias,
               float* __restrict__ C)
{
    GEMM_CORE_DECL
    const int row0 = blockIdx.y * 128;
    const int col0 = blockIdx.x * 128;
    for (int c = 0; c < 4; c++) {
        #pragma unroll
        for (int i = 0; i < 4; i++) {
            int li = i * 256 + tid;
            int r = li >> 3, qf = (li & 7) * 8;
            size_t ai = (size_t)(row0 + r) * 256 + c * 64 + qf;
            float4 a0 = *(const float4*)(Acat + ai);
            float4 a1 = *(const float4*)(Acat + ai + 4);
            uint4 lh = *(const uint4*)(Alepe + ai);
            __half2* lp = (__half2*)&lh;
            float2 l0 = __half22float2(lp[0]);
            float2 l1 = __half22float2(lp[1]);
            float2 l2 = __half22float2(lp[2]);
            float2 l3 = __half22float2(lp[3]);
            __half2 h0 = __floats2half2_rn(a0.x + l0.x, a0.y + l0.y);
            __half2 h1 = __floats2half2_rn(a0.z + l1.x, a0.w + l1.y);
            __half2 h2 = __floats2half2_rn(a1.x + l2.x, a1.y + l2.y);
            __half2 h3 = __floats2half2_rn(a1.z + l3.x, a1.w + l3.y);
            uint4 pk;
            pk.x = *(uint32_t*)&h0; pk.y = *(uint32_t*)&h1;
            pk.z = *(uint32_t*)&h2; pk.w = *(uint32_t*)&h3;
            *(uint4*)(As + r * APITCH + qf) = pk;
            *(uint4*)(Bs + r * APITCH + qf) =
                *(const uint4*)(BT + (size_t)(col0 + r) * 256 + c * 64 + qf);
        }
        GEMM_CORE_MMA
    }
    GEMM_STORE_STAGE
    #pragma unroll
    for (int i = 0; i < 16; i++) {
        int lin = i * 256 + tid;
        int r = lin >> 5, c4 = (lin & 31) * 4;
        const float* s = Cst + r * CPITCH + c4;
        float4 v = make_float4(2.f * (s[0] + bias[col0 + c4 + 0]),
                               2.f * (s[1] + bias[col0 + c4 + 1]),
                               2.f * (s[2] + bias[col0 + c4 + 2]),
                               2.f * (s[3] + bias[col0 + c4 + 3]));
        *(float4*)(C + (size_t)(row0 + r) * 256 + col0 + c4) = v;
    }
}

// ---------------------------------------------------------------------------
// prep
// ---------------------------------------------------------------------------
__global__ void cvt_f16(const float* __restrict__ in, __half* __restrict__ out) {
    int idx = blockIdx.x * 256 + threadIdx.x;
    float4 v = *(const float4*)(in + (size_t)idx * 4);
    __half2 h0 = __floats2half2_rn(v.x, v.y);
    __half2 h1 = __floats2half2_rn(v.z, v.w);
    uint2 pk; pk.x = *(uint32_t*)&h0; pk.y = *(uint32_t*)&h1;
    *(uint2*)(out + (size_t)idx * 4) = pk;
}

__global__ void prep_w(const float* __restrict__ q1w, const float* __restrict__ q2w,
                       const float* __restrict__ kv2w, const float* __restrict__ lepew,
                       const float* __restrict__ kv1w, const float* __restrict__ projw,
                       const float* __restrict__ srw,
                       __half* __restrict__ wfused, __half* __restrict__ wkv1t,
                       __half* __restrict__ wprojt, __half* __restrict__ wsrt)
{
    int idx = blockIdx.x * 256 + threadIdx.x;
    if (idx < 196608) {
        int r = idx >> 8, k = idx & 255;
        float v;
        if (r < 128)      v = q1w[(size_t)k * 128 + r];
        else if (r < 256) v = q2w[(size_t)k * 128 + (r - 128)];
        else if (r < 512) v = kv2w[(size_t)k * 256 + (r - 256)];
        else              v = lepew[(size_t)k * 256 + (r - 512)];
        wfused[idx] = __float2half(v);
    } else if (idx < 262144) {
        int i = idx - 196608;
        int n = i >> 8, k = i & 255;
        wkv1t[i] = __float2half(kv1w[(size_t)k * 256 + n]);
    } else if (idx < 327680) {
        int i = idx - 262144;
        int n = i >> 8, k = i & 255;
        wprojt[i] = __float2half(projw[(size_t)k * 256 + n]);
    } else {
        int i = idx - 327680;
        int co = i >> 10, k = i & 1023;
        int kk = k >> 8, ci = k & 255;
        wsrt[i] = __float2half(srw[(size_t)co * 1024 + ci * 4 + kk]);
    }
}

// ---------------------------------------------------------------------------
// depthwise 3x3 conv, pad 1. Block = 4-row x 16-px tile x batch.
// Stage 6x18 pixels x 256 ch in smem via COALESCED linear uint4 copy
// (consecutive threads read consecutive 16B within a pixel's 512B channel run).
// Compute: thread owns channel pair c2, 32 pixels; smem reads conflict-free.
// ---------------------------------------------------------------------------
#define LEPE_SMEM (108 * 256 * 2 + 2304 * 4 + 256 * 4)   // 55296 + 9216 + 1024

__global__ __launch_bounds__(256)
void lepe_conv(const __half* __restrict__ in, const float* __restrict__ w,
               const float* __restrict__ bias, __half* __restrict__ out)
{
    extern __shared__ char lsm[];
    __half* sIn = (__half*)lsm;                 // [108 pixels][256 ch]
    float* ws = (float*)(lsm + 108 * 256 * 2);  // [2304]
    float* bs = ws + 2304;                      // [256]
    const int tid = threadIdx.x;
    const int tile = blockIdx.x;                // 0..63
    const int yt = tile >> 2, xt = tile & 3;    // yt: 4-row band, xt: 16-px span
    const int b = blockIdx.y;

    for (int i = tid; i < 2304; i += 256) ws[i] = w[i];
    bs[tid] = bias[tid];

    // stage 6 rows x 18 px x 256 ch (halo, zero-padded)
    for (int i = tid; i < 3456; i += 256) {
        int p = i >> 5, q = (i & 31) * 8;
        int ry = p / 18, px = p - ry * 18;
        int gy = yt * 4 - 1 + ry, gx = xt * 16 - 1 + px;
        uint4 v = make_uint4(0u, 0u, 0u, 0u);
        if (gy >= 0 && gy < KH && gx >= 0 && gx < KH)
            v = *(const uint4*)(in + ((size_t)b * KN + gy * KH + gx) * 256 + q);
        *(uint4*)(sIn + p * 256 + q) = v;
    }
    __syncthreads();

    const int c2 = tid & 127;
    const int g = tid >> 7;
    float wr[18];
    #pragma unroll
    for (int t = 0; t < 9; t++) {
        wr[t]     = ws[(c2 * 2) * 9 + t];
        wr[9 + t] = ws[(c2 * 2 + 1) * 9 + t];
    }
    const float b0 = bs[c2 * 2], b1 = bs[c2 * 2 + 1];

    #pragma unroll 4
    for (int j = 0; j < 32; j++) {
        int pl = g * 32 + j;
        int ry = pl >> 4, xi = pl & 15;
        float a0 = b0, a1 = b1;
        const __half* base = sIn + (ry * 18 + xi) * 256 + c2 * 2;
        #pragma unroll
        for (int dy = 0; dy < 3; dy++)
            #pragma unroll
            for (int dx = 0; dx < 3; dx++) {
                float2 f = __half22float2(*(const __half2*)(base + (dy * 18 + dx) * 256));
                a0 += f.x * wr[dy * 3 + dx];
                a1 += f.y * wr[9 + dy * 3 + dx];
            }
        int gy = yt * 4 + ry, gx = xt * 16 + xi;
        *(__half2*)(out + ((size_t)b * KN + gy * KH + gx) * 256 + c2 * 2) =
            __floats2half2_rn(a0, a1);
    }
}

// ---------------------------------------------------------------------------
// LayerNorm + GELU -> f16
// ---------------------------------------------------------------------------
__global__ void ln_gelu(const float* __restrict__ xs, const float* __restrict__ nw,
                        const float* __restrict__ nb, __half* __restrict__ o16)
{
    int row = blockIdx.x;
    int tid = threadIdx.x;
    float v = xs[(size_t)row * 256 + tid];
    __shared__ float red[16];
    float s = v, sq = v * v;
    #pragma unroll
    for (int o = 16; o; o >>= 1) {
        s  += __shfl_xor_sync(0xffffffffu, s, o);
        sq += __shfl_xor_sync(0xffffffffu, sq, o);
    }
    int w = tid >> 5, lane = tid & 31;
    if (lane == 0) { red[w] = s; red[8 + w] = sq; }
    __syncthreads();
    if (tid == 0) {
        float S = 0.f, SQ = 0.f;
        for (int i = 0; i < 8; i++) { S += red[i]; SQ += red[8 + i]; }
        red[0] = S; red[8] = SQ;
    }
    __syncthreads();
    float mean = red[0] * (1.f / 256.f);
    float var  = red[8] * (1.f / 256.f) - mean * mean;
    float t = (v - mean) * rsqrtf(var + 1e-5f) * nw[tid] + nb[tid];
    float g = 0.5f * t * (1.f + erff(t * 0.70710678118654752f));
    o16[(size_t)row * 256 + tid] = __float2half(g);
}

// ---------------------------------------------------------------------------
// Branch-1 attention, 512 threads = 16 warps
// ---------------------------------------------------------------------------
#define SPITCH 1040
#define PPITCH 1032
#define ATTN1_SMEM (32 * SPITCH * 4 + 32 * PPITCH * 2 + 128)

__global__ __launch_bounds__(512)
void attn1_kernel(const __half* __restrict__ q1h, const __half* __restrict__ kv1h,
                  float* __restrict__ concat, float* __restrict__ gpart)
{
    extern __shared__ char smraw[];
    float* S = (float*)smraw;
    __half* P = (__half*)(smraw + 32 * SPITCH * 4);
    float* rs = (float*)(smraw + 32 * SPITCH * 4 + 32 * PPITCH * 2);
    const int tid = threadIdx.x;
    const int w = tid >> 5, lane = tid & 31;
    const int qt = blockIdx.x, h = blockIdx.y, b = blockIdx.z;

    {
        wmma::fragment<wmma::matrix_a, 16, 16, 16, __half, wmma::row_major> af[2][2];
        #pragma unroll
        for (int mt = 0; mt < 2; mt++)
            #pragma unroll
            for (int ks = 0; ks < 2; ks++)
                wmma::load_matrix_sync(af[mt][ks],
                    q1h + ((size_t)b * KN + qt * 32 + mt * 16) * 128 + h * 32 + ks * 16, 128);
        #pragma unroll
        for (int nt = 0; nt < 4; nt++) {
            int col = w * 64 + nt * 16;
            wmma::fragment<wmma::accumulator, 16, 16, 16, float> a0, a1;
            wmma::fill_fragment(a0, 0.f);
            wmma::fill_fragment(a1, 0.f);
            #pragma unroll
            for (int ks = 0; ks < 2; ks++) {
                wmma::fragment<wmma::matrix_b, 16, 16, 16, __half, wmma::col_major> bf;
                wmma::load_matrix_sync(bf,
                    kv1h + ((size_t)b * KN1 + col) * 256 + h * 32 + ks * 16, 256);
                wmma::mma_sync(a0, af[0][ks], bf, a0);
                wmma::mma_sync(a1, af[1][ks], bf, a1);
            }
            #pragma unroll
            for (int e = 0; e < a0.num_elements; e++) { a0.x[e] *= KSCALE; a1.x[e] *= KSCALE; }
            wmma::store_matrix_sync(S + 0 * SPITCH + col, a0, SPITCH, wmma::mem_row_major);
            wmma::store_matrix_sync(S + 16 * SPITCH + col, a1, SPITCH, wmma::mem_row_major);
        }
    }
    __syncthreads();

    #pragma unroll
    for (int ri = 0; ri < 2; ri++) {
        int r = w * 2 + ri;
        float ssum = 0.f;
        #pragma unroll 8
        for (int m = lane; m < 1024; m += 32) {
            float e = __expf(S[r * SPITCH + m]);
            S[r * SPITCH + m] = e;
            ssum += e;
        }
        #pragma unroll
        for (int o = 16; o; o >>= 1) ssum += __shfl_xor_sync(0xffffffffu, ssum, o);
        if (lane == 0) rs[r] = ssum;
    }
    __syncthreads();
    if (tid < 32) rs[tid] = 1.f / rs[tid];
    __syncthreads();

    #pragma unroll
    for (int mi = 0; mi < 2; mi++) {
        int m = tid + mi * 512;
        float cs = 0.f;
        #pragma unroll
        for (int r = 0; r < 32; r++) {
            float v = S[r * SPITCH + m] * rs[r];
            cs += v;
            P[r * PPITCH + m] = __float2half(v);
        }
        gpart[(((size_t)(b * 4 + h) * 128) + qt) * 1024 + m] = cs;
    }
    __syncthreads();

    {
        wmma::fragment<wmma::accumulator, 16, 16, 16, float> acc2[2][2];
        #pragma unroll
        for (int mt = 0; mt < 2; mt++)
            #pragma unroll
            for (int nt = 0; nt < 2; nt++)
                wmma::fill_fragment(acc2[mt][nt], 0.f);
        #pragma unroll
        for (int ks = 0; ks < 4; ks++) {
            int kk = w * 64 + ks * 16;
            wmma::fragment<wmma::matrix_a, 16, 16, 16, __half, wmma::row_major> ap[2];
            wmma::fragment<wmma::matrix_b, 16, 16, 16, __half, wmma::row_major> bp[2];
            #pragma unroll
            for (int mt = 0; mt < 2; mt++)
                wmma::load_matrix_sync(ap[mt], P + (mt * 16) * PPITCH + kk, PPITCH);
            #pragma unroll
            for (int nt = 0; nt < 2; nt++)
                wmma::load_matrix_sync(bp[nt],
                    kv1h + ((size_t)b * KN1 + kk) * 256 + 128 + h * 32 + nt * 16, 256);
            #pragma unroll
            for (int mt = 0; mt < 2; mt++)
                #pragma unroll
                for (int nt = 0; nt < 2; nt++)
                    wmma::mma_sync(acc2[mt][nt], ap[mt], bp[nt], acc2[mt][nt]);
        }
        float* Sp = S + w * 1024;
        #pragma unroll
        for (int mt = 0; mt < 2; mt++)
            #pragma unroll
            for (int nt = 0; nt < 2; nt++)
                wmma::store_matrix_sync(Sp + mt * 16 * 32 + nt * 16, acc2[mt][nt],
                                        32, wmma::mem_row_major);
    }
    __syncthreads();

    #pragma unroll
    for (int ii = 0; ii < 2; ii++) {
        int idx = tid + ii * 512;
        int q = idx >> 5, dd = idx & 31;
        float sum = 0.f;
        #pragma unroll
        for (int j = 0; j < 16; j++) sum += S[j * 1024 + idx];
        concat[((size_t)b * KN + qt * 32 + q) * 256 + h * 32 + dd] = sum;
    }
}

// ---------------------------------------------------------------------------
// Branch-2 windowed attention (fp32)
// ---------------------------------------------------------------------------
__global__ void attn2_kernel(const float* __restrict__ q2, const float* __restrict__ kv2,
                             float* __restrict__ concat, float* __restrict__ lmpart)
{
    __shared__ float sQ[4][512];
    __shared__ float sKT[4][512];
    __shared__ float sV[4][512];
    __shared__ float sS[4][16 * 17];
    const int w = threadIdx.x >> 5, lane = threadIdx.x & 31;
    const int gw = blockIdx.x * 4 + w;
    const int b = gw >> 10;
    const int rem = gw & 1023;
    const int h = rem >> 8;
    const int win = rem & 255;
    const int wy = win >> 4, wx = win & 15;

    for (int t = 0; t < 16; t++) {
        int n = (wy * 4 + (t >> 2)) * KH + wx * 4 + (t & 3);
        sQ[w][t * 32 + lane]  = q2[((size_t)b * KN + n) * 128 + h * 32 + lane];
        sKT[w][lane * 16 + t] = kv2[((size_t)b * KN + n) * 256 + h * 32 + lane];
        sV[w][t * 32 + lane]  = kv2[((size_t)b * KN + n) * 256 + 128 + h * 32 + lane];
    }
    __syncwarp();

    #pragma unroll
    for (int r = 0; r < 8; r++) {
        int e = r * 32 + lane;
        int i = e >> 4, j = e & 15;
        float acc = 0.f;
        #pragma unroll
        for (int k = 0; k < 32; k++) acc += sQ[w][i * 32 + k] * sKT[w][k * 16 + j];
        sS[w][i * 17 + j] = acc * KSCALE;
    }
    __syncwarp();

    if (lane < 16) {
        float mx = -1e30f;
        #pragma unroll
        for (int j = 0; j < 16; j++) mx = fmaxf(mx, sS[w][lane * 17 + j]);
        float s = 0.f;
        #pragma unroll
        for (int j = 0; j < 16; j++) {
            float e = __expf(sS[w][lane * 17 + j] - mx);
            sS[w][lane * 17 + j] = e;
            s += e;
        }
        float inv = 1.f / s;
        #pragma unroll
        for (int j = 0; j < 16; j++) sS[w][lane * 17 + j] *= inv;
    }
    __syncwarp();

    if (lane < 16) {
        float cs = 0.f;
        #pragma unroll
        for (int i = 0; i < 16; i++) cs += sS[w][i * 17 + lane];
        lmpart[(((size_t)(b * 4 + h) * 256) + win) * 16 + lane] = cs;
    }

    for (int i = 0; i < 16; i++) {
        float acc = 0.f;
        #pragma unroll
        for (int j = 0; j < 16; j++) acc += sS[w][i * 17 + j] * sV[w][j * 32 + lane];
        int n = (wy * 4 + (i >> 2)) * KH + wx * 4 + (i & 3);
        concat[((size_t)b * KN + n) * 256 + 128 + h * 32 + lane] = acc;
    }
}

// ---------------------------------------------------------------------------
// stage-1 g reduce: 8 partials per (b,m), 32768 threads
// ---------------------------------------------------------------------------
__global__ void g_reduce(const float* __restrict__ gpart, float* __restrict__ gred2)
{
    int idx = blockIdx.x * 256 + threadIdx.x;   // 32768
    int g = idx >> 12;
    int r = idx & 4095;
    int b = r >> 10, m = r & 1023;
    float s = 0.f;
    #pragma unroll 8
    for (int j = 0; j < 64; j++)
        s += gpart[((size_t)b * 512 + g * 64 + j) * 1024 + m];
    gred2[(size_t)g * 4096 + r] = s;
}

__global__ void mask_kernel(const float* __restrict__ gred2, const float* __restrict__ lmpart,
                            float* __restrict__ m1, float* __restrict__ m2)
{
    int idx = blockIdx.x * 256 + threadIdx.x;
    int b = idx >> 12, n = idx & 4095;
    int y = n >> 6, x = n & 63;
    int ri = b * 1024 + (y >> 1) * 32 + (x >> 1);
    float gv = 0.f;
    #pragma unroll
    for (int g = 0; g < 8; g++) gv += gred2[g * 4096 + ri];
    gv *= (1.f / 16384.f);
    int win = (y >> 2) * 16 + (x >> 2);
    int t = (y & 3) * 4 + (x & 3);
    float lv = 0.f;
    #pragma unroll
    for (int h = 0; h < 4; h++)
        lv += lmpart[(((size_t)(b * 4 + h) * 256) + win) * 16 + t];
    lv *= (1.f / 64.f);
    float val = gv + lv;
    m1[b * KN + y * KH + x] = val;
    m2[b * KN + x * KH + y] = val;
}

// ---------------------------------------------------------------------------
// launcher
// ---------------------------------------------------------------------------
extern "C" void kernel_launch(void* const* d_in, const int* in_sizes, int n_in,
                              void* d_out, int out_size)
{
    const float* x      = (const float*)d_in[0];
    const float* q1_w   = (const float*)d_in[1];
    const float* q1_b   = (const float*)d_in[2];
    const float* kv1_w  = (const float*)d_in[3];
    const float* kv1_b  = (const float*)d_in[4];
    const float* q2_w   = (const float*)d_in[5];
    const float* q2_b   = (const float*)d_in[6];
    const float* kv2_w  = (const float*)d_in[7];
    const float* kv2_b  = (const float*)d_in[8];
    const float* lepe_w = (const float*)d_in[9];
    const float* lepe_b = (const float*)d_in[10];
    const float* lcw    = (const float*)d_in[11];
    const float* lcb    = (const float*)d_in[12];
    const float* sr_w   = (const float*)d_in[13];
    const float* sr_b   = (const float*)d_in[14];
    const float* norm_w = (const float*)d_in[15];
    const float* norm_b = (const float*)d_in[16];
    const float* proj_w = (const float*)d_in[17];
    const float* proj_b = (const float*)d_in[18];
    (void)in_sizes; (void)n_in; (void)out_size;

    float* scratch = nullptr;
    cudaGetSymbolAddress((void**)&scratch, g_scratch);
    __half* hs = nullptr;
    cudaGetSymbolAddress((void**)&hs, g_scratch_h);

    float* q2buf  = scratch + OFF_Q2;
    float* kv2buf = scratch + OFF_KV2;
    float* xs     = scratch + OFF_XS;
    float* concat = scratch + OFF_CONCAT;
    float* gpart  = scratch + OFF_GPART;
    float* gred2  = scratch + OFF_GRED2;
    float* lmpart = scratch + OFF_LMPART;

    __half* xh     = hs + HOFF_XH;
    __half* xsh    = hs + HOFF_XSH;
    __half* q1h    = hs + HOFF_Q1H;
    __half* kv1h   = hs + HOFF_KV1H;
    __half* lepeh  = hs + HOFF_LEPEH;
    __half* lepec  = hs + HOFF_LEPEC;
    __half* wfused = hs + HOFF_WFUSE;
    __half* wkv1t  = hs + HOFF_WKV1;
    __half* wprojt = hs + HOFF_WPROJ;
    __half* wsrt   = hs + HOFF_WSR;

    float* out = (float*)d_out;
    float* m1  = out + (size_t)KB * KN * KC;
    float* m2  = m1 + (size_t)KB * KN;

    cudaFuncSetAttribute(hgemm_h,   cudaFuncAttributeMaxDynamicSharedMemorySize, HG_SMEM);
    cudaFuncSetAttribute(qkv_gemm,  cudaFuncAttributeMaxDynamicSharedMemorySize, HG_SMEM);
    cudaFuncSetAttribute(sr_gemm,   cudaFuncAttributeMaxDynamicSharedMemorySize, HG_SMEM);
    cudaFuncSetAttribute(proj_gemm, cudaFuncAttributeMaxDynamicSharedMemorySize, HG_SMEM);
    cudaFuncSetAttribute(attn1_kernel, cudaFuncAttributeMaxDynamicSharedMemorySize, ATTN1_SMEM);
    cudaFuncSetAttribute(lepe_conv, cudaFuncAttributeMaxDynamicSharedMemorySize, LEPE_SMEM);

    cvt_f16<<<4096, 256>>>(x, xh);
    prep_w<<<2304, 256>>>(q1_w, q2_w, kv2_w, lepe_w, kv1_w, proj_w, sr_w,
                          wfused, wkv1t, wprojt, wsrt);

    // fused projections: q1(f16), q2(f32), kv2(f32), lepe_lin(f16)
    qkv_gemm<<<dim3(6, 128), 256, HG_SMEM>>>(xh, wfused, q1_b, q2_b, kv2_b, lepe_b,
                                             q1h, q2buf, kv2buf, lepeh);
    lepe_conv<<<dim3(64, 4), 256, LEPE_SMEM>>>(lepeh, lcw, lcb, lepec);

    // spatial reduction -> LN -> GELU -> kv1
    sr_gemm<<<dim3(2, 32), 256, HG_SMEM>>>(xh, wsrt, sr_b, xs);
    ln_gelu<<<KB * KN1, 256>>>(xs, norm_w, norm_b, xsh);
    hgemm_h<<<dim3(2, 32), 256, HG_SMEM>>>(xsh, wkv1t, kv1_b, kv1h,
                                           KB * KN1, 256, 256);

    // attention branches
    attn1_kernel<<<dim3(128, 4, 4), 512, ATTN1_SMEM>>>(q1h, kv1h, concat, gpart);
    g_reduce<<<128, 256>>>(gpart, gred2);
    attn2_kernel<<<1024, 128>>>(q2buf, kv2buf, concat, lmpart);
    mask_kernel<<<64, 256>>>(gred2, lmpart, m1, m2);

    // output projection with fused (concat + lepe_f16) and x2 epilogue
    proj_gemm<<<dim3(2, 128), 256, HG_SMEM>>>(concat, lepec, wprojt, proj_b, out);
}

// round 16
// speedup vs baseline: 3.2500x; 1.0350x over previous
#include <cuda_runtime.h>
#include <cuda_fp16.h>
#include <mma.h>
#include <math.h>
#include <stdint.h>

using namespace nvcuda;

#define KB   4
#define KN   4096
#define KC   256
#define KH   64
#define KN1  1024
#define KSCALE 0.17677669529663687f

// fp32 scratch
#define OFF_Q2       ((size_t)0)
#define OFF_KV2      (OFF_Q2     + (size_t)KB*KN*128)
#define OFF_XS       (OFF_KV2    + (size_t)KB*KN*256)
#define OFF_GPART    (OFF_XS     + (size_t)KB*KN1*256)
#define OFF_GRED2    (OFF_GPART  + (size_t)KB*4*128*1024)
#define OFF_LMPART   (OFF_GRED2  + (size_t)8*KB*1024)
#define SCRATCH_TOT  (OFF_LMPART + (size_t)KB*4*256*16)

__device__ float g_scratch[SCRATCH_TOT];

// f16 scratch
#define HOFF_XH    ((size_t)0)
#define HOFF_XSH   (HOFF_XH    + (size_t)4194304)
#define HOFF_Q1H   (HOFF_XSH   + (size_t)1048576)
#define HOFF_KV1H  (HOFF_Q1H   + (size_t)2097152)
#define HOFF_LEPEH (HOFF_KV1H  + (size_t)1048576)
#define HOFF_LEPEC (HOFF_LEPEH + (size_t)4194304)
#define HOFF_CATH  (HOFF_LEPEC + (size_t)4194304)
#define HOFF_WFUSE (HOFF_CATH  + (size_t)4194304)
#define HOFF_WKV1  (HOFF_WFUSE + (size_t)196608)
#define HOFF_WPROJ (HOFF_WKV1  + (size_t)65536)
#define HOFF_WSR   (HOFF_WPROJ + (size_t)65536)
#define HSCRATCH_TOT (HOFF_WSR + (size_t)262144)

__device__ __half g_scratch_h[HSCRATCH_TOT];

// ---------------------------------------------------------------------------
// common wmma tile config: 128x128 tile, 256 threads = 8 warps (2 x 4)
// ---------------------------------------------------------------------------
#define APITCH 72
#define CPITCH 132
#define HG_SMEM (128 * CPITCH * 4)

#define GEMM_CORE_DECL \
    extern __shared__ char smraw[]; \
    __half* As = (__half*)smraw; \
    __half* Bs = As + 128 * APITCH; \
    float*  Cst = (float*)smraw; \
    const int tid = threadIdx.x; \
    const int wid = tid >> 5; \
    const int warp_row = wid >> 2; \
    const int warp_col = wid & 3; \
    wmma::fragment<wmma::accumulator, 16, 16, 16, float> acc[4][2]; \
    _Pragma("unroll") \
    for (int mt = 0; mt < 4; mt++) \
        _Pragma("unroll") \
        for (int nt = 0; nt < 2; nt++) \
            wmma::fill_fragment(acc[mt][nt], 0.f);

#define GEMM_CORE_MMA \
    __syncthreads(); \
    _Pragma("unroll") \
    for (int ks = 0; ks < 4; ks++) { \
        wmma::fragment<wmma::matrix_a, 16, 16, 16, __half, wmma::row_major> af[4]; \
        wmma::fragment<wmma::matrix_b, 16, 16, 16, __half, wmma::col_major> bf[2]; \
        _Pragma("unroll") \
        for (int mt = 0; mt < 4; mt++) \
            wmma::load_matrix_sync(af[mt], As + (warp_row * 64 + mt * 16) * APITCH + ks * 16, APITCH); \
        _Pragma("unroll") \
        for (int nt = 0; nt < 2; nt++) \
            wmma::load_matrix_sync(bf[nt], Bs + (warp_col * 32 + nt * 16) * APITCH + ks * 16, APITCH); \
        _Pragma("unroll") \
        for (int mt = 0; mt < 4; mt++) \
            _Pragma("unroll") \
            for (int nt = 0; nt < 2; nt++) \
                wmma::mma_sync(acc[mt][nt], af[mt], bf[nt], acc[mt][nt]); \
    } \
    __syncthreads();

#define GEMM_STORE_STAGE \
    _Pragma("unroll") \
    for (int mt = 0; mt < 4; mt++) \
        _Pragma("unroll") \
        for (int nt = 0; nt < 2; nt++) \
            wmma::store_matrix_sync(Cst + (warp_row * 64 + mt * 16) * CPITCH + warp_col * 32 + nt * 16, \
                                    acc[mt][nt], CPITCH, wmma::mem_row_major); \
    __syncthreads();

// ---------------------------------------------------------------------------
// generic hgemm (kv1): C = A @ BT^T + bias, f16 out
// ---------------------------------------------------------------------------
__global__ __launch_bounds__(256)
void hgemm_h(const __half* __restrict__ A, const __half* __restrict__ BT,
             const float* __restrict__ bias, __half* __restrict__ Cout,
             int M, int N, int K)
{
    GEMM_CORE_DECL
    const int row0 = blockIdx.y * 128;
    const int col0 = blockIdx.x * 128;
    const int kn = K >> 6;
    for (int c = 0; c < kn; c++) {
        #pragma unroll
        for (int i = 0; i < 4; i++) {
            int li = i * 256 + tid;
            int r = li >> 3, q = (li & 7) * 8;
            *(uint4*)(As + r * APITCH + q) = *(const uint4*)(A + (size_t)(row0 + r) * K + c * 64 + q);
            *(uint4*)(Bs + r * APITCH + q) = *(const uint4*)(BT + (size_t)(col0 + r) * K + c * 64 + q);
        }
        GEMM_CORE_MMA
    }
    GEMM_STORE_STAGE
    #pragma unroll
    for (int i = 0; i < 16; i++) {
        int lin = i * 256 + tid;
        int r = lin >> 5, c4 = (lin & 31) * 4;
        const float* s = Cst + r * CPITCH + c4;
        __half2 h0 = __floats2half2_rn(s[0] + bias[col0 + c4 + 0], s[1] + bias[col0 + c4 + 1]);
        __half2 h1 = __floats2half2_rn(s[2] + bias[col0 + c4 + 2], s[3] + bias[col0 + c4 + 3]);
        uint2 pk; pk.x = *(uint32_t*)&h0; pk.y = *(uint32_t*)&h1;
        *(uint2*)(Cout + (size_t)(row0 + r) * N + col0 + c4) = pk;
    }
}

// ---------------------------------------------------------------------------
// fused projection GEMM: col tiles 0->q1h 1->q2 2,3->kv2 4,5->lepeh
// ---------------------------------------------------------------------------
__global__ __launch_bounds__(256)
void qkv_gemm(const __half* __restrict__ A, const __half* __restrict__ BT,
              const float* __restrict__ q1_b, const float* __restrict__ q2_b,
              const float* __restrict__ kv2_b, const float* __restrict__ lepe_b,
              __half* __restrict__ q1h, float* __restrict__ q2o,
              float* __restrict__ kv2o, __half* __restrict__ lepeh)
{
    GEMM_CORE_DECL
    const int row0 = blockIdx.y * 128;
    const int col0 = blockIdx.x * 128;
    for (int c = 0; c < 4; c++) {
        #pragma unroll
        for (int i = 0; i < 4; i++) {
            int li = i * 256 + tid;
            int r = li >> 3, q = (li & 7) * 8;
            *(uint4*)(As + r * APITCH + q) = *(const uint4*)(A + (size_t)(row0 + r) * 256 + c * 64 + q);
            *(uint4*)(Bs + r * APITCH + q) = *(const uint4*)(BT + (size_t)(col0 + r) * 256 + c * 64 + q);
        }
        GEMM_CORE_MMA
    }
    GEMM_STORE_STAGE

    const int t = blockIdx.x;
    __half* hdst = nullptr; float* fdst = nullptr;
    const float* bp; int pitch, cofs;
    switch (t) {
        case 0:  hdst = q1h;  bp = q1_b;  pitch = 128; cofs = 0;   break;
        case 1:  fdst = q2o;  bp = q2_b;  pitch = 128; cofs = 0;   break;
        case 2:  fdst = kv2o; bp = kv2_b; pitch = 256; cofs = 0;   break;
        case 3:  fdst = kv2o; bp = kv2_b; pitch = 256; cofs = 128; break;
        case 4:  hdst = lepeh; bp = lepe_b; pitch = 256; cofs = 0;   break;
        default: hdst = lepeh; bp = lepe_b; pitch = 256; cofs = 128; break;
    }
    #pragma unroll
    for (int i = 0; i < 16; i++) {
        int lin = i * 256 + tid;
        int r = lin >> 5, c4 = (lin & 31) * 4;
        const float* s = Cst + r * CPITCH + c4;
        float v0 = s[0] + bp[cofs + c4 + 0];
        float v1 = s[1] + bp[cofs + c4 + 1];
        float v2 = s[2] + bp[cofs + c4 + 2];
        float v3 = s[3] + bp[cofs + c4 + 3];
        size_t o = (size_t)(row0 + r) * pitch + cofs + c4;
        if (hdst) {
            __half2 h0 = __floats2half2_rn(v0, v1);
            __half2 h1 = __floats2half2_rn(v2, v3);
            uint2 pk; pk.x = *(uint32_t*)&h0; pk.y = *(uint32_t*)&h1;
            *(uint2*)(hdst + o) = pk;
        } else {
            *(float4*)(fdst + o) = make_float4(v0, v1, v2, v3);
        }
    }
}

// ---------------------------------------------------------------------------
// sr conv as GEMM with inline im2col gather from xh
// ---------------------------------------------------------------------------
__global__ __launch_bounds__(256)
void sr_gemm(const __half* __restrict__ xh, const __half* __restrict__ BT,
             const float* __restrict__ bias, float* __restrict__ C)
{
    GEMM_CORE_DECL
    const int row0 = blockIdx.y * 128;
    const int col0 = blockIdx.x * 128;
    for (int c = 0; c < 16; c++) {
        const int kk = c >> 2;
        const int ky = kk >> 1, kx = kk & 1;
        const int cib = (c & 3) * 64;
        #pragma unroll
        for (int i = 0; i < 4; i++) {
            int li = i * 256 + tid;
            int r = li >> 3, q = (li & 7) * 8;
            int m = row0 + r;
            int b = m >> 10, p = m & 1023;
            int oy = p >> 5, ox = p & 31;
            int n = (2 * oy + ky) * KH + 2 * ox + kx;
            *(uint4*)(As + r * APITCH + q) =
                *(const uint4*)(xh + ((size_t)b * KN + n) * 256 + cib + q);
            *(uint4*)(Bs + r * APITCH + q) =
                *(const uint4*)(BT + (size_t)(col0 + r) * 1024 + c * 64 + q);
        }
        GEMM_CORE_MMA
    }
    GEMM_STORE_STAGE
    #pragma unroll
    for (int i = 0; i < 16; i++) {
        int lin = i * 256 + tid;
        int r = lin >> 5, c4 = (lin & 31) * 4;
        const float* s = Cst + r * CPITCH + c4;
        float4 v = make_float4(s[0] + bias[col0 + c4 + 0], s[1] + bias[col0 + c4 + 1],
                               s[2] + bias[col0 + c4 + 2], s[3] + bias[col0 + c4 + 3]);
        *(float4*)(C + (size_t)(row0 + r) * 256 + col0 + c4) = v;
    }
}

// ---------------------------------------------------------------------------
// output GEMM: A = f16(concat_f16 + lepe_f16), x2 epilogue, f32 out
// ---------------------------------------------------------------------------
__global__ __launch_bounds__(256)
void proj_gemm(const __half* __restrict__ Acat, const __half* __restrict__ Alepe,
               const __half* __restrict__ BT, const float* __restrict__ bias,
               float* __restrict__ C)
{
    GEMM_CORE_DECL
    const int row0 = blockIdx.y * 128;
    const int col0 = blockIdx.x * 128;
    for (int c = 0; c < 4; c++) {
        #pragma unroll
        for (int i = 0; i < 4; i++) {
            int li = i * 256 + tid;
            int r = li >> 3, qf = (li & 7) * 8;
            size_t ai = (size_t)(row0 + r) * 256 + c * 64 + qf;
            uint4 chv = *(const uint4*)(Acat + ai);
            uint4 lhv = *(const uint4*)(Alepe + ai);
            __half2* cp = (__half2*)&chv;
            __half2* lp = (__half2*)&lhv;
            uint4 pk;
            __half2* op = (__half2*)&pk;
            #pragma unroll
            for (int u = 0; u < 4; u++) {
                float2 a = __half22float2(cp[u]);
                float2 l = __half22float2(lp[u]);
                op[u] = __floats2half2_rn(a.x + l.x, a.y + l.y);
            }
            *(uint4*)(As + r * APITCH + qf) = pk;
            *(uint4*)(Bs + r * APITCH + qf) =
                *(const uint4*)(BT + (size_t)(col0 + r) * 256 + c * 64 + qf);
        }
        GEMM_CORE_MMA
    }
    GEMM_STORE_STAGE
    #pragma unroll
    for (int i = 0; i < 16; i++) {
        int lin = i * 256 + tid;
        int r = lin >> 5, c4 = (lin & 31) * 4;
        const float* s = Cst + r * CPITCH + c4;
        float4 v = make_float4(2.f * (s[0] + bias[col0 + c4 + 0]),
                               2.f * (s[1] + bias[col0 + c4 + 1]),
                               2.f * (s[2] + bias[col0 + c4 + 2]),
                               2.f * (s[3] + bias[col0 + c4 + 3]));
        *(float4*)(C + (size_t)(row0 + r) * 256 + col0 + c4) = v;
    }
}

// ---------------------------------------------------------------------------
// prep
// ---------------------------------------------------------------------------
__global__ void cvt_f16(const float* __restrict__ in, __half* __restrict__ out) {
    int idx = blockIdx.x * 256 + threadIdx.x;
    float4 v = *(const float4*)(in + (size_t)idx * 4);
    __half2 h0 = __floats2half2_rn(v.x, v.y);
    __half2 h1 = __floats2half2_rn(v.z, v.w);
    uint2 pk; pk.x = *(uint32_t*)&h0; pk.y = *(uint32_t*)&h1;
    *(uint2*)(out + (size_t)idx * 4) = pk;
}

__global__ void prep_w(const float* __restrict__ q1w, const float* __restrict__ q2w,
                       const float* __restrict__ kv2w, const float* __restrict__ lepew,
                       const float* __restrict__ kv1w, const float* __restrict__ projw,
                       const float* __restrict__ srw,
                       __half* __restrict__ wfused, __half* __restrict__ wkv1t,
                       __half* __restrict__ wprojt, __half* __restrict__ wsrt)
{
    int idx = blockIdx.x * 256 + threadIdx.x;
    if (idx < 196608) {
        int r = idx >> 8, k = idx & 255;
        float v;
        if (r < 128)      v = q1w[(size_t)k * 128 + r];
        else if (r < 256) v = q2w[(size_t)k * 128 + (r - 128)];
        else if (r < 512) v = kv2w[(size_t)k * 256 + (r - 256)];
        else              v = lepew[(size_t)k * 256 + (r - 512)];
        wfused[idx] = __float2half(v);
    } else if (idx < 262144) {
        int i = idx - 196608;
        int n = i >> 8, k = i & 255;
        wkv1t[i] = __float2half(kv1w[(size_t)k * 256 + n]);
    } else if (idx < 327680) {
        int i = idx - 262144;
        int n = i >> 8, k = i & 255;
        wprojt[i] = __float2half(projw[(size_t)k * 256 + n]);
    } else {
        int i = idx - 327680;
        int co = i >> 10, k = i & 1023;
        int kk = k >> 8, ci = k & 255;
        wsrt[i] = __float2half(srw[(size_t)co * 1024 + ci * 4 + kk]);
    }
}

// ---------------------------------------------------------------------------
// depthwise 3x3 conv, pad 1. Block = 4-row x 16-px tile x 128-ch half x batch.
// 512 blocks, 32KB smem (coalesced staging, conflict-free compute).
// ---------------------------------------------------------------------------
#define LEPE_SMEM (108 * 128 * 2 + 1152 * 4 + 128 * 4)   // 27648 + 4608 + 512 = 32768

__global__ __launch_bounds__(256)
void lepe_conv(const __half* __restrict__ in, const float* __restrict__ w,
               const float* __restrict__ bias, __half* __restrict__ out)
{
    extern __shared__ char lsm[];
    __half* sIn = (__half*)lsm;                 // [108 pixels][128 ch]
    float* ws = (float*)(lsm + 108 * 128 * 2);  // [1152]
    float* bs = ws + 1152;                      // [128]
    const int tid = threadIdx.x;
    const int tile = blockIdx.x;                // 0..63
    const int yt = tile >> 2, xt = tile & 3;
    const int cg = blockIdx.y;                  // channel half
    const int b = blockIdx.z;

    for (int i = tid; i < 1152; i += 256) ws[i] = w[cg * 1152 + i];
    if (tid < 128) bs[tid] = bias[cg * 128 + tid];

    // stage 6 rows x 18 px x 128 ch
    for (int i = tid; i < 1728; i += 256) {
        int p = i >> 4, q = (i & 15) * 8;
        int ry = p / 18, px = p - ry * 18;
        int gy = yt * 4 - 1 + ry, gx = xt * 16 - 1 + px;
        uint4 v = make_uint4(0u, 0u, 0u, 0u);
        if (gy >= 0 && gy < KH && gx >= 0 && gx < KH)
            v = *(const uint4*)(in + ((size_t)b * KN + gy * KH + gx) * 256 + cg * 128 + q);
        *(uint4*)(sIn + p * 128 + q) = v;
    }
    __syncthreads();

    const int c2 = tid & 63;          // channel pair within the 128-ch half
    const int g = tid >> 6;           // pixel group (4 x 16 px)
    float wr[18];
    #pragma unroll
    for (int t = 0; t < 9; t++) {
        wr[t]     = ws[(c2 * 2) * 9 + t];
        wr[9 + t] = ws[(c2 * 2 + 1) * 9 + t];
    }
    const float b0 = bs[c2 * 2], b1 = bs[c2 * 2 + 1];

    #pragma unroll 4
    for (int j = 0; j < 16; j++) {
        int pl = g * 16 + j;
        int ry = pl >> 4, xi = pl & 15;
        float a0 = b0, a1 = b1;
        const __half* base = sIn + (ry * 18 + xi) * 128 + c2 * 2;
        #pragma unroll
        for (int dy = 0; dy < 3; dy++)
            #pragma unroll
            for (int dx = 0; dx < 3; dx++) {
                float2 f = __half22float2(*(const __half2*)(base + (dy * 18 + dx) * 128));
                a0 += f.x * wr[dy * 3 + dx];
                a1 += f.y * wr[9 + dy * 3 + dx];
            }
        int gy = yt * 4 + ry, gx = xt * 16 + xi;
        *(__half2*)(out + ((size_t)b * KN + gy * KH + gx) * 256 + cg * 128 + c2 * 2) =
            __floats2half2_rn(a0, a1);
    }
}

// ---------------------------------------------------------------------------
// LayerNorm + GELU -> f16
// ---------------------------------------------------------------------------
__global__ void ln_gelu(const float* __restrict__ xs, const float* __restrict__ nw,
                        const float* __restrict__ nb, __half* __restrict__ o16)
{
    int row = blockIdx.x;
    int tid = threadIdx.x;
    float v = xs[(size_t)row * 256 + tid];
    __shared__ float red[16];
    float s = v, sq = v * v;
    #pragma unroll
    for (int o = 16; o; o >>= 1) {
        s  += __shfl_xor_sync(0xffffffffu, s, o);
        sq += __shfl_xor_sync(0xffffffffu, sq, o);
    }
    int w = tid >> 5, lane = tid & 31;
    if (lane == 0) { red[w] = s; red[8 + w] = sq; }
    __syncthreads();
    if (tid == 0) {
        float S = 0.f, SQ = 0.f;
        for (int i = 0; i < 8; i++) { S += red[i]; SQ += red[8 + i]; }
        red[0] = S; red[8] = SQ;
    }
    __syncthreads();
    float mean = red[0] * (1.f / 256.f);
    float var  = red[8] * (1.f / 256.f) - mean * mean;
    float t = (v - mean) * rsqrtf(var + 1e-5f) * nw[tid] + nb[tid];
    float g = 0.5f * t * (1.f + erff(t * 0.70710678118654752f));
    o16[(size_t)row * 256 + tid] = __float2half(g);
}

// ---------------------------------------------------------------------------
// Branch-1 attention, 512 threads = 16 warps. exp applied in-register.
// ---------------------------------------------------------------------------
#define SPITCH 1040
#define PPITCH 1032
#define ATTN1_SMEM (32 * SPITCH * 4 + 32 * PPITCH * 2 + 128)

__global__ __launch_bounds__(512)
void attn1_kernel(const __half* __restrict__ q1h, const __half* __restrict__ kv1h,
                  __half* __restrict__ concath, float* __restrict__ gpart)
{
    extern __shared__ char smraw[];
    float* S = (float*)smraw;
    __half* P = (__half*)(smraw + 32 * SPITCH * 4);
    float* rs = (float*)(smraw + 32 * SPITCH * 4 + 32 * PPITCH * 2);
    const int tid = threadIdx.x;
    const int w = tid >> 5, lane = tid & 31;
    const int qt = blockIdx.x, h = blockIdx.y, b = blockIdx.z;

    // ---- QK^T with in-register exp: warp w covers key cols [w*64, w*64+64) ----
    {
        wmma::fragment<wmma::matrix_a, 16, 16, 16, __half, wmma::row_major> af[2][2];
        #pragma unroll
        for (int mt = 0; mt < 2; mt++)
            #pragma unroll
            for (int ks = 0; ks < 2; ks++)
                wmma::load_matrix_sync(af[mt][ks],
                    q1h + ((size_t)b * KN + qt * 32 + mt * 16) * 128 + h * 32 + ks * 16, 128);
        #pragma unroll
        for (int nt = 0; nt < 4; nt++) {
            int col = w * 64 + nt * 16;
            wmma::fragment<wmma::accumulator, 16, 16, 16, float> a0, a1;
            wmma::fill_fragment(a0, 0.f);
            wmma::fill_fragment(a1, 0.f);
            #pragma unroll
            for (int ks = 0; ks < 2; ks++) {
                wmma::fragment<wmma::matrix_b, 16, 16, 16, __half, wmma::col_major> bf;
                wmma::load_matrix_sync(bf,
                    kv1h + ((size_t)b * KN1 + col) * 256 + h * 32 + ks * 16, 256);
                wmma::mma_sync(a0, af[0][ks], bf, a0);
                wmma::mma_sync(a1, af[1][ks], bf, a1);
            }
            #pragma unroll
            for (int e = 0; e < a0.num_elements; e++) {
                a0.x[e] = __expf(a0.x[e] * KSCALE);
                a1.x[e] = __expf(a1.x[e] * KSCALE);
            }
            wmma::store_matrix_sync(S + 0 * SPITCH + col, a0, SPITCH, wmma::mem_row_major);
            wmma::store_matrix_sync(S + 16 * SPITCH + col, a1, SPITCH, wmma::mem_row_major);
        }
    }
    __syncthreads();

    // ---- row sums (read-only), 2 rows per warp ----
    #pragma unroll
    for (int ri = 0; ri < 2; ri++) {
        int r = w * 2 + ri;
        float ssum = 0.f;
        #pragma unroll 8
        for (int m = lane; m < 1024; m += 32) ssum += S[r * SPITCH + m];
        #pragma unroll
        for (int o = 16; o; o >>= 1) ssum += __shfl_xor_sync(0xffffffffu, ssum, o);
        if (lane == 0) rs[r] = ssum;
    }
    __syncthreads();
    if (tid < 32) rs[tid] = 1.f / rs[tid];
    __syncthreads();

    // ---- normalize + convert to f16 + deterministic column sums ----
    #pragma unroll
    for (int mi = 0; mi < 2; mi++) {
        int m = tid + mi * 512;
        float cs = 0.f;
        #pragma unroll
        for (int r = 0; r < 32; r++) {
            float v = S[r * SPITCH + m] * rs[r];
            cs += v;
            P[r * PPITCH + m] = __float2half(v);
        }
        gpart[(((size_t)(b * 4 + h) * 128) + qt) * 1024 + m] = cs;
    }
    __syncthreads();

    // ---- PV: warp w handles keys [w*64, (w+1)*64), partials into S region ----
    {
        wmma::fragment<wmma::accumulator, 16, 16, 16, float> acc2[2][2];
        #pragma unroll
        for (int mt = 0; mt < 2; mt++)
            #pragma unroll
            for (int nt = 0; nt < 2; nt++)
                wmma::fill_fragment(acc2[mt][nt], 0.f);
        #pragma unroll
        for (int ks = 0; ks < 4; ks++) {
            int kk = w * 64 + ks * 16;
            wmma::fragment<wmma::matrix_a, 16, 16, 16, __half, wmma::row_major> ap[2];
            wmma::fragment<wmma::matrix_b, 16, 16, 16, __half, wmma::row_major> bp[2];
            #pragma unroll
            for (int mt = 0; mt < 2; mt++)
                wmma::load_matrix_sync(ap[mt], P + (mt * 16) * PPITCH + kk, PPITCH);
            #pragma unroll
            for (int nt = 0; nt < 2; nt++)
                wmma::load_matrix_sync(bp[nt],
                    kv1h + ((size_t)b * KN1 + kk) * 256 + 128 + h * 32 + nt * 16, 256);
            #pragma unroll
            for (int mt = 0; mt < 2; mt++)
                #pragma unroll
                for (int nt = 0; nt < 2; nt++)
                    wmma::mma_sync(acc2[mt][nt], ap[mt], bp[nt], acc2[mt][nt]);
        }
        float* Sp = S + w * 1024;
        #pragma unroll
        for (int mt = 0; mt < 2; mt++)
            #pragma unroll
            for (int nt = 0; nt < 2; nt++)
                wmma::store_matrix_sync(Sp + mt * 16 * 32 + nt * 16, acc2[mt][nt],
                                        32, wmma::mem_row_major);
    }
    __syncthreads();

    // reduce 16 warp partials -> concat (f16, half2 stores)
    {
        int q = tid >> 4, dp = (tid & 15) * 2;   // 512 threads cover 32x16 pairs
        int idx = q * 32 + dp;
        float s0 = 0.f, s1 = 0.f;
        #pragma unroll
        for (int j = 0; j < 16; j++) {
            s0 += S[j * 1024 + idx];
            s1 += S[j * 1024 + idx + 1];
        }
        *(__half2*)(concath + ((size_t)b * KN + qt * 32 + q) * 256 + h * 32 + dp) =
            __floats2half2_rn(s0, s1);
    }
}

// ---------------------------------------------------------------------------
// Branch-2 windowed attention (fp32 compute, f16 concat out)
// ---------------------------------------------------------------------------
__global__ void attn2_kernel(const float* __restrict__ q2, const float* __restrict__ kv2,
                             __half* __restrict__ concath, float* __restrict__ lmpart)
{
    __shared__ float sQ[4][512];
    __shared__ float sKT[4][512];
    __shared__ float sV[4][512];
    __shared__ float sS[4][16 * 17];
    const int w = threadIdx.x >> 5, lane = threadIdx.x & 31;
    const int gw = blockIdx.x * 4 + w;
    const int b = gw >> 10;
    const int rem = gw & 1023;
    const int h = rem >> 8;
    const int win = rem & 255;
    const int wy = win >> 4, wx = win & 15;

    for (int t = 0; t < 16; t++) {
        int n = (wy * 4 + (t >> 2)) * KH + wx * 4 + (t & 3);
        sQ[w][t * 32 + lane]  = q2[((size_t)b * KN + n) * 128 + h * 32 + lane];
        sKT[w][lane * 16 + t] = kv2[((size_t)b * KN + n) * 256 + h * 32 + lane];
        sV[w][t * 32 + lane]  = kv2[((size_t)b * KN + n) * 256 + 128 + h * 32 + lane];
    }
    __syncwarp();

    #pragma unroll
    for (int r = 0; r < 8; r++) {
        int e = r * 32 + lane;
        int i = e >> 4, j = e & 15;
        float acc = 0.f;
        #pragma unroll
        for (int k = 0; k < 32; k++) acc += sQ[w][i * 32 + k] * sKT[w][k * 16 + j];
        sS[w][i * 17 + j] = acc * KSCALE;
    }
    __syncwarp();

    if (lane < 16) {
        float mx = -1e30f;
        #pragma unroll
        for (int j = 0; j < 16; j++) mx = fmaxf(mx, sS[w][lane * 17 + j]);
        float s = 0.f;
        #pragma unroll
        for (int j = 0; j < 16; j++) {
            float e = __expf(sS[w][lane * 17 + j] - mx);
            sS[w][lane * 17 + j] = e;
            s += e;
        }
        float inv = 1.f / s;
        #pragma unroll
        for (int j = 0; j < 16; j++) sS[w][lane * 17 + j] *= inv;
    }
    __syncwarp();

    if (lane < 16) {
        float cs = 0.f;
        #pragma unroll
        for (int i = 0; i < 16; i++) cs += sS[w][i * 17 + lane];
        lmpart[(((size_t)(b * 4 + h) * 256) + win) * 16 + lane] = cs;
    }

    for (int i = 0; i < 16; i++) {
        float acc = 0.f;
        #pragma unroll
        for (int j = 0; j < 16; j++) acc += sS[w][i * 17 + j] * sV[w][j * 32 + lane];
        int n = (wy * 4 + (i >> 2)) * KH + wx * 4 + (i & 3);
        concath[((size_t)b * KN + n) * 256 + 128 + h * 32 + lane] = __float2half(acc);
    }
}

// ---------------------------------------------------------------------------
// stage-1 g reduce: 8 partials per (b,m), 32768 threads
// ---------------------------------------------------------------------------
__global__ void g_reduce(const float* __restrict__ gpart, float* __restrict__ gred2)
{
    int idx = blockIdx.x * 256 + threadIdx.x;   // 32768
    int g = idx >> 12;
    int r = idx & 4095;
    int b = r >> 10, m = r & 1023;
    float s = 0.f;
    #pragma unroll 8
    for (int j = 0; j < 64; j++)
        s += gpart[((size_t)b * 512 + g * 64 + j) * 1024 + m];
    gred2[(size_t)g * 4096 + r] = s;
}

__global__ void mask_kernel(const float* __restrict__ gred2, const float* __restrict__ lmpart,
                            float* __restrict__ m1, float* __restrict__ m2)
{
    int idx = blockIdx.x * 256 + threadIdx.x;
    int b = idx >> 12, n = idx & 4095;
    int y = n >> 6, x = n & 63;
    int ri = b * 1024 + (y >> 1) * 32 + (x >> 1);
    float gv = 0.f;
    #pragma unroll
    for (int g = 0; g < 8; g++) gv += gred2[g * 4096 + ri];
    gv *= (1.f / 16384.f);
    int win = (y >> 2) * 16 + (x >> 2);
    int t = (y & 3) * 4 + (x & 3);
    float lv = 0.f;
    #pragma unroll
    for (int h = 0; h < 4; h++)
        lv += lmpart[(((size_t)(b * 4 + h) * 256) + win) * 16 + t];
    lv *= (1.f / 64.f);
    float val = gv + lv;
    m1[b * KN + y * KH + x] = val;
    m2[b * KN + x * KH + y] = val;
}

// ---------------------------------------------------------------------------
// launcher
// ---------------------------------------------------------------------------
extern "C" void kernel_launch(void* const* d_in, const int* in_sizes, int n_in,
                              void* d_out, int out_size)
{
    const float* x      = (const float*)d_in[0];
    const float* q1_w   = (const float*)d_in[1];
    const float* q1_b   = (const float*)d_in[2];
    const float* kv1_w  = (const float*)d_in[3];
    const float* kv1_b  = (const float*)d_in[4];
    const float* q2_w   = (const float*)d_in[5];
    const float* q2_b   = (const float*)d_in[6];
    const float* kv2_w  = (const float*)d_in[7];
    const float* kv2_b  = (const float*)d_in[8];
    const float* lepe_w = (const float*)d_in[9];
    const float* lepe_b = (const float*)d_in[10];
    const float* lcw    = (const float*)d_in[11];
    const float* lcb    = (const float*)d_in[12];
    const float* sr_w   = (const float*)d_in[13];
    const float* sr_b   = (const float*)d_in[14];
    const float* norm_w = (const float*)d_in[15];
    const float* norm_b = (const float*)d_in[16];
    const float* proj_w = (const float*)d_in[17];
    const float* proj_b = (const float*)d_in[18];
    (void)in_sizes; (void)n_in; (void)out_size;

    float* scratch = nullptr;
    cudaGetSymbolAddress((void**)&scratch, g_scratch);
    __half* hs = nullptr;
    cudaGetSymbolAddress((void**)&hs, g_scratch_h);

    float* q2buf  = scratch + OFF_Q2;
    float* kv2buf = scratch + OFF_KV2;
    float* xs     = scratch + OFF_XS;
    float* gpart  = scratch + OFF_GPART;
    float* gred2  = scratch + OFF_GRED2;
    float* lmpart = scratch + OFF_LMPART;

    __half* xh     = hs + HOFF_XH;
    __half* xsh    = hs + HOFF_XSH;
    __half* q1h    = hs + HOFF_Q1H;
    __half* kv1h   = hs + HOFF_KV1H;
    __half* lepeh  = hs + HOFF_LEPEH;
    __half* lepec  = hs + HOFF_LEPEC;
    __half* cath   = hs + HOFF_CATH;
    __half* wfused = hs + HOFF_WFUSE;
    __half* wkv1t  = hs + HOFF_WKV1;
    __half* wprojt = hs + HOFF_WPROJ;
    __half* wsrt   = hs + HOFF_WSR;

    float* out = (float*)d_out;
    float* m1  = out + (size_t)KB * KN * KC;
    float* m2  = m1 + (size_t)KB * KN;

    cudaFuncSetAttribute(hgemm_h,   cudaFuncAttributeMaxDynamicSharedMemorySize, HG_SMEM);
    cudaFuncSetAttribute(qkv_gemm,  cudaFuncAttributeMaxDynamicSharedMemorySize, HG_SMEM);
    cudaFuncSetAttribute(sr_gemm,   cudaFuncAttributeMaxDynamicSharedMemorySize, HG_SMEM);
    cudaFuncSetAttribute(proj_gemm, cudaFuncAttributeMaxDynamicSharedMemorySize, HG_SMEM);
    cudaFuncSetAttribute(attn1_kernel, cudaFuncAttributeMaxDynamicSharedMemorySize, ATTN1_SMEM);
    cudaFuncSetAttribute(lepe_conv, cudaFuncAttributeMaxDynamicSharedMemorySize, LEPE_SMEM);

    cvt_f16<<<4096, 256>>>(x, xh);
    prep_w<<<2304, 256>>>(q1_w, q2_w, kv2_w, lepe_w, kv1_w, proj_w, sr_w,
                          wfused, wkv1t, wprojt, wsrt);

    // fused projections: q1(f16), q2(f32), kv2(f32), lepe_lin(f16)
    qkv_gemm<<<dim3(6, 128), 256, HG_SMEM>>>(xh, wfused, q1_b, q2_b, kv2_b, lepe_b,
                                             q1h, q2buf, kv2buf, lepeh);
    lepe_conv<<<dim3(64, 2, 4), 256, LEPE_SMEM>>>(lepeh, lcw, lcb, lepec);

    // spatial reduction -> LN -> GELU -> kv1
    sr_gemm<<<dim3(2, 32), 256, HG_SMEM>>>(xh, wsrt, sr_b, xs);
    ln_gelu<<<KB * KN1, 256>>>(xs, norm_w, norm_b, xsh);
    hgemm_h<<<dim3(2, 32), 256, HG_SMEM>>>(xsh, wkv1t, kv1_b, kv1h,
                                           KB * KN1, 256, 256);

    // attention branches
    attn1_kernel<<<dim3(128, 4, 4), 512, ATTN1_SMEM>>>(q1h, kv1h, cath, gpart);
    g_reduce<<<128, 256>>>(gpart, gred2);
    attn2_kernel<<<1024, 128>>>(q2buf, kv2buf, cath, lmpart);
    mask_kernel<<<64, 256>>>(gred2, lmpart, m1, m2);

    // output projection with fused (concat_f16 + lepe_f16) and x2 epilogue
    proj_gemm<<<dim3(2, 128), 256, HG_SMEM>>>(cath, lepec, wprojt, proj_b, out);
}

// round 17
// speedup vs baseline: 3.7026x; 1.1393x over previous
#include <cuda_runtime.h>
#include <cuda_fp16.h>
#include <mma.h>
#include <math.h>
#include <stdint.h>

using namespace nvcuda;

#define KB   4
#define KN   4096
#define KC   256
#define KH   64
#define KN1  1024
#define KSCALE 0.17677669529663687f

// fp32 scratch
#define OFF_Q2       ((size_t)0)
#define OFF_KV2      (OFF_Q2     + (size_t)KB*KN*128)
#define OFF_XS       (OFF_KV2    + (size_t)KB*KN*256)
#define OFF_GPART    (OFF_XS     + (size_t)KB*KN1*256)
#define OFF_GRED2    (OFF_GPART  + (size_t)KB*4*128*1024)
#define OFF_LMPART   (OFF_GRED2  + (size_t)8*KB*1024)
#define SCRATCH_TOT  (OFF_LMPART + (size_t)KB*4*256*16)

__device__ float g_scratch[SCRATCH_TOT];

// f16 scratch
#define HOFF_XH    ((size_t)0)
#define HOFF_XSH   (HOFF_XH    + (size_t)4194304)
#define HOFF_Q1H   (HOFF_XSH   + (size_t)1048576)
#define HOFF_KV1H  (HOFF_Q1H   + (size_t)2097152)
#define HOFF_LEPEH (HOFF_KV1H  + (size_t)1048576)
#define HOFF_LEPEC (HOFF_LEPEH + (size_t)4194304)
#define HOFF_CATH  (HOFF_LEPEC + (size_t)4194304)
#define HOFF_WFUSE (HOFF_CATH  + (size_t)4194304)
#define HOFF_WKV1  (HOFF_WFUSE + (size_t)196608)
#define HOFF_WPROJ (HOFF_WKV1  + (size_t)65536)
#define HOFF_WSR   (HOFF_WPROJ + (size_t)65536)
#define HSCRATCH_TOT (HOFF_WSR + (size_t)262144)

__device__ __half g_scratch_h[HSCRATCH_TOT];

// ---------------------------------------------------------------------------
// common wmma tile config: 128x128 tile, 256 threads = 8 warps (2 x 4)
// ---------------------------------------------------------------------------
#define APITCH 72
#define CPITCH 132
#define HG_SMEM (128 * CPITCH * 4)

#define GEMM_CORE_DECL \
    extern __shared__ char smraw[]; \
    __half* As = (__half*)smraw; \
    __half* Bs = As + 128 * APITCH; \
    float*  Cst = (float*)smraw; \
    const int tid = threadIdx.x; \
    const int wid = tid >> 5; \
    const int warp_row = wid >> 2; \
    const int warp_col = wid & 3; \
    wmma::fragment<wmma::accumulator, 16, 16, 16, float> acc[4][2]; \
    _Pragma("unroll") \
    for (int mt = 0; mt < 4; mt++) \
        _Pragma("unroll") \
        for (int nt = 0; nt < 2; nt++) \
            wmma::fill_fragment(acc[mt][nt], 0.f);

#define GEMM_CORE_MMA \
    __syncthreads(); \
    _Pragma("unroll") \
    for (int ks = 0; ks < 4; ks++) { \
        wmma::fragment<wmma::matrix_a, 16, 16, 16, __half, wmma::row_major> af[4]; \
        wmma::fragment<wmma::matrix_b, 16, 16, 16, __half, wmma::col_major> bf[2]; \
        _Pragma("unroll") \
        for (int mt = 0; mt < 4; mt++) \
            wmma::load_matrix_sync(af[mt], As + (warp_row * 64 + mt * 16) * APITCH + ks * 16, APITCH); \
        _Pragma("unroll") \
        for (int nt = 0; nt < 2; nt++) \
            wmma::load_matrix_sync(bf[nt], Bs + (warp_col * 32 + nt * 16) * APITCH + ks * 16, APITCH); \
        _Pragma("unroll") \
        for (int mt = 0; mt < 4; mt++) \
            _Pragma("unroll") \
            for (int nt = 0; nt < 2; nt++) \
                wmma::mma_sync(acc[mt][nt], af[mt], bf[nt], acc[mt][nt]); \
    } \
    __syncthreads();

#define GEMM_STORE_STAGE \
    _Pragma("unroll") \
    for (int mt = 0; mt < 4; mt++) \
        _Pragma("unroll") \
        for (int nt = 0; nt < 2; nt++) \
            wmma::store_matrix_sync(Cst + (warp_row * 64 + mt * 16) * CPITCH + warp_col * 32 + nt * 16, \
                                    acc[mt][nt], CPITCH, wmma::mem_row_major); \
    __syncthreads();

// ---------------------------------------------------------------------------
// generic hgemm (kv1): C = A @ BT^T + bias, f16 out
// ---------------------------------------------------------------------------
__global__ __launch_bounds__(256)
void hgemm_h(const __half* __restrict__ A, const __half* __restrict__ BT,
             const float* __restrict__ bias, __half* __restrict__ Cout,
             int M, int N, int K)
{
    GEMM_CORE_DECL
    const int row0 = blockIdx.y * 128;
    const int col0 = blockIdx.x * 128;
    const int kn = K >> 6;
    for (int c = 0; c < kn; c++) {
        #pragma unroll
        for (int i = 0; i < 4; i++) {
            int li = i * 256 + tid;
            int r = li >> 3, q = (li & 7) * 8;
            *(uint4*)(As + r * APITCH + q) = *(const uint4*)(A + (size_t)(row0 + r) * K + c * 64 + q);
            *(uint4*)(Bs + r * APITCH + q) = *(const uint4*)(BT + (size_t)(col0 + r) * K + c * 64 + q);
        }
        GEMM_CORE_MMA
    }
    GEMM_STORE_STAGE
    #pragma unroll
    for (int i = 0; i < 16; i++) {
        int lin = i * 256 + tid;
        int r = lin >> 5, c4 = (lin & 31) * 4;
        const float* s = Cst + r * CPITCH + c4;
        __half2 h0 = __floats2half2_rn(s[0] + bias[col0 + c4 + 0], s[1] + bias[col0 + c4 + 1]);
        __half2 h1 = __floats2half2_rn(s[2] + bias[col0 + c4 + 2], s[3] + bias[col0 + c4 + 3]);
        uint2 pk; pk.x = *(uint32_t*)&h0; pk.y = *(uint32_t*)&h1;
        *(uint2*)(Cout + (size_t)(row0 + r) * N + col0 + c4) = pk;
    }
}

// ---------------------------------------------------------------------------
// fused projection GEMM: col tiles 0->q1h 1->q2 2,3->kv2 4,5->lepeh
// ---------------------------------------------------------------------------
__global__ __launch_bounds__(256)
void qkv_gemm(const __half* __restrict__ A, const __half* __restrict__ BT,
              const float* __restrict__ q1_b, const float* __restrict__ q2_b,
              const float* __restrict__ kv2_b, const float* __restrict__ lepe_b,
              __half* __restrict__ q1h, float* __restrict__ q2o,
              float* __restrict__ kv2o, __half* __restrict__ lepeh)
{
    GEMM_CORE_DECL
    const int row0 = blockIdx.y * 128;
    const int col0 = blockIdx.x * 128;
    for (int c = 0; c < 4; c++) {
        #pragma unroll
        for (int i = 0; i < 4; i++) {
            int li = i * 256 + tid;
            int r = li >> 3, q = (li & 7) * 8;
            *(uint4*)(As + r * APITCH + q) = *(const uint4*)(A + (size_t)(row0 + r) * 256 + c * 64 + q);
            *(uint4*)(Bs + r * APITCH + q) = *(const uint4*)(BT + (size_t)(col0 + r) * 256 + c * 64 + q);
        }
        GEMM_CORE_MMA
    }
    GEMM_STORE_STAGE

    const int t = blockIdx.x;
    __half* hdst = nullptr; float* fdst = nullptr;
    const float* bp; int pitch, cofs;
    switch (t) {
        case 0:  hdst = q1h;  bp = q1_b;  pitch = 128; cofs = 0;   break;
        case 1:  fdst = q2o;  bp = q2_b;  pitch = 128; cofs = 0;   break;
        case 2:  fdst = kv2o; bp = kv2_b; pitch = 256; cofs = 0;   break;
        case 3:  fdst = kv2o; bp = kv2_b; pitch = 256; cofs = 128; break;
        case 4:  hdst = lepeh; bp = lepe_b; pitch = 256; cofs = 0;   break;
        default: hdst = lepeh; bp = lepe_b; pitch = 256; cofs = 128; break;
    }
    #pragma unroll
    for (int i = 0; i < 16; i++) {
        int lin = i * 256 + tid;
        int r = lin >> 5, c4 = (lin & 31) * 4;
        const float* s = Cst + r * CPITCH + c4;
        float v0 = s[0] + bp[cofs + c4 + 0];
        float v1 = s[1] + bp[cofs + c4 + 1];
        float v2 = s[2] + bp[cofs + c4 + 2];
        float v3 = s[3] + bp[cofs + c4 + 3];
        size_t o = (size_t)(row0 + r) * pitch + cofs + c4;
        if (hdst) {
            __half2 h0 = __floats2half2_rn(v0, v1);
            __half2 h1 = __floats2half2_rn(v2, v3);
            uint2 pk; pk.x = *(uint32_t*)&h0; pk.y = *(uint32_t*)&h1;
            *(uint2*)(hdst + o) = pk;
        } else {
            *(float4*)(fdst + o) = make_float4(v0, v1, v2, v3);
        }
    }
}

// ---------------------------------------------------------------------------
// sr conv as GEMM with inline im2col gather from xh
// ---------------------------------------------------------------------------
__global__ __launch_bounds__(256)
void sr_gemm(const __half* __restrict__ xh, const __half* __restrict__ BT,
             const float* __restrict__ bias, float* __restrict__ C)
{
    GEMM_CORE_DECL
    const int row0 = blockIdx.y * 128;
    const int col0 = blockIdx.x * 128;
    for (int c = 0; c < 16; c++) {
        const int kk = c >> 2;
        const int ky = kk >> 1, kx = kk & 1;
        const int cib = (c & 3) * 64;
        #pragma unroll
        for (int i = 0; i < 4; i++) {
            int li = i * 256 + tid;
            int r = li >> 3, q = (li & 7) * 8;
            int m = row0 + r;
            int b = m >> 10, p = m & 1023;
            int oy = p >> 5, ox = p & 31;
            int n = (2 * oy + ky) * KH + 2 * ox + kx;
            *(uint4*)(As + r * APITCH + q) =
                *(const uint4*)(xh + ((size_t)b * KN + n) * 256 + cib + q);
            *(uint4*)(Bs + r * APITCH + q) =
                *(const uint4*)(BT + (size_t)(col0 + r) * 1024 + c * 64 + q);
        }
        GEMM_CORE_MMA
    }
    GEMM_STORE_STAGE
    #pragma unroll
    for (int i = 0; i < 16; i++) {
        int lin = i * 256 + tid;
        int r = lin >> 5, c4 = (lin & 31) * 4;
        const float* s = Cst + r * CPITCH + c4;
        float4 v = make_float4(s[0] + bias[col0 + c4 + 0], s[1] + bias[col0 + c4 + 1],
                               s[2] + bias[col0 + c4 + 2], s[3] + bias[col0 + c4 + 3]);
        *(float4*)(C + (size_t)(row0 + r) * 256 + col0 + c4) = v;
    }
}

// ---------------------------------------------------------------------------
// output GEMM: A = f16(concat_f16 + lepe_f16), x2 epilogue, f32 out
// ---------------------------------------------------------------------------
__global__ __launch_bounds__(256)
void proj_gemm(const __half* __restrict__ Acat, const __half* __restrict__ Alepe,
               const __half* __restrict__ BT, const float* __restrict__ bias,
               float* __restrict__ C)
{
    GEMM_CORE_DECL
    const int row0 = blockIdx.y * 128;
    const int col0 = blockIdx.x * 128;
    for (int c = 0; c < 4; c++) {
        #pragma unroll
        for (int i = 0; i < 4; i++) {
            int li = i * 256 + tid;
            int r = li >> 3, qf = (li & 7) * 8;
            size_t ai = (size_t)(row0 + r) * 256 + c * 64 + qf;
            uint4 chv = *(const uint4*)(Acat + ai);
            uint4 lhv = *(const uint4*)(Alepe + ai);
            __half2* cp = (__half2*)&chv;
            __half2* lp = (__half2*)&lhv;
            uint4 pk;
            __half2* op = (__half2*)&pk;
            #pragma unroll
            for (int u = 0; u < 4; u++) {
                float2 a = __half22float2(cp[u]);
                float2 l = __half22float2(lp[u]);
                op[u] = __floats2half2_rn(a.x + l.x, a.y + l.y);
            }
            *(uint4*)(As + r * APITCH + qf) = pk;
            *(uint4*)(Bs + r * APITCH + qf) =
                *(const uint4*)(BT + (size_t)(col0 + r) * 256 + c * 64 + qf);
        }
        GEMM_CORE_MMA
    }
    GEMM_STORE_STAGE
    #pragma unroll
    for (int i = 0; i < 16; i++) {
        int lin = i * 256 + tid;
        int r = lin >> 5, c4 = (lin & 31) * 4;
        const float* s = Cst + r * CPITCH + c4;
        float4 v = make_float4(2.f * (s[0] + bias[col0 + c4 + 0]),
                               2.f * (s[1] + bias[col0 + c4 + 1]),
                               2.f * (s[2] + bias[col0 + c4 + 2]),
                               2.f * (s[3] + bias[col0 + c4 + 3]));
        *(float4*)(C + (size_t)(row0 + r) * 256 + col0 + c4) = v;
    }
}

// ---------------------------------------------------------------------------
// prep
// ---------------------------------------------------------------------------
__global__ void cvt_f16(const float* __restrict__ in, __half* __restrict__ out) {
    int idx = blockIdx.x * 256 + threadIdx.x;
    float4 v = *(const float4*)(in + (size_t)idx * 4);
    __half2 h0 = __floats2half2_rn(v.x, v.y);
    __half2 h1 = __floats2half2_rn(v.z, v.w);
    uint2 pk; pk.x = *(uint32_t*)&h0; pk.y = *(uint32_t*)&h1;
    *(uint2*)(out + (size_t)idx * 4) = pk;
}

__global__ void prep_w(const float* __restrict__ q1w, const float* __restrict__ q2w,
                       const float* __restrict__ kv2w, const float* __restrict__ lepew,
                       const float* __restrict__ kv1w, const float* __restrict__ projw,
                       const float* __restrict__ srw,
                       __half* __restrict__ wfused, __half* __restrict__ wkv1t,
                       __half* __restrict__ wprojt, __half* __restrict__ wsrt)
{
    int idx = blockIdx.x * 256 + threadIdx.x;
    if (idx < 196608) {
        int r = idx >> 8, k = idx & 255;
        float v;
        if (r < 128)      v = q1w[(size_t)k * 128 + r];
        else if (r < 256) v = q2w[(size_t)k * 128 + (r - 128)];
        else if (r < 512) v = kv2w[(size_t)k * 256 + (r - 256)];
        else              v = lepew[(size_t)k * 256 + (r - 512)];
        wfused[idx] = __float2half(v);
    } else if (idx < 262144) {
        int i = idx - 196608;
        int n = i >> 8, k = i & 255;
        wkv1t[i] = __float2half(kv1w[(size_t)k * 256 + n]);
    } else if (idx < 327680) {
        int i = idx - 262144;
        int n = i >> 8, k = i & 255;
        wprojt[i] = __float2half(projw[(size_t)k * 256 + n]);
    } else {
        int i = idx - 327680;
        int co = i >> 10, k = i & 1023;
        int kk = k >> 8, ci = k & 255;
        wsrt[i] = __float2half(srw[(size_t)co * 1024 + ci * 4 + kk]);
    }
}

// ---------------------------------------------------------------------------
// depthwise 3x3 conv, pad 1. Block = 4-row x 16-px tile x 128-ch half x batch.
// ---------------------------------------------------------------------------
#define LEPE_SMEM (108 * 128 * 2 + 1152 * 4 + 128 * 4)

__global__ __launch_bounds__(256)
void lepe_conv(const __half* __restrict__ in, const float* __restrict__ w,
               const float* __restrict__ bias, __half* __restrict__ out)
{
    extern __shared__ char lsm[];
    __half* sIn = (__half*)lsm;
    float* ws = (float*)(lsm + 108 * 128 * 2);
    float* bs = ws + 1152;
    const int tid = threadIdx.x;
    const int tile = blockIdx.x;
    const int yt = tile >> 2, xt = tile & 3;
    const int cg = blockIdx.y;
    const int b = blockIdx.z;

    for (int i = tid; i < 1152; i += 256) ws[i] = w[cg * 1152 + i];
    if (tid < 128) bs[tid] = bias[cg * 128 + tid];

    for (int i = tid; i < 1728; i += 256) {
        int p = i >> 4, q = (i & 15) * 8;
        int ry = p / 18, px = p - ry * 18;
        int gy = yt * 4 - 1 + ry, gx = xt * 16 - 1 + px;
        uint4 v = make_uint4(0u, 0u, 0u, 0u);
        if (gy >= 0 && gy < KH && gx >= 0 && gx < KH)
            v = *(const uint4*)(in + ((size_t)b * KN + gy * KH + gx) * 256 + cg * 128 + q);
        *(uint4*)(sIn + p * 128 + q) = v;
    }
    __syncthreads();

    const int c2 = tid & 63;
    const int g = tid >> 6;
    float wr[18];
    #pragma unroll
    for (int t = 0; t < 9; t++) {
        wr[t]     = ws[(c2 * 2) * 9 + t];
        wr[9 + t] = ws[(c2 * 2 + 1) * 9 + t];
    }
    const float b0 = bs[c2 * 2], b1 = bs[c2 * 2 + 1];

    #pragma unroll 4
    for (int j = 0; j < 16; j++) {
        int pl = g * 16 + j;
        int ry = pl >> 4, xi = pl & 15;
        float a0 = b0, a1 = b1;
        const __half* base = sIn + (ry * 18 + xi) * 128 + c2 * 2;
        #pragma unroll
        for (int dy = 0; dy < 3; dy++)
            #pragma unroll
            for (int dx = 0; dx < 3; dx++) {
                float2 f = __half22float2(*(const __half2*)(base + (dy * 18 + dx) * 128));
                a0 += f.x * wr[dy * 3 + dx];
                a1 += f.y * wr[9 + dy * 3 + dx];
            }
        int gy = yt * 4 + ry, gx = xt * 16 + xi;
        *(__half2*)(out + ((size_t)b * KN + gy * KH + gx) * 256 + cg * 128 + c2 * 2) =
            __floats2half2_rn(a0, a1);
    }
}

// ---------------------------------------------------------------------------
// LayerNorm + GELU -> f16
// ---------------------------------------------------------------------------
__global__ void ln_gelu(const float* __restrict__ xs, const float* __restrict__ nw,
                        const float* __restrict__ nb, __half* __restrict__ o16)
{
    int row = blockIdx.x;
    int tid = threadIdx.x;
    float v = xs[(size_t)row * 256 + tid];
    __shared__ float red[16];
    float s = v, sq = v * v;
    #pragma unroll
    for (int o = 16; o; o >>= 1) {
        s  += __shfl_xor_sync(0xffffffffu, s, o);
        sq += __shfl_xor_sync(0xffffffffu, sq, o);
    }
    int w = tid >> 5, lane = tid & 31;
    if (lane == 0) { red[w] = s; red[8 + w] = sq; }
    __syncthreads();
    if (tid == 0) {
        float S = 0.f, SQ = 0.f;
        for (int i = 0; i < 8; i++) { S += red[i]; SQ += red[8 + i]; }
        red[0] = S; red[8] = SQ;
    }
    __syncthreads();
    float mean = red[0] * (1.f / 256.f);
    float var  = red[8] * (1.f / 256.f) - mean * mean;
    float t = (v - mean) * rsqrtf(var + 1e-5f) * nw[tid] + nb[tid];
    float g = 0.5f * t * (1.f + erff(t * 0.70710678118654752f));
    o16[(size_t)row * 256 + tid] = __float2half(g);
}

// ---------------------------------------------------------------------------
// Branch-1 attention, 512 threads = 16 warps. exp applied in-register.
// ---------------------------------------------------------------------------
#define SPITCH 1040
#define PPITCH 1032
#define ATTN1_SMEM (32 * SPITCH * 4 + 32 * PPITCH * 2 + 128)

__global__ __launch_bounds__(512)
void attn1_kernel(const __half* __restrict__ q1h, const __half* __restrict__ kv1h,
                  __half* __restrict__ concath, float* __restrict__ gpart)
{
    extern __shared__ char smraw[];
    float* S = (float*)smraw;
    __half* P = (__half*)(smraw + 32 * SPITCH * 4);
    float* rs = (float*)(smraw + 32 * SPITCH * 4 + 32 * PPITCH * 2);
    const int tid = threadIdx.x;
    const int w = tid >> 5, lane = tid & 31;
    const int qt = blockIdx.x, h = blockIdx.y, b = blockIdx.z;

    {
        wmma::fragment<wmma::matrix_a, 16, 16, 16, __half, wmma::row_major> af[2][2];
        #pragma unroll
        for (int mt = 0; mt < 2; mt++)
            #pragma unroll
            for (int ks = 0; ks < 2; ks++)
                wmma::load_matrix_sync(af[mt][ks],
                    q1h + ((size_t)b * KN + qt * 32 + mt * 16) * 128 + h * 32 + ks * 16, 128);
        #pragma unroll
        for (int nt = 0; nt < 4; nt++) {
            int col = w * 64 + nt * 16;
            wmma::fragment<wmma::accumulator, 16, 16, 16, float> a0, a1;
            wmma::fill_fragment(a0, 0.f);
            wmma::fill_fragment(a1, 0.f);
            #pragma unroll
            for (int ks = 0; ks < 2; ks++) {
                wmma::fragment<wmma::matrix_b, 16, 16, 16, __half, wmma::col_major> bf;
                wmma::load_matrix_sync(bf,
                    kv1h + ((size_t)b * KN1 + col) * 256 + h * 32 + ks * 16, 256);
                wmma::mma_sync(a0, af[0][ks], bf, a0);
                wmma::mma_sync(a1, af[1][ks], bf, a1);
            }
            #pragma unroll
            for (int e = 0; e < a0.num_elements; e++) {
                a0.x[e] = __expf(a0.x[e] * KSCALE);
                a1.x[e] = __expf(a1.x[e] * KSCALE);
            }
            wmma::store_matrix_sync(S + 0 * SPITCH + col, a0, SPITCH, wmma::mem_row_major);
            wmma::store_matrix_sync(S + 16 * SPITCH + col, a1, SPITCH, wmma::mem_row_major);
        }
    }
    __syncthreads();

    #pragma unroll
    for (int ri = 0; ri < 2; ri++) {
        int r = w * 2 + ri;
        float ssum = 0.f;
        #pragma unroll 8
        for (int m = lane; m < 1024; m += 32) ssum += S[r * SPITCH + m];
        #pragma unroll
        for (int o = 16; o; o >>= 1) ssum += __shfl_xor_sync(0xffffffffu, ssum, o);
        if (lane == 0) rs[r] = ssum;
    }
    __syncthreads();
    if (tid < 32) rs[tid] = 1.f / rs[tid];
    __syncthreads();

    #pragma unroll
    for (int mi = 0; mi < 2; mi++) {
        int m = tid + mi * 512;
        float cs = 0.f;
        #pragma unroll
        for (int r = 0; r < 32; r++) {
            float v = S[r * SPITCH + m] * rs[r];
            cs += v;
            P[r * PPITCH + m] = __float2half(v);
        }
        gpart[(((size_t)(b * 4 + h) * 128) + qt) * 1024 + m] = cs;
    }
    __syncthreads();

    {
        wmma::fragment<wmma::accumulator, 16, 16, 16, float> acc2[2][2];
        #pragma unroll
        for (int mt = 0; mt < 2; mt++)
            #pragma unroll
            for (int nt = 0; nt < 2; nt++)
                wmma::fill_fragment(acc2[mt][nt], 0.f);
        #pragma unroll
        for (int ks = 0; ks < 4; ks++) {
            int kk = w * 64 + ks * 16;
            wmma::fragment<wmma::matrix_a, 16, 16, 16, __half, wmma::row_major> ap[2];
            wmma::fragment<wmma::matrix_b, 16, 16, 16, __half, wmma::row_major> bp[2];
            #pragma unroll
            for (int mt = 0; mt < 2; mt++)
                wmma::load_matrix_sync(ap[mt], P + (mt * 16) * PPITCH + kk, PPITCH);
            #pragma unroll
            for (int nt = 0; nt < 2; nt++)
                wmma::load_matrix_sync(bp[nt],
                    kv1h + ((size_t)b * KN1 + kk) * 256 + 128 + h * 32 + nt * 16, 256);
            #pragma unroll
            for (int mt = 0; mt < 2; mt++)
                #pragma unroll
                for (int nt = 0; nt < 2; nt++)
                    wmma::mma_sync(acc2[mt][nt], ap[mt], bp[nt], acc2[mt][nt]);
        }
        float* Sp = S + w * 1024;
        #pragma unroll
        for (int mt = 0; mt < 2; mt++)
            #pragma unroll
            for (int nt = 0; nt < 2; nt++)
                wmma::store_matrix_sync(Sp + mt * 16 * 32 + nt * 16, acc2[mt][nt],
                                        32, wmma::mem_row_major);
    }
    __syncthreads();

    {
        int q = tid >> 4, dp = (tid & 15) * 2;
        int idx = q * 32 + dp;
        float s0 = 0.f, s1 = 0.f;
        #pragma unroll
        for (int j = 0; j < 16; j++) {
            s0 += S[j * 1024 + idx];
            s1 += S[j * 1024 + idx + 1];
        }
        *(__half2*)(concath + ((size_t)b * KN + qt * 32 + q) * 256 + h * 32 + dp) =
            __floats2half2_rn(s0, s1);
    }
}

// ---------------------------------------------------------------------------
// Branch-2 windowed attention (fp32 compute, f16 concat out)
// ---------------------------------------------------------------------------
__global__ void attn2_kernel(const float* __restrict__ q2, const float* __restrict__ kv2,
                             __half* __restrict__ concath, float* __restrict__ lmpart)
{
    __shared__ float sQ[4][512];
    __shared__ float sKT[4][512];
    __shared__ float sV[4][512];
    __shared__ float sS[4][16 * 17];
    const int w = threadIdx.x >> 5, lane = threadIdx.x & 31;
    const int gw = blockIdx.x * 4 + w;
    const int b = gw >> 10;
    const int rem = gw & 1023;
    const int h = rem >> 8;
    const int win = rem & 255;
    const int wy = win >> 4, wx = win & 15;

    for (int t = 0; t < 16; t++) {
        int n = (wy * 4 + (t >> 2)) * KH + wx * 4 + (t & 3);
        sQ[w][t * 32 + lane]  = q2[((size_t)b * KN + n) * 128 + h * 32 + lane];
        sKT[w][lane * 16 + t] = kv2[((size_t)b * KN + n) * 256 + h * 32 + lane];
        sV[w][t * 32 + lane]  = kv2[((size_t)b * KN + n) * 256 + 128 + h * 32 + lane];
    }
    __syncwarp();

    #pragma unroll
    for (int r = 0; r < 8; r++) {
        int e = r * 32 + lane;
        int i = e >> 4, j = e & 15;
        float acc = 0.f;
        #pragma unroll
        for (int k = 0; k < 32; k++) acc += sQ[w][i * 32 + k] * sKT[w][k * 16 + j];
        sS[w][i * 17 + j] = acc * KSCALE;
    }
    __syncwarp();

    if (lane < 16) {
        float mx = -1e30f;
        #pragma unroll
        for (int j = 0; j < 16; j++) mx = fmaxf(mx, sS[w][lane * 17 + j]);
        float s = 0.f;
        #pragma unroll
        for (int j = 0; j < 16; j++) {
            float e = __expf(sS[w][lane * 17 + j] - mx);
            sS[w][lane * 17 + j] = e;
            s += e;
        }
        float inv = 1.f / s;
        #pragma unroll
        for (int j = 0; j < 16; j++) sS[w][lane * 17 + j] *= inv;
    }
    __syncwarp();

    if (lane < 16) {
        float cs = 0.f;
        #pragma unroll
        for (int i = 0; i < 16; i++) cs += sS[w][i * 17 + lane];
        lmpart[(((size_t)(b * 4 + h) * 256) + win) * 16 + lane] = cs;
    }

    for (int i = 0; i < 16; i++) {
        float acc = 0.f;
        #pragma unroll
        for (int j = 0; j < 16; j++) acc += sS[w][i * 17 + j] * sV[w][j * 32 + lane];
        int n = (wy * 4 + (i >> 2)) * KH + wx * 4 + (i & 3);
        concath[((size_t)b * KN + n) * 256 + 128 + h * 32 + lane] = __float2half(acc);
    }
}

// ---------------------------------------------------------------------------
// stage-1 g reduce
// ---------------------------------------------------------------------------
__global__ void g_reduce(const float* __restrict__ gpart, float* __restrict__ gred2)
{
    int idx = blockIdx.x * 256 + threadIdx.x;
    int g = idx >> 12;
    int r = idx & 4095;
    int b = r >> 10, m = r & 1023;
    float s = 0.f;
    #pragma unroll 8
    for (int j = 0; j < 64; j++)
        s += gpart[((size_t)b * 512 + g * 64 + j) * 1024 + m];
    gred2[(size_t)g * 4096 + r] = s;
}

__global__ void mask_kernel(const float* __restrict__ gred2, const float* __restrict__ lmpart,
                            float* __restrict__ m1, float* __restrict__ m2)
{
    int idx = blockIdx.x * 256 + threadIdx.x;
    int b = idx >> 12, n = idx & 4095;
    int y = n >> 6, x = n & 63;
    int ri = b * 1024 + (y >> 1) * 32 + (x >> 1);
    float gv = 0.f;
    #pragma unroll
    for (int g = 0; g < 8; g++) gv += gred2[g * 4096 + ri];
    gv *= (1.f / 16384.f);
    int win = (y >> 2) * 16 + (x >> 2);
    int t = (y & 3) * 4 + (x & 3);
    float lv = 0.f;
    #pragma unroll
    for (int h = 0; h < 4; h++)
        lv += lmpart[(((size_t)(b * 4 + h) * 256) + win) * 16 + t];
    lv *= (1.f / 64.f);
    float val = gv + lv;
    m1[b * KN + y * KH + x] = val;
    m2[b * KN + x * KH + y] = val;
}

// ---------------------------------------------------------------------------
// stream/event helpers (created once; no device memory involved)
// ---------------------------------------------------------------------------
static cudaStream_t make_stream() {
    cudaStream_t s;
    cudaStreamCreateWithFlags(&s, cudaStreamNonBlocking);
    return s;
}
static cudaEvent_t make_event() {
    cudaEvent_t e;
    cudaEventCreateWithFlags(&e, cudaEventDisableTiming);
    return e;
}

// ---------------------------------------------------------------------------
// launcher: multi-stream fork/join (graph-capture-compatible)
// ---------------------------------------------------------------------------
extern "C" void kernel_launch(void* const* d_in, const int* in_sizes, int n_in,
                              void* d_out, int out_size)
{
    const float* x      = (const float*)d_in[0];
    const float* q1_w   = (const float*)d_in[1];
    const float* q1_b   = (const float*)d_in[2];
    const float* kv1_w  = (const float*)d_in[3];
    const float* kv1_b  = (const float*)d_in[4];
    const float* q2_w   = (const float*)d_in[5];
    const float* q2_b   = (const float*)d_in[6];
    const float* kv2_w  = (const float*)d_in[7];
    const float* kv2_b  = (const float*)d_in[8];
    const float* lepe_w = (const float*)d_in[9];
    const float* lepe_b = (const float*)d_in[10];
    const float* lcw    = (const float*)d_in[11];
    const float* lcb    = (const float*)d_in[12];
    const float* sr_w   = (const float*)d_in[13];
    const float* sr_b   = (const float*)d_in[14];
    const float* norm_w = (const float*)d_in[15];
    const float* norm_b = (const float*)d_in[16];
    const float* proj_w = (const float*)d_in[17];
    const float* proj_b = (const float*)d_in[18];
    (void)in_sizes; (void)n_in; (void)out_size;

    float* scratch = nullptr;
    cudaGetSymbolAddress((void**)&scratch, g_scratch);
    __half* hs = nullptr;
    cudaGetSymbolAddress((void**)&hs, g_scratch_h);

    float* q2buf  = scratch + OFF_Q2;
    float* kv2buf = scratch + OFF_KV2;
    float* xs     = scratch + OFF_XS;
    float* gpart  = scratch + OFF_GPART;
    float* gred2  = scratch + OFF_GRED2;
    float* lmpart = scratch + OFF_LMPART;

    __half* xh     = hs + HOFF_XH;
    __half* xsh    = hs + HOFF_XSH;
    __half* q1h    = hs + HOFF_Q1H;
    __half* kv1h   = hs + HOFF_KV1H;
    __half* lepeh  = hs + HOFF_LEPEH;
    __half* lepec  = hs + HOFF_LEPEC;
    __half* cath   = hs + HOFF_CATH;
    __half* wfused = hs + HOFF_WFUSE;
    __half* wkv1t  = hs + HOFF_WKV1;
    __half* wprojt = hs + HOFF_WPROJ;
    __half* wsrt   = hs + HOFF_WSR;

    float* out = (float*)d_out;
    float* m1  = out + (size_t)KB * KN * KC;
    float* m2  = m1 + (size_t)KB * KN;

    cudaFuncSetAttribute(hgemm_h,   cudaFuncAttributeMaxDynamicSharedMemorySize, HG_SMEM);
    cudaFuncSetAttribute(qkv_gemm,  cudaFuncAttributeMaxDynamicSharedMemorySize, HG_SMEM);
    cudaFuncSetAttribute(sr_gemm,   cudaFuncAttributeMaxDynamicSharedMemorySize, HG_SMEM);
    cudaFuncSetAttribute(proj_gemm, cudaFuncAttributeMaxDynamicSharedMemorySize, HG_SMEM);
    cudaFuncSetAttribute(attn1_kernel, cudaFuncAttributeMaxDynamicSharedMemorySize, ATTN1_SMEM);
    cudaFuncSetAttribute(lepe_conv, cudaFuncAttributeMaxDynamicSharedMemorySize, LEPE_SMEM);

    // one-time stream/event creation (no device memory allocated)
    static cudaStream_t s1 = make_stream();
    static cudaStream_t s2 = make_stream();
    static cudaEvent_t ev0    = make_event();
    static cudaEvent_t evCvt  = make_event();
    static cudaEvent_t evPrep = make_event();
    static cudaEvent_t evQkv  = make_event();
    static cudaEvent_t evS1   = make_event();
    static cudaEvent_t evS2   = make_event();

    // fork point on origin (default) stream
    cudaEventRecord(ev0, 0);

    // default: x -> f16
    cvt_f16<<<4096, 256>>>(x, xh);
    cudaEventRecord(evCvt, 0);

    // s1: weight prep (independent of cvt)
    cudaStreamWaitEvent(s1, ev0, 0);
    prep_w<<<2304, 256, 0, s1>>>(q1_w, q2_w, kv2_w, lepe_w, kv1_w, proj_w, sr_w,
                                 wfused, wkv1t, wprojt, wsrt);
    cudaEventRecord(evPrep, s1);

    // default: fused projections (needs xh + wfused)
    cudaStreamWaitEvent(0, evPrep, 0);
    qkv_gemm<<<dim3(6, 128), 256, HG_SMEM>>>(xh, wfused, q1_b, q2_b, kv2_b, lepe_b,
                                             q1h, q2buf, kv2buf, lepeh);
    cudaEventRecord(evQkv, 0);

    // s2: sr chain (needs xh + wsrt), runs concurrent with qkv
    cudaStreamWaitEvent(s2, evCvt, 0);
    cudaStreamWaitEvent(s2, evPrep, 0);
    sr_gemm<<<dim3(2, 32), 256, HG_SMEM, s2>>>(xh, wsrt, sr_b, xs);
    ln_gelu<<<KB * KN1, 256, 0, s2>>>(xs, norm_w, norm_b, xsh);
    hgemm_h<<<dim3(2, 32), 256, HG_SMEM, s2>>>(xsh, wkv1t, kv1_b, kv1h,
                                               KB * KN1, 256, 256);
    cudaEventRecord(evS2, s2);

    // s1: lepe conv + branch-2 attention (need qkv outputs), concurrent with attn1
    cudaStreamWaitEvent(s1, evQkv, 0);
    lepe_conv<<<dim3(64, 2, 4), 256, LEPE_SMEM, s1>>>(lepeh, lcw, lcb, lepec);
    attn2_kernel<<<1024, 128, 0, s1>>>(q2buf, kv2buf, cath, lmpart);
    cudaEventRecord(evS1, s1);

    // default: branch-1 attention (needs q1h + kv1h)
    cudaStreamWaitEvent(0, evS2, 0);
    attn1_kernel<<<dim3(128, 4, 4), 512, ATTN1_SMEM>>>(q1h, kv1h, cath, gpart);
    g_reduce<<<128, 256>>>(gpart, gred2);

    // join s1 (attn2 + lepe done), then mask + output projection
    cudaStreamWaitEvent(0, evS1, 0);
    mask_kernel<<<64, 256>>>(gred2, lmpart, m1, m2);
    proj_gemm<<<dim3(2, 128), 256, HG_SMEM>>>(cath, lepec, wprojt, proj_b, out);
}